// round 1
// baseline (speedup 1.0000x reference)
#include <cuda_runtime.h>
#include <math.h>
#include <stdint.h>

#define S_LEN   2048
#define NBATCH  2
#define EMB     2048
#define NHEADS  16
#define NKV     4
#define HD      128
#define KVW     1024   // 2*NKV*HD

typedef unsigned long long u64;

// ---------------- scratch (device globals: no allocation allowed) ----------------
__device__ float  g_q   [(size_t)NBATCH * S_LEN * EMB];   // 32 MB
__device__ float  g_kv  [(size_t)NBATCH * S_LEN * KVW];   // 16 MB
__device__ float  g_attn[(size_t)NBATCH * S_LEN * EMB];   // 32 MB
__device__ double g_invfreq[64];

// ---------------- packed f32x2 helpers (FFMA2: 2x fp32 throughput on sm_103a) ----
#define PACKF2(d, lo, hi) \
    asm("mov.b64 %0, {%1, %2};" : "=l"(d) : "r"(__float_as_uint(lo)), "r"(__float_as_uint(hi)))
#define UNPACKF2(lo, hi, v) do { unsigned int _u0, _u1;                                  \
    asm("mov.b64 {%0, %1}, %2;" : "=r"(_u0), "=r"(_u1) : "l"(v));                        \
    (lo) = __uint_as_float(_u0); (hi) = __uint_as_float(_u1); } while (0)
#define FMAF2(acc, a, b) \
    asm("fma.rn.f32x2 %0, %1, %2, %0;" : "+l"(acc) : "l"(a), "l"(b))
#define MULF2(d, a, b) \
    asm("mul.rn.f32x2 %0, %1, %2;" : "=l"(d) : "l"(a), "l"(b))

// ---------------- fast exp (avoids MUFU.EX2 which is rt=8/SMSP) -------------------
// exp(x) for x <= 0. Degree-6 Taylor of 2^f on [0,1): abs err ~1.5e-5, plenty for softmax.
__device__ __forceinline__ float fast_exp(float x) {
    float y  = fmaxf(x * 1.4426950408889634f, -127.0f);
    float fl = floorf(y);
    float f  = y - fl;
    float p  = 1.5403530e-4f;
    p = fmaf(p, f, 1.3333558e-3f);
    p = fmaf(p, f, 9.6181291e-3f);
    p = fmaf(p, f, 5.5504109e-2f);
    p = fmaf(p, f, 2.4022651e-1f);
    p = fmaf(p, f, 6.9314718e-1f);
    p = fmaf(p, f, 1.0f);
    int e = (int)fl;
    float s = __int_as_float((e + 127) << 23);   // e in [-127, 0]
    return p * s;
}

// ---------------- GEMM: C[M,N] = A[M,K] @ W[N,K]^T (+bias) ------------------------
// 128x128 block, BK=16, 256 threads, 8x8 per thread, FFMA2 inner loop.
__global__ __launch_bounds__(256, 2) void gemm_tn(
    const float* __restrict__ A, const float* __restrict__ W,
    const float* __restrict__ bias, float* __restrict__ C,
    int N, int K)
{
    __shared__ float As[16][132];  // [k][m], pad 4 (row = 528B, 16B-aligned)
    __shared__ float Bs[16][132];  // [k][n]

    const int tid = threadIdx.x;
    const int m0  = blockIdx.y * 128;
    const int n0  = blockIdx.x * 128;
    const int tr  = tid >> 4;      // 0..15
    const int tc  = tid & 15;      // 0..15

    u64 acc2[8][4];
    #pragma unroll
    for (int i = 0; i < 8; i++)
        #pragma unroll
        for (int j = 0; j < 4; j++) acc2[i][j] = 0ull;

    const int row_a = tid >> 2;    // 0..63
    const int kq    = tid & 3;

    for (int k0 = 0; k0 < K; k0 += 16) {
        #pragma unroll
        for (int ld = 0; ld < 2; ld++) {
            int row = row_a + ld * 64;
            float4 av = *(const float4*)&A[(size_t)(m0 + row) * K + k0 + kq * 4];
            As[kq*4+0][row] = av.x; As[kq*4+1][row] = av.y;
            As[kq*4+2][row] = av.z; As[kq*4+3][row] = av.w;
            float4 bv = *(const float4*)&W[(size_t)(n0 + row) * K + k0 + kq * 4];
            Bs[kq*4+0][row] = bv.x; Bs[kq*4+1][row] = bv.y;
            Bs[kq*4+2][row] = bv.z; Bs[kq*4+3][row] = bv.w;
        }
        __syncthreads();
        #pragma unroll
        for (int kk = 0; kk < 16; kk++) {
            float4 a0 = *(const float4*)&As[kk][tr * 8];
            float4 a1 = *(const float4*)&As[kk][tr * 8 + 4];
            ulonglong2 bq0 = *(const ulonglong2*)&Bs[kk][tc * 8];
            ulonglong2 bq1 = *(const ulonglong2*)&Bs[kk][tc * 8 + 4];
            float a[8] = {a0.x, a0.y, a0.z, a0.w, a1.x, a1.y, a1.z, a1.w};
            #pragma unroll
            for (int i = 0; i < 8; i++) {
                u64 ap; PACKF2(ap, a[i], a[i]);
                FMAF2(acc2[i][0], ap, bq0.x);
                FMAF2(acc2[i][1], ap, bq0.y);
                FMAF2(acc2[i][2], ap, bq1.x);
                FMAF2(acc2[i][3], ap, bq1.y);
            }
        }
        __syncthreads();
    }

    #pragma unroll
    for (int i = 0; i < 8; i++) {
        int row = m0 + tr * 8 + i;
        int col = n0 + tc * 8;
        float c[8];
        #pragma unroll
        for (int jp = 0; jp < 4; jp++) { UNPACKF2(c[2*jp], c[2*jp+1], acc2[i][jp]); }
        if (bias) {
            #pragma unroll
            for (int j = 0; j < 8; j++) c[j] += bias[col + j];
        }
        *(float4*)&C[(size_t)row * N + col]     = make_float4(c[0], c[1], c[2], c[3]);
        *(float4*)&C[(size_t)row * N + col + 4] = make_float4(c[4], c[5], c[6], c[7]);
    }
}

// ---------------- RoPE ------------------------------------------------------------
__global__ void init_invfreq_kernel() {
    int d = threadIdx.x;
    if (d < 64) g_invfreq[d] = pow(10000.0, -(double)d / 64.0);
}

// which=0: q buffer (16 heads, row width 2048); which=1: k half of kv (4 heads, width 1024)
__global__ void rope_kernel(int which) {
    float* buf   = which ? g_kv : g_q;
    int nHeads   = which ? NKV : NHEADS;
    int rowW     = which ? KVW : EMB;
    int idx = blockIdx.x * blockDim.x + threadIdx.x;
    int total = NBATCH * S_LEN * nHeads * 64;
    if (idx >= total) return;
    int d = idx & 63;
    int h = (idx >> 6) % nHeads;
    int r = idx / (64 * nHeads);
    int s = r & (S_LEN - 1);
    size_t base = (size_t)r * rowW + h * HD;
    float t1 = buf[base + d];
    float t2 = buf[base + 64 + d];
    double ang = (double)s * g_invfreq[d];
    double k   = floor(ang * 0.15915494309189535);           // /(2*pi)
    float a    = (float)(ang - k * 6.283185307179586);       // [0, 2pi)
    float sn, cs;
    sincosf(a, &sn, &cs);
    buf[base + d]      = t1 * cs - t2 * sn;
    buf[base + 64 + d] = t2 * cs + t1 * sn;
}

// ---------------- attention (flash-style, 64q x 64k tiles, online softmax) --------
// grid (S/64, H, B), 256 threads. thread = (qi = tid>>2, part = tid&3).
#define ATTN_SMEM_FLOATS (64*132 + 64*132 + 64*128 + 64*65 + 64 + 64)

__global__ __launch_bounds__(256, 1) void attn_kernel() {
    extern __shared__ float sm[];
    float* Qs = sm;                 // 64 x 132
    float* Ks = Qs + 64 * 132;      // 64 x 132
    float* Vs = Ks + 64 * 132;      // 64 x 128 (rows broadcast -> no pad needed)
    float* Sc = Vs + 64 * 128;      // 64 x 65
    float* Ms = Sc + 64 * 65;       // 64
    float* Ls = Ms + 64;            // 64

    const int tid  = threadIdx.x;
    const int q0   = blockIdx.x * 64;
    const int h    = blockIdx.y;
    const int b    = blockIdx.z;
    const int kvh  = h >> 2;        // GQA group
    const int qi   = tid >> 2;
    const int part = tid & 3;
    const float scale = 0.08838834764831845f;   // 1/sqrt(128)

    const float* qbase = g_q + (size_t)(b * S_LEN + q0) * EMB + h * HD;
    #pragma unroll
    for (int it = 0; it < 8; it++) {
        int idx = tid + it * 256;
        int row = idx >> 5, c4 = idx & 31;
        float4 v = *(const float4*)&qbase[(size_t)row * EMB + c4 * 4];
        v.x *= scale; v.y *= scale; v.z *= scale; v.w *= scale;
        *(float4*)&Qs[row * 132 + c4 * 4] = v;
    }
    if (tid < 64) { Ms[tid] = -1e30f; Ls[tid] = 0.f; }

    u64 oacc2[8][2];
    #pragma unroll
    for (int i = 0; i < 8; i++) { oacc2[i][0] = 0ull; oacc2[i][1] = 0ull; }

    const float* kbase = g_kv + (size_t)(b * S_LEN) * KVW + kvh * HD;
    const float* vbase = kbase + NKV * HD;   // v half starts at col 512

    for (int t = 0; t < 32; t++) {
        int j0 = t * 64;
        #pragma unroll
        for (int it = 0; it < 8; it++) {
            int idx = tid + it * 256;
            int row = idx >> 5, c4 = idx & 31;
            *(float4*)&Ks[row * 132 + c4 * 4] =
                *(const float4*)&kbase[(size_t)(j0 + row) * KVW + c4 * 4];
            *(float4*)&Vs[row * 128 + c4 * 4] =
                *(const float4*)&vbase[(size_t)(j0 + row) * KVW + c4 * 4];
        }
        __syncthreads();

        // ---- scores: thread covers j = jj*4 + part (conflict-free K reads) ----
        u64 sacc[16];
        #pragma unroll
        for (int jj = 0; jj < 16; jj++) sacc[jj] = 0ull;
        #pragma unroll 2
        for (int d4 = 0; d4 < 32; d4++) {
            ulonglong2 qq = *(const ulonglong2*)&Qs[qi * 132 + d4 * 4];
            #pragma unroll
            for (int jj = 0; jj < 16; jj++) {
                ulonglong2 kp = *(const ulonglong2*)&Ks[(jj * 4 + part) * 132 + d4 * 4];
                FMAF2(sacc[jj], qq.x, kp.x);
                FMAF2(sacc[jj], qq.y, kp.y);
            }
        }
        float scv[16];
        float lmax = -1e30f;
        #pragma unroll
        for (int jj = 0; jj < 16; jj++) {
            float lo, hi; UNPACKF2(lo, hi, sacc[jj]);
            scv[jj] = lo + hi;
            lmax = fmaxf(lmax, scv[jj]);
        }
        // quad (4 lanes, same qi) reduction
        lmax = fmaxf(lmax, __shfl_xor_sync(0xffffffffu, lmax, 1));
        lmax = fmaxf(lmax, __shfl_xor_sync(0xffffffffu, lmax, 2));
        float mold = Ms[qi];
        float lold = Ls[qi];
        float mnew = fmaxf(mold, lmax);
        float alpha = fast_exp(mold - mnew);
        float psum = 0.f;
        #pragma unroll
        for (int jj = 0; jj < 16; jj++) {
            float p = fast_exp(scv[jj] - mnew);
            Sc[qi * 65 + jj * 4 + part] = p;
            psum += p;
        }
        psum += __shfl_xor_sync(0xffffffffu, psum, 1);
        psum += __shfl_xor_sync(0xffffffffu, psum, 2);
        __syncwarp();
        if (part == 0) { Ms[qi] = mnew; Ls[qi] = lold * alpha + psum; }

        // ---- rescale accumulators, then O += P @ V ----
        u64 alpha2; PACKF2(alpha2, alpha, alpha);
        #pragma unroll
        for (int i = 0; i < 8; i++) {
            MULF2(oacc2[i][0], oacc2[i][0], alpha2);
            MULF2(oacc2[i][1], oacc2[i][1], alpha2);
        }
        __syncwarp();   // Sc rows are quad-local (same warp)
        #pragma unroll 2
        for (int j4 = 0; j4 < 16; j4++) {
            float p0 = Sc[qi * 65 + j4 * 4 + 0];
            float p1 = Sc[qi * 65 + j4 * 4 + 1];
            float p2 = Sc[qi * 65 + j4 * 4 + 2];
            float p3 = Sc[qi * 65 + j4 * 4 + 3];
            u64 pp0, pp1, pp2, pp3;
            PACKF2(pp0, p0, p0); PACKF2(pp1, p1, p1);
            PACKF2(pp2, p2, p2); PACKF2(pp3, p3, p3);
            #pragma unroll
            for (int d4 = 0; d4 < 8; d4++) {
                int c = d4 * 4 + part;   // interleaved dims -> conflict-free V reads
                ulonglong2 v0 = *(const ulonglong2*)&Vs[(j4 * 4 + 0) * 128 + c * 4];
                ulonglong2 v1 = *(const ulonglong2*)&Vs[(j4 * 4 + 1) * 128 + c * 4];
                ulonglong2 v2 = *(const ulonglong2*)&Vs[(j4 * 4 + 2) * 128 + c * 4];
                ulonglong2 v3 = *(const ulonglong2*)&Vs[(j4 * 4 + 3) * 128 + c * 4];
                FMAF2(oacc2[d4][0], pp0, v0.x); FMAF2(oacc2[d4][1], pp0, v0.y);
                FMAF2(oacc2[d4][0], pp1, v1.x); FMAF2(oacc2[d4][1], pp1, v1.y);
                FMAF2(oacc2[d4][0], pp2, v2.x); FMAF2(oacc2[d4][1], pp2, v2.y);
                FMAF2(oacc2[d4][0], pp3, v3.x); FMAF2(oacc2[d4][1], pp3, v3.y);
            }
        }
        __syncthreads();
    }

    float linv = 1.0f / Ls[qi];
    float* obase = g_attn + (size_t)(b * S_LEN + q0 + qi) * EMB + h * HD;
    #pragma unroll
    for (int d4 = 0; d4 < 8; d4++) {
        int c = d4 * 4 + part;
        float f0, f1, f2, f3;
        UNPACKF2(f0, f1, oacc2[d4][0]);
        UNPACKF2(f2, f3, oacc2[d4][1]);
        *(float4*)&obase[c * 4] = make_float4(f0 * linv, f1 * linv, f2 * linv, f3 * linv);
    }
}

// ---------------- launch ----------------------------------------------------------
extern "C" void kernel_launch(void* const* d_in, const int* in_sizes, int n_in,
                              void* d_out, int out_size)
{
    const float* x   = (const float*)d_in[0];
    const float* Wq  = (const float*)d_in[1];
    const float* bq  = (const float*)d_in[2];
    const float* Wkv = (const float*)d_in[3];
    const float* bkv = (const float*)d_in[4];
    const float* Wo  = (const float*)d_in[5];
    float* out = (float*)d_out;

    float *qp, *kvp, *ap;
    cudaGetSymbolAddress((void**)&qp,  g_q);
    cudaGetSymbolAddress((void**)&kvp, g_kv);
    cudaGetSymbolAddress((void**)&ap,  g_attn);

    const int attn_smem = ATTN_SMEM_FLOATS * (int)sizeof(float);   // 117504 B
    cudaFuncSetAttribute(attn_kernel, cudaFuncAttributeMaxDynamicSharedMemorySize, attn_smem);

    dim3 blk(256);

    init_invfreq_kernel<<<1, 64>>>();

    // Q = x @ Wq^T + bq  : M=4096, N=2048, K=2048
    gemm_tn<<<dim3(16, 32), blk>>>(x, Wq, bq, qp, EMB, EMB);
    // KV = x @ Wkv^T + bkv : M=4096, N=1024, K=2048
    gemm_tn<<<dim3(8, 32), blk>>>(x, Wkv, bkv, kvp, KVW, EMB);

    rope_kernel<<<(NBATCH * S_LEN * NHEADS * 64 + 255) / 256, 256>>>(0);
    rope_kernel<<<(NBATCH * S_LEN * NKV    * 64 + 255) / 256, 256>>>(1);

    attn_kernel<<<dim3(S_LEN / 64, NHEADS, NBATCH), blk, attn_smem>>>();

    // out = attn @ Wo^T : M=4096, N=2048, K=2048
    gemm_tn<<<dim3(16, 32), blk>>>(ap, Wo, nullptr, out, EMB, EMB);
}

// round 3
// speedup vs baseline: 1.2746x; 1.2746x over previous
#include <cuda_runtime.h>
#include <cuda_bf16.h>
#include <math.h>
#include <stdint.h>

#define S_LEN   2048
#define NBATCH  2
#define EMB     2048
#define NHEADS  16
#define NKV     4
#define HD      128
#define KVW     1024   // 2*NKV*HD

typedef unsigned long long u64;

// ---------------- scratch (device globals: no allocation allowed) ----------------
__device__ float  g_q   [(size_t)NBATCH * S_LEN * EMB];   // 32 MB
__device__ float  g_kv  [(size_t)NBATCH * S_LEN * KVW];   // 16 MB
__device__ float  g_attn[(size_t)NBATCH * S_LEN * EMB];   // 32 MB
__device__ double g_invfreq[64];

// ---------------- packed f32x2 helpers -------------------------------------------
#define PACKF2(d, lo, hi) \
    asm("mov.b64 %0, {%1, %2};" : "=l"(d) : "r"(__float_as_uint(lo)), "r"(__float_as_uint(hi)))
#define UNPACKF2(lo, hi, v) do { unsigned int _u0, _u1;                                  \
    asm("mov.b64 {%0, %1}, %2;" : "=r"(_u0), "=r"(_u1) : "l"(v));                        \
    (lo) = __uint_as_float(_u0); (hi) = __uint_as_float(_u1); } while (0)
#define FMAF2(acc, a, b) \
    asm("fma.rn.f32x2 %0, %1, %2, %0;" : "+l"(acc) : "l"(a), "l"(b))
#define MULF2(d, a, b) \
    asm("mul.rn.f32x2 %0, %1, %2;" : "=l"(d) : "l"(a), "l"(b))

// ---------------- fast exp --------------------------------------------------------
__device__ __forceinline__ float fast_exp(float x) {
    float y  = fmaxf(x * 1.4426950408889634f, -127.0f);
    float fl = floorf(y);
    float f  = y - fl;
    float p  = 1.5403530e-4f;
    p = fmaf(p, f, 1.3333558e-3f);
    p = fmaf(p, f, 9.6181291e-3f);
    p = fmaf(p, f, 5.5504109e-2f);
    p = fmaf(p, f, 2.4022651e-1f);
    p = fmaf(p, f, 6.9314718e-1f);
    p = fmaf(p, f, 1.0f);
    int e = (int)fl;
    float s = __int_as_float((e + 127) << 23);
    return p * s;
}

// ---------------- mma.sync helpers ------------------------------------------------
__device__ __forceinline__ uint32_t smem_u32(const void* p) {
    uint32_t a;
    asm("{ .reg .u64 t; cvta.to.shared.u64 t, %1; cvt.u32.u64 %0, t; }" : "=r"(a) : "l"(p));
    return a;
}
#define LDSM_X4(r0, r1, r2, r3, addr) \
    asm volatile("ldmatrix.sync.aligned.m8n8.x4.shared.b16 {%0,%1,%2,%3}, [%4];" \
        : "=r"(r0), "=r"(r1), "=r"(r2), "=r"(r3) : "r"(addr))
#define MMA16816(c0, c1, c2, c3, a0, a1, a2, a3, b0, b1) \
    asm volatile("mma.sync.aligned.m16n8k16.row.col.f32.bf16.bf16.f32 " \
        "{%0,%1,%2,%3}, {%4,%5,%6,%7}, {%8,%9}, {%0,%1,%2,%3};" \
        : "+f"(c0), "+f"(c1), "+f"(c2), "+f"(c3) \
        : "r"(a0), "r"(a1), "r"(a2), "r"(a3), "r"(b0), "r"(b1))

// ================= HMMA GEMM: C[M,N] = A[M,K] @ W[N,K]^T (+bias) =================
// bf16 hi/lo split: C = Ahi*Whi + Ahi*Wlo + Alo*Whi (fp32 accum in registers).
// 128x128 CTA tile, 8 warps (2x4), warp tile 64x32, K-chunk 32, double buffer.
#define GP_ROW    40                     // padded row: 40 bf16 = 80 B (conflict-free LDSM)
#define GP_TILE   (128 * GP_ROW * 2)     // 10240 B per tile
#define GP_BUF    (4 * GP_TILE)          // Ahi, Alo, Whi, Wlo
#define GEMM_SMEM (2 * GP_BUF)           // 81920 B

__global__ __launch_bounds__(256, 1)
void gemm_mma(const float* __restrict__ A, const float* __restrict__ W,
              const float* __restrict__ bias, float* __restrict__ C,
              int N, int K)
{
    extern __shared__ char smp[];
    const uint32_t sbase = smem_u32(smp);

    const int tid  = threadIdx.x;
    const int wid  = tid >> 5;
    const int lane = tid & 31;
    const int m0   = blockIdx.y * 128;
    const int n0   = blockIdx.x * 128;
    const int wm   = (wid >> 2) * 64;     // warp M offset in tile
    const int wn   = (wid & 3) * 32;      // warp N offset in tile

    // ldmatrix per-lane offsets (bytes) within a tile region
    const int rIT  = lane & 7;
    const int b0_  = (lane >> 3) & 1;
    const int b1_  = (lane >> 4) & 1;
    const uint32_t aLane = (uint32_t)(((b0_ * 8 + rIT) * GP_ROW + b1_ * 8) * 2);
    const uint32_t bLane = (uint32_t)(((b1_ * 8 + rIT) * GP_ROW + b0_ * 8) * 2);

    float acc[4][4][4];
    #pragma unroll
    for (int i = 0; i < 4; i++)
        #pragma unroll
        for (int j = 0; j < 4; j++)
            #pragma unroll
            for (int e = 0; e < 4; e++) acc[i][j][e] = 0.f;

    const int r_   = tid >> 3;           // 0..31 base row (+32 per it)
    const int k4_  = tid & 7;            // float4 index along 32-col chunk

    float4 pa[4], pw[4];
    const int nch = K >> 5;              // K / 32

    // ---- helpers as macros over locals ----
    #define LOAD_CHUNK(c) do {                                                          \
        int _k0 = (c) << 5;                                                             \
        _Pragma("unroll")                                                               \
        for (int it = 0; it < 4; it++) {                                                \
            int r = r_ + it * 32;                                                       \
            pa[it] = *(const float4*)&A[(size_t)(m0 + r) * K + _k0 + k4_ * 4];          \
            pw[it] = *(const float4*)&W[(size_t)(n0 + r) * K + _k0 + k4_ * 4];          \
        }                                                                               \
    } while (0)

    #define CVT_STORE(vv, hip, lop, off) do {                                           \
        __nv_bfloat162 _h01 = __floats2bfloat162_rn((vv).x, (vv).y);                    \
        __nv_bfloat162 _h23 = __floats2bfloat162_rn((vv).z, (vv).w);                    \
        float _r0 = (vv).x - __bfloat162float(_h01.x);                                  \
        float _r1 = (vv).y - __bfloat162float(_h01.y);                                  \
        float _r2 = (vv).z - __bfloat162float(_h23.x);                                  \
        float _r3 = (vv).w - __bfloat162float(_h23.y);                                  \
        __nv_bfloat162 _l01 = __floats2bfloat162_rn(_r0, _r1);                          \
        __nv_bfloat162 _l23 = __floats2bfloat162_rn(_r2, _r3);                          \
        uint2 _hv; _hv.x = *(uint32_t*)&_h01; _hv.y = *(uint32_t*)&_h23;                \
        uint2 _lv; _lv.x = *(uint32_t*)&_l01; _lv.y = *(uint32_t*)&_l23;                \
        *(uint2*)(hip + (off)) = _hv;                                                   \
        *(uint2*)(lop + (off)) = _lv;                                                   \
    } while (0)

    #define STORE_CHUNK(buf) do {                                                      \
        char* _b  = smp + (buf) * GP_BUF;                                              \
        char* _Ah = _b;                                                                \
        char* _Al = _b + GP_TILE;                                                      \
        char* _Wh = _b + 2 * GP_TILE;                                                  \
        char* _Wl = _b + 3 * GP_TILE;                                                  \
        _Pragma("unroll")                                                              \
        for (int it = 0; it < 4; it++) {                                               \
            int r = r_ + it * 32;                                                      \
            uint32_t off = (uint32_t)((r * GP_ROW + k4_ * 4) * 2);                     \
            CVT_STORE(pa[it], _Ah, _Al, off);                                          \
            CVT_STORE(pw[it], _Wh, _Wl, off);                                          \
        }                                                                              \
    } while (0)

    LOAD_CHUNK(0);
    STORE_CHUNK(0);
    __syncthreads();

    for (int c = 0; c < nch; c++) {
        if (c + 1 < nch) LOAD_CHUNK(c + 1);

        const uint32_t bb  = sbase + (uint32_t)((c & 1) * GP_BUF);
        const uint32_t Ah  = bb;
        const uint32_t Al  = bb + GP_TILE;
        const uint32_t Wh  = bb + 2 * GP_TILE;
        const uint32_t Wl  = bb + 3 * GP_TILE;

        #pragma unroll
        for (int ks = 0; ks < 2; ks++) {
            const uint32_t kOff = (uint32_t)(ks * 32);   // 16 bf16 = 32 B
            uint32_t ah[4][4], al[4][4], bh[4][2], bl[4][2];
            // load A-hi fragments (4x ldmatrix.x4)
            #pragma unroll
            for (int mf = 0; mf < 4; mf++) {
                uint32_t addr = Ah + (uint32_t)((wm + mf * 16) * GP_ROW * 2) + kOff + aLane;
                LDSM_X4(ah[mf][0], ah[mf][1], ah[mf][2], ah[mf][3], addr);
            }
            // load W-hi fragments (2x ldmatrix.x4 -> 4 n-frags)
            #pragma unroll
            for (int np = 0; np < 2; np++) {
                uint32_t addr = Wh + (uint32_t)((wn + np * 16) * GP_ROW * 2) + kOff + bLane;
                uint32_t r0, r1, r2, r3;
                LDSM_X4(r0, r1, r2, r3, addr);
                bh[np * 2][0] = r0; bh[np * 2][1] = r1;
                bh[np * 2 + 1][0] = r2; bh[np * 2 + 1][1] = r3;
            }
            // pass 1: Ahi * Whi
            #pragma unroll
            for (int mf = 0; mf < 4; mf++)
                #pragma unroll
                for (int nf = 0; nf < 4; nf++)
                    MMA16816(acc[mf][nf][0], acc[mf][nf][1], acc[mf][nf][2], acc[mf][nf][3],
                             ah[mf][0], ah[mf][1], ah[mf][2], ah[mf][3],
                             bh[nf][0], bh[nf][1]);
            // load W-lo
            #pragma unroll
            for (int np = 0; np < 2; np++) {
                uint32_t addr = Wl + (uint32_t)((wn + np * 16) * GP_ROW * 2) + kOff + bLane;
                uint32_t r0, r1, r2, r3;
                LDSM_X4(r0, r1, r2, r3, addr);
                bl[np * 2][0] = r0; bl[np * 2][1] = r1;
                bl[np * 2 + 1][0] = r2; bl[np * 2 + 1][1] = r3;
            }
            // pass 2: Ahi * Wlo
            #pragma unroll
            for (int mf = 0; mf < 4; mf++)
                #pragma unroll
                for (int nf = 0; nf < 4; nf++)
                    MMA16816(acc[mf][nf][0], acc[mf][nf][1], acc[mf][nf][2], acc[mf][nf][3],
                             ah[mf][0], ah[mf][1], ah[mf][2], ah[mf][3],
                             bl[nf][0], bl[nf][1]);
            // load A-lo
            #pragma unroll
            for (int mf = 0; mf < 4; mf++) {
                uint32_t addr = Al + (uint32_t)((wm + mf * 16) * GP_ROW * 2) + kOff + aLane;
                LDSM_X4(al[mf][0], al[mf][1], al[mf][2], al[mf][3], addr);
            }
            // pass 3: Alo * Whi
            #pragma unroll
            for (int mf = 0; mf < 4; mf++)
                #pragma unroll
                for (int nf = 0; nf < 4; nf++)
                    MMA16816(acc[mf][nf][0], acc[mf][nf][1], acc[mf][nf][2], acc[mf][nf][3],
                             al[mf][0], al[mf][1], al[mf][2], al[mf][3],
                             bh[nf][0], bh[nf][1]);
        }

        if (c + 1 < nch) STORE_CHUNK((c + 1) & 1);
        __syncthreads();
    }

    // ---- epilogue ----
    const int trow  = lane >> 2;
    const int tcol2 = (lane & 3) * 2;
    #pragma unroll
    for (int mf = 0; mf < 4; mf++) {
        #pragma unroll
        for (int nf = 0; nf < 4; nf++) {
            int row = m0 + wm + mf * 16 + trow;
            int col = n0 + wn + nf * 8 + tcol2;
            float c0 = acc[mf][nf][0], c1 = acc[mf][nf][1];
            float c2 = acc[mf][nf][2], c3 = acc[mf][nf][3];
            if (bias) {
                float2 bv = *(const float2*)&bias[col];
                c0 += bv.x; c1 += bv.y; c2 += bv.x; c3 += bv.y;
            }
            *(float2*)&C[(size_t)row * N + col]       = make_float2(c0, c1);
            *(float2*)&C[(size_t)(row + 8) * N + col] = make_float2(c2, c3);
        }
    }
    #undef LOAD_CHUNK
    #undef CVT_STORE
    #undef STORE_CHUNK
}

// ---------------- RoPE ------------------------------------------------------------
__global__ void init_invfreq_kernel() {
    int d = threadIdx.x;
    if (d < 64) g_invfreq[d] = pow(10000.0, -(double)d / 64.0);
}

__global__ void rope_kernel(int which) {
    float* buf   = which ? g_kv : g_q;
    int nHeads   = which ? NKV : NHEADS;
    int rowW     = which ? KVW : EMB;
    int idx = blockIdx.x * blockDim.x + threadIdx.x;
    int total = NBATCH * S_LEN * nHeads * 64;
    if (idx >= total) return;
    int d = idx & 63;
    int h = (idx >> 6) % nHeads;
    int r = idx / (64 * nHeads);
    int s = r & (S_LEN - 1);
    size_t base = (size_t)r * rowW + h * HD;
    float t1 = buf[base + d];
    float t2 = buf[base + 64 + d];
    double ang = (double)s * g_invfreq[d];
    double k   = floor(ang * 0.15915494309189535);
    float a    = (float)(ang - k * 6.283185307179586);
    float sn, cs;
    sincosf(a, &sn, &cs);
    buf[base + d]      = t1 * cs - t2 * sn;
    buf[base + 64 + d] = t2 * cs + t1 * sn;
}

// ---------------- attention (flash-style, 64q x 64k tiles, online softmax) --------
#define ATTN_SMEM_FLOATS (64*132 + 64*132 + 64*128 + 64*65 + 64 + 64)

__global__ __launch_bounds__(256, 1) void attn_kernel() {
    extern __shared__ float sm[];
    float* Qs = sm;
    float* Ks = Qs + 64 * 132;
    float* Vs = Ks + 64 * 132;
    float* Sc = Vs + 64 * 128;
    float* Ms = Sc + 64 * 65;
    float* Ls = Ms + 64;

    const int tid  = threadIdx.x;
    const int q0   = blockIdx.x * 64;
    const int h    = blockIdx.y;
    const int b    = blockIdx.z;
    const int kvh  = h >> 2;
    const int qi   = tid >> 2;
    const int part = tid & 3;
    const float scale = 0.08838834764831845f;

    const float* qbase = g_q + (size_t)(b * S_LEN + q0) * EMB + h * HD;
    #pragma unroll
    for (int it = 0; it < 8; it++) {
        int idx = tid + it * 256;
        int row = idx >> 5, c4 = idx & 31;
        float4 v = *(const float4*)&qbase[(size_t)row * EMB + c4 * 4];
        v.x *= scale; v.y *= scale; v.z *= scale; v.w *= scale;
        *(float4*)&Qs[row * 132 + c4 * 4] = v;
    }
    if (tid < 64) { Ms[tid] = -1e30f; Ls[tid] = 0.f; }

    u64 oacc2[8][2];
    #pragma unroll
    for (int i = 0; i < 8; i++) { oacc2[i][0] = 0ull; oacc2[i][1] = 0ull; }

    const float* kbase = g_kv + (size_t)(b * S_LEN) * KVW + kvh * HD;
    const float* vbase = kbase + NKV * HD;

    for (int t = 0; t < 32; t++) {
        int j0 = t * 64;
        #pragma unroll
        for (int it = 0; it < 8; it++) {
            int idx = tid + it * 256;
            int row = idx >> 5, c4 = idx & 31;
            *(float4*)&Ks[row * 132 + c4 * 4] =
                *(const float4*)&kbase[(size_t)(j0 + row) * KVW + c4 * 4];
            *(float4*)&Vs[row * 128 + c4 * 4] =
                *(const float4*)&vbase[(size_t)(j0 + row) * KVW + c4 * 4];
        }
        __syncthreads();

        u64 sacc[16];
        #pragma unroll
        for (int jj = 0; jj < 16; jj++) sacc[jj] = 0ull;
        #pragma unroll 2
        for (int d4 = 0; d4 < 32; d4++) {
            ulonglong2 qq = *(const ulonglong2*)&Qs[qi * 132 + d4 * 4];
            #pragma unroll
            for (int jj = 0; jj < 16; jj++) {
                ulonglong2 kp = *(const ulonglong2*)&Ks[(jj * 4 + part) * 132 + d4 * 4];
                FMAF2(sacc[jj], qq.x, kp.x);
                FMAF2(sacc[jj], qq.y, kp.y);
            }
        }
        float scv[16];
        float lmax = -1e30f;
        #pragma unroll
        for (int jj = 0; jj < 16; jj++) {
            float lo, hi; UNPACKF2(lo, hi, sacc[jj]);
            scv[jj] = lo + hi;
            lmax = fmaxf(lmax, scv[jj]);
        }
        lmax = fmaxf(lmax, __shfl_xor_sync(0xffffffffu, lmax, 1));
        lmax = fmaxf(lmax, __shfl_xor_sync(0xffffffffu, lmax, 2));
        float mold = Ms[qi];
        float lold = Ls[qi];
        float mnew = fmaxf(mold, lmax);
        float alpha = fast_exp(mold - mnew);
        float psum = 0.f;
        #pragma unroll
        for (int jj = 0; jj < 16; jj++) {
            float p = fast_exp(scv[jj] - mnew);
            Sc[qi * 65 + jj * 4 + part] = p;
            psum += p;
        }
        psum += __shfl_xor_sync(0xffffffffu, psum, 1);
        psum += __shfl_xor_sync(0xffffffffu, psum, 2);
        __syncwarp();
        if (part == 0) { Ms[qi] = mnew; Ls[qi] = lold * alpha + psum; }

        u64 alpha2; PACKF2(alpha2, alpha, alpha);
        #pragma unroll
        for (int i = 0; i < 8; i++) {
            MULF2(oacc2[i][0], oacc2[i][0], alpha2);
            MULF2(oacc2[i][1], oacc2[i][1], alpha2);
        }
        __syncwarp();
        #pragma unroll 2
        for (int j4 = 0; j4 < 16; j4++) {
            float p0 = Sc[qi * 65 + j4 * 4 + 0];
            float p1 = Sc[qi * 65 + j4 * 4 + 1];
            float p2 = Sc[qi * 65 + j4 * 4 + 2];
            float p3 = Sc[qi * 65 + j4 * 4 + 3];
            u64 pp0, pp1, pp2, pp3;
            PACKF2(pp0, p0, p0); PACKF2(pp1, p1, p1);
            PACKF2(pp2, p2, p2); PACKF2(pp3, p3, p3);
            #pragma unroll
            for (int d4 = 0; d4 < 8; d4++) {
                int c = d4 * 4 + part;
                ulonglong2 v0 = *(const ulonglong2*)&Vs[(j4 * 4 + 0) * 128 + c * 4];
                ulonglong2 v1 = *(const ulonglong2*)&Vs[(j4 * 4 + 1) * 128 + c * 4];
                ulonglong2 v2 = *(const ulonglong2*)&Vs[(j4 * 4 + 2) * 128 + c * 4];
                ulonglong2 v3 = *(const ulonglong2*)&Vs[(j4 * 4 + 3) * 128 + c * 4];
                FMAF2(oacc2[d4][0], pp0, v0.x); FMAF2(oacc2[d4][1], pp0, v0.y);
                FMAF2(oacc2[d4][0], pp1, v1.x); FMAF2(oacc2[d4][1], pp1, v1.y);
                FMAF2(oacc2[d4][0], pp2, v2.x); FMAF2(oacc2[d4][1], pp2, v2.y);
                FMAF2(oacc2[d4][0], pp3, v3.x); FMAF2(oacc2[d4][1], pp3, v3.y);
            }
        }
        __syncthreads();
    }

    float linv = 1.0f / Ls[qi];
    float* obase = g_attn + (size_t)(b * S_LEN + q0 + qi) * EMB + h * HD;
    #pragma unroll
    for (int d4 = 0; d4 < 8; d4++) {
        int c = d4 * 4 + part;
        float f0, f1, f2, f3;
        UNPACKF2(f0, f1, oacc2[d4][0]);
        UNPACKF2(f2, f3, oacc2[d4][1]);
        *(float4*)&obase[c * 4] = make_float4(f0 * linv, f1 * linv, f2 * linv, f3 * linv);
    }
}

// ---------------- launch ----------------------------------------------------------
extern "C" void kernel_launch(void* const* d_in, const int* in_sizes, int n_in,
                              void* d_out, int out_size)
{
    const float* x   = (const float*)d_in[0];
    const float* Wq  = (const float*)d_in[1];
    const float* bq  = (const float*)d_in[2];
    const float* Wkv = (const float*)d_in[3];
    const float* bkv = (const float*)d_in[4];
    const float* Wo  = (const float*)d_in[5];
    float* out = (float*)d_out;

    float *qp, *kvp, *ap;
    cudaGetSymbolAddress((void**)&qp,  g_q);
    cudaGetSymbolAddress((void**)&kvp, g_kv);
    cudaGetSymbolAddress((void**)&ap,  g_attn);

    const int attn_smem = ATTN_SMEM_FLOATS * (int)sizeof(float);
    cudaFuncSetAttribute(attn_kernel, cudaFuncAttributeMaxDynamicSharedMemorySize, attn_smem);
    cudaFuncSetAttribute(gemm_mma, cudaFuncAttributeMaxDynamicSharedMemorySize, GEMM_SMEM);

    dim3 blk(256);

    init_invfreq_kernel<<<1, 64>>>();

    // Q = x @ Wq^T + bq  : M=4096, N=2048, K=2048
    gemm_mma<<<dim3(16, 32), blk, GEMM_SMEM>>>(x, Wq, bq, qp, EMB, EMB);
    // KV = x @ Wkv^T + bkv : M=4096, N=1024, K=2048
    gemm_mma<<<dim3(8, 32), blk, GEMM_SMEM>>>(x, Wkv, bkv, kvp, KVW, EMB);

    rope_kernel<<<(NBATCH * S_LEN * NHEADS * 64 + 255) / 256, 256>>>(0);
    rope_kernel<<<(NBATCH * S_LEN * NKV    * 64 + 255) / 256, 256>>>(1);

    attn_kernel<<<dim3(S_LEN / 64, NHEADS, NBATCH), blk, attn_smem>>>();

    // out = attn @ Wo^T : M=4096, N=2048, K=2048
    gemm_mma<<<dim3(16, 32), blk, GEMM_SMEM>>>(ap, Wo, nullptr, out, EMB, EMB);
}

// round 4
// speedup vs baseline: 4.1692x; 3.2709x over previous
#include <cuda_runtime.h>
#include <cuda_bf16.h>
#include <math.h>
#include <stdint.h>

#define S_LEN   2048
#define NBATCH  2
#define EMB     2048
#define NHEADS  16
#define NKV     4
#define HD      128
#define KVW     1024   // 2*NKV*HD

typedef unsigned long long u64;

// ---------------- scratch (device globals: no allocation allowed) ----------------
__device__ float  g_q   [(size_t)NBATCH * S_LEN * EMB];   // fp32 Q proj
__device__ float  g_kv  [(size_t)NBATCH * S_LEN * KVW];   // fp32 KV proj
__device__ float  g_attn[(size_t)NBATCH * S_LEN * EMB];   // attention out
__device__ double g_invfreq[64];
// bf16 hi/lo operands for attention
__device__ __nv_bfloat16 g_qh[(size_t)NBATCH * S_LEN * EMB];
__device__ __nv_bfloat16 g_ql[(size_t)NBATCH * S_LEN * EMB];
__device__ __nv_bfloat16 g_kh[(size_t)NBATCH * S_LEN * NKV * HD];
__device__ __nv_bfloat16 g_kl[(size_t)NBATCH * S_LEN * NKV * HD];
__device__ __nv_bfloat16 g_vh[(size_t)NBATCH * S_LEN * NKV * HD];
__device__ __nv_bfloat16 g_vl[(size_t)NBATCH * S_LEN * NKV * HD];

// ---------------- fast exp --------------------------------------------------------
__device__ __forceinline__ float fast_exp(float x) {
    float y  = fmaxf(x * 1.4426950408889634f, -127.0f);
    float fl = floorf(y);
    float f  = y - fl;
    float p  = 1.5403530e-4f;
    p = fmaf(p, f, 1.3333558e-3f);
    p = fmaf(p, f, 9.6181291e-3f);
    p = fmaf(p, f, 5.5504109e-2f);
    p = fmaf(p, f, 2.4022651e-1f);
    p = fmaf(p, f, 6.9314718e-1f);
    p = fmaf(p, f, 1.0f);
    int e = (int)fl;
    float s = __int_as_float((e + 127) << 23);
    return p * s;
}

// ---------------- mma.sync / ldmatrix / cp.async helpers --------------------------
__device__ __forceinline__ uint32_t smem_u32(const void* p) {
    uint32_t a;
    asm("{ .reg .u64 t; cvta.to.shared.u64 t, %1; cvt.u32.u64 %0, t; }" : "=r"(a) : "l"(p));
    return a;
}
#define LDSM_X4(r0, r1, r2, r3, addr) \
    asm volatile("ldmatrix.sync.aligned.m8n8.x4.shared.b16 {%0,%1,%2,%3}, [%4];" \
        : "=r"(r0), "=r"(r1), "=r"(r2), "=r"(r3) : "r"(addr))
#define LDSM_T_X4(r0, r1, r2, r3, addr) \
    asm volatile("ldmatrix.sync.aligned.m8n8.x4.trans.shared.b16 {%0,%1,%2,%3}, [%4];" \
        : "=r"(r0), "=r"(r1), "=r"(r2), "=r"(r3) : "r"(addr))
#define MMA16816(c0, c1, c2, c3, a0, a1, a2, a3, b0, b1) \
    asm volatile("mma.sync.aligned.m16n8k16.row.col.f32.bf16.bf16.f32 " \
        "{%0,%1,%2,%3}, {%4,%5,%6,%7}, {%8,%9}, {%0,%1,%2,%3};" \
        : "+f"(c0), "+f"(c1), "+f"(c2), "+f"(c3) \
        : "r"(a0), "r"(a1), "r"(a2), "r"(a3), "r"(b0), "r"(b1))
#define CP16(d, s) \
    asm volatile("cp.async.cg.shared.global [%0], [%1], 16;" :: "r"(d), "l"(s))
#define CP_COMMIT asm volatile("cp.async.commit_group;" ::: "memory")
#define CP_WAIT1  asm volatile("cp.async.wait_group 1;" ::: "memory")
#define CP_WAIT0  asm volatile("cp.async.wait_group 0;" ::: "memory")

// ================= HMMA GEMM: C[M,N] = A[M,K] @ W[N,K]^T (+bias) =================
#define GP_ROW    40
#define GP_TILE   (128 * GP_ROW * 2)
#define GP_BUF    (4 * GP_TILE)
#define GEMM_SMEM (2 * GP_BUF)

__global__ __launch_bounds__(256, 1)
void gemm_mma(const float* __restrict__ A, const float* __restrict__ W,
              const float* __restrict__ bias, float* __restrict__ C,
              int N, int K)
{
    extern __shared__ char smp[];
    const uint32_t sbase = smem_u32(smp);

    const int tid  = threadIdx.x;
    const int wid  = tid >> 5;
    const int lane = tid & 31;
    const int m0   = blockIdx.y * 128;
    const int n0   = blockIdx.x * 128;
    const int wm   = (wid >> 2) * 64;
    const int wn   = (wid & 3) * 32;

    const int rIT  = lane & 7;
    const int b0_  = (lane >> 3) & 1;
    const int b1_  = (lane >> 4) & 1;
    const uint32_t aLane = (uint32_t)(((b0_ * 8 + rIT) * GP_ROW + b1_ * 8) * 2);
    const uint32_t bLane = (uint32_t)(((b1_ * 8 + rIT) * GP_ROW + b0_ * 8) * 2);

    float acc[4][4][4];
    #pragma unroll
    for (int i = 0; i < 4; i++)
        #pragma unroll
        for (int j = 0; j < 4; j++)
            #pragma unroll
            for (int e = 0; e < 4; e++) acc[i][j][e] = 0.f;

    const int r_   = tid >> 3;
    const int k4_  = tid & 7;

    float4 pa[4], pw[4];
    const int nch = K >> 5;

    #define LOAD_CHUNK(c) do {                                                          \
        int _k0 = (c) << 5;                                                             \
        _Pragma("unroll")                                                               \
        for (int it = 0; it < 4; it++) {                                                \
            int r = r_ + it * 32;                                                       \
            pa[it] = *(const float4*)&A[(size_t)(m0 + r) * K + _k0 + k4_ * 4];          \
            pw[it] = *(const float4*)&W[(size_t)(n0 + r) * K + _k0 + k4_ * 4];          \
        }                                                                               \
    } while (0)

    #define CVT_STORE(vv, hip, lop, off) do {                                           \
        __nv_bfloat162 _h01 = __floats2bfloat162_rn((vv).x, (vv).y);                    \
        __nv_bfloat162 _h23 = __floats2bfloat162_rn((vv).z, (vv).w);                    \
        float _r0 = (vv).x - __bfloat162float(_h01.x);                                  \
        float _r1 = (vv).y - __bfloat162float(_h01.y);                                  \
        float _r2 = (vv).z - __bfloat162float(_h23.x);                                  \
        float _r3 = (vv).w - __bfloat162float(_h23.y);                                  \
        __nv_bfloat162 _l01 = __floats2bfloat162_rn(_r0, _r1);                          \
        __nv_bfloat162 _l23 = __floats2bfloat162_rn(_r2, _r3);                          \
        uint2 _hv; _hv.x = *(uint32_t*)&_h01; _hv.y = *(uint32_t*)&_h23;                \
        uint2 _lv; _lv.x = *(uint32_t*)&_l01; _lv.y = *(uint32_t*)&_l23;                \
        *(uint2*)(hip + (off)) = _hv;                                                   \
        *(uint2*)(lop + (off)) = _lv;                                                   \
    } while (0)

    #define STORE_CHUNK(buf) do {                                                      \
        char* _b  = smp + (buf) * GP_BUF;                                              \
        char* _Ah = _b;                                                                \
        char* _Al = _b + GP_TILE;                                                      \
        char* _Wh = _b + 2 * GP_TILE;                                                  \
        char* _Wl = _b + 3 * GP_TILE;                                                  \
        _Pragma("unroll")                                                              \
        for (int it = 0; it < 4; it++) {                                               \
            int r = r_ + it * 32;                                                      \
            uint32_t off = (uint32_t)((r * GP_ROW + k4_ * 4) * 2);                     \
            CVT_STORE(pa[it], _Ah, _Al, off);                                          \
            CVT_STORE(pw[it], _Wh, _Wl, off);                                          \
        }                                                                              \
    } while (0)

    LOAD_CHUNK(0);
    STORE_CHUNK(0);
    __syncthreads();

    for (int c = 0; c < nch; c++) {
        if (c + 1 < nch) LOAD_CHUNK(c + 1);

        const uint32_t bb  = sbase + (uint32_t)((c & 1) * GP_BUF);
        const uint32_t Ah  = bb;
        const uint32_t Al  = bb + GP_TILE;
        const uint32_t Wh  = bb + 2 * GP_TILE;
        const uint32_t Wl  = bb + 3 * GP_TILE;

        #pragma unroll
        for (int ks = 0; ks < 2; ks++) {
            const uint32_t kOff = (uint32_t)(ks * 32);
            uint32_t ah[4][4], al[4][4], bh[4][2], bl[4][2];
            #pragma unroll
            for (int mf = 0; mf < 4; mf++) {
                uint32_t addr = Ah + (uint32_t)((wm + mf * 16) * GP_ROW * 2) + kOff + aLane;
                LDSM_X4(ah[mf][0], ah[mf][1], ah[mf][2], ah[mf][3], addr);
            }
            #pragma unroll
            for (int np = 0; np < 2; np++) {
                uint32_t addr = Wh + (uint32_t)((wn + np * 16) * GP_ROW * 2) + kOff + bLane;
                uint32_t r0, r1, r2, r3;
                LDSM_X4(r0, r1, r2, r3, addr);
                bh[np * 2][0] = r0; bh[np * 2][1] = r1;
                bh[np * 2 + 1][0] = r2; bh[np * 2 + 1][1] = r3;
            }
            #pragma unroll
            for (int mf = 0; mf < 4; mf++)
                #pragma unroll
                for (int nf = 0; nf < 4; nf++)
                    MMA16816(acc[mf][nf][0], acc[mf][nf][1], acc[mf][nf][2], acc[mf][nf][3],
                             ah[mf][0], ah[mf][1], ah[mf][2], ah[mf][3],
                             bh[nf][0], bh[nf][1]);
            #pragma unroll
            for (int np = 0; np < 2; np++) {
                uint32_t addr = Wl + (uint32_t)((wn + np * 16) * GP_ROW * 2) + kOff + bLane;
                uint32_t r0, r1, r2, r3;
                LDSM_X4(r0, r1, r2, r3, addr);
                bl[np * 2][0] = r0; bl[np * 2][1] = r1;
                bl[np * 2 + 1][0] = r2; bl[np * 2 + 1][1] = r3;
            }
            #pragma unroll
            for (int mf = 0; mf < 4; mf++)
                #pragma unroll
                for (int nf = 0; nf < 4; nf++)
                    MMA16816(acc[mf][nf][0], acc[mf][nf][1], acc[mf][nf][2], acc[mf][nf][3],
                             ah[mf][0], ah[mf][1], ah[mf][2], ah[mf][3],
                             bl[nf][0], bl[nf][1]);
            #pragma unroll
            for (int mf = 0; mf < 4; mf++) {
                uint32_t addr = Al + (uint32_t)((wm + mf * 16) * GP_ROW * 2) + kOff + aLane;
                LDSM_X4(al[mf][0], al[mf][1], al[mf][2], al[mf][3], addr);
            }
            #pragma unroll
            for (int mf = 0; mf < 4; mf++)
                #pragma unroll
                for (int nf = 0; nf < 4; nf++)
                    MMA16816(acc[mf][nf][0], acc[mf][nf][1], acc[mf][nf][2], acc[mf][nf][3],
                             al[mf][0], al[mf][1], al[mf][2], al[mf][3],
                             bh[nf][0], bh[nf][1]);
        }

        if (c + 1 < nch) STORE_CHUNK((c + 1) & 1);
        __syncthreads();
    }

    const int trow  = lane >> 2;
    const int tcol2 = (lane & 3) * 2;
    #pragma unroll
    for (int mf = 0; mf < 4; mf++) {
        #pragma unroll
        for (int nf = 0; nf < 4; nf++) {
            int row = m0 + wm + mf * 16 + trow;
            int col = n0 + wn + nf * 8 + tcol2;
            float c0 = acc[mf][nf][0], c1 = acc[mf][nf][1];
            float c2 = acc[mf][nf][2], c3 = acc[mf][nf][3];
            if (bias) {
                float2 bv = *(const float2*)&bias[col];
                c0 += bv.x; c1 += bv.y; c2 += bv.x; c3 += bv.y;
            }
            *(float2*)&C[(size_t)row * N + col]       = make_float2(c0, c1);
            *(float2*)&C[(size_t)(row + 8) * N + col] = make_float2(c2, c3);
        }
    }
    #undef LOAD_CHUNK
    #undef CVT_STORE
    #undef STORE_CHUNK
}

// ---------------- RoPE -> bf16 hi/lo ----------------------------------------------
__global__ void init_invfreq_kernel() {
    int d = threadIdx.x;
    if (d < 64) g_invfreq[d] = pow(10000.0, -(double)d / 64.0);
}

// which=0: Q (16 heads, width 2048, scale folded); which=1: K (4 heads, width 1024)
__global__ void rope_bf16_kernel(int which) {
    const float* src = which ? g_kv : g_q;
    __nv_bfloat16* oh = which ? g_kh : g_qh;
    __nv_bfloat16* ol = which ? g_kl : g_ql;
    int nHeads   = which ? NKV : NHEADS;
    int rowW     = which ? KVW : EMB;
    int outW     = which ? (NKV * HD) : EMB;
    float sc     = which ? 1.0f : 0.08838834764831845f;   // 1/sqrt(128) on Q
    int idx = blockIdx.x * blockDim.x + threadIdx.x;
    int total = NBATCH * S_LEN * nHeads * 64;
    if (idx >= total) return;
    int d = idx & 63;
    int h = (idx >> 6) % nHeads;
    int r = idx / (64 * nHeads);
    int s = r & (S_LEN - 1);
    size_t base = (size_t)r * rowW + h * HD;
    float t1 = src[base + d];
    float t2 = src[base + 64 + d];
    double ang = (double)s * g_invfreq[d];
    double k   = floor(ang * 0.15915494309189535);
    float a    = (float)(ang - k * 6.283185307179586);
    float sn, cs;
    sincosf(a, &sn, &cs);
    float o1 = (t1 * cs - t2 * sn) * sc;
    float o2 = (t2 * cs + t1 * sn) * sc;
    size_t ob = (size_t)r * outW + h * HD;
    __nv_bfloat16 h1 = __float2bfloat16_rn(o1);
    __nv_bfloat16 h2 = __float2bfloat16_rn(o2);
    oh[ob + d]      = h1;
    oh[ob + 64 + d] = h2;
    ol[ob + d]      = __float2bfloat16_rn(o1 - __bfloat162float(h1));
    ol[ob + 64 + d] = __float2bfloat16_rn(o2 - __bfloat162float(h2));
}

__global__ void vconv_kernel() {
    int idx = blockIdx.x * blockDim.x + threadIdx.x;
    int total = NBATCH * S_LEN * NKV * HD;
    if (idx >= total) return;
    int r = idx >> 9;          // row (b*S + s)
    int c = idx & 511;
    float v = g_kv[(size_t)r * KVW + 512 + c];
    __nv_bfloat16 h = __float2bfloat16_rn(v);
    g_vh[(size_t)r * 512 + c] = h;
    g_vl[(size_t)r * 512 + c] = __float2bfloat16_rn(v - __bfloat162float(h));
}

// ================= HMMA attention (FA2 layout, hi/lo bf16, 3 products) ============
// CTA: 128 q-rows x (h, b). 8 warps x 16 rows. K-tiles of 64 keys, double-buffered.
#define AP        272                    // smem pitch bytes (136 bf16)
#define QT_BYTES  (128 * AP)             // 34816 per Q array
#define KT_BYTES  (64 * AP)              // 17408 per KV array
#define KVBUF     (4 * KT_BYTES)         // 69632
#define ATTN_SMEM (2 * QT_BYTES + 2 * KVBUF)   // 208896

__global__ __launch_bounds__(256, 1) void attn_mma() {
    extern __shared__ char smb[];
    const uint32_t sb = smem_u32(smb);

    const int tid  = threadIdx.x;
    const int wid  = tid >> 5;
    const int lane = tid & 31;
    const int q0   = blockIdx.x * 128;
    const int h    = blockIdx.y;
    const int b    = blockIdx.z;
    const int kvh  = h >> 2;

    const int rIT  = lane & 7;
    const int b3   = (lane >> 3) & 1;
    const int b4   = (lane >> 4) & 1;
    const uint32_t offA = (uint32_t)((b3 * 8 + rIT) * AP + b4 * 16);   // A-frag & V-trans
    const uint32_t offB = (uint32_t)((b4 * 8 + rIT) * AP + b3 * 16);   // K-frag

    const uint32_t Qh_s = sb;
    const uint32_t Ql_s = sb + QT_BYTES;
    const uint32_t KV0  = sb + 2 * QT_BYTES;

    const __nv_bfloat16* qh_g = g_qh + (size_t)(b * S_LEN + q0) * EMB + h * HD;
    const __nv_bfloat16* ql_g = g_ql + (size_t)(b * S_LEN + q0) * EMB + h * HD;
    const __nv_bfloat16* kh_g = g_kh + (size_t)b * S_LEN * 512 + kvh * HD;
    const __nv_bfloat16* kl_g = g_kl + (size_t)b * S_LEN * 512 + kvh * HD;
    const __nv_bfloat16* vh_g = g_vh + (size_t)b * S_LEN * 512 + kvh * HD;
    const __nv_bfloat16* vl_g = g_vl + (size_t)b * S_LEN * 512 + kvh * HD;

    // stage Q (hi+lo) via cp.async
    #pragma unroll
    for (int i = 0; i < 8; i++) {
        int c = tid + i * 256;             // 0..2047
        int row = c >> 4, col = c & 15;
        uint32_t d0 = (uint32_t)(row * AP + col * 16);
        CP16(Qh_s + d0, qh_g + (size_t)row * EMB + col * 8);
        CP16(Ql_s + d0, ql_g + (size_t)row * EMB + col * 8);
    }

    #define LOAD_KV(T, BUF) do {                                                       \
        size_t _j = (size_t)((T) * 64);                                                \
        uint32_t _dst = KV0 + (uint32_t)((BUF) * KVBUF);                               \
        _Pragma("unroll")                                                              \
        for (int _i = 0; _i < 4; _i++) {                                               \
            int _c = tid + _i * 256;                                                   \
            int _row = _c >> 4, _col = _c & 15;                                        \
            uint32_t _d0 = _dst + (uint32_t)(_row * AP + _col * 16);                   \
            size_t _s0 = (_j + _row) * 512 + _col * 8;                                 \
            CP16(_d0,                kh_g + _s0);                                      \
            CP16(_d0 +     KT_BYTES, kl_g + _s0);                                      \
            CP16(_d0 + 2 * KT_BYTES, vh_g + _s0);                                      \
            CP16(_d0 + 3 * KT_BYTES, vl_g + _s0);                                      \
        } } while (0)

    LOAD_KV(0, 0);
    CP_COMMIT;

    float m0 = -1e30f, m1 = -1e30f, l0 = 0.f, l1 = 0.f;
    float ofr[16][4];
    #pragma unroll
    for (int i = 0; i < 16; i++)
        #pragma unroll
        for (int e = 0; e < 4; e++) ofr[i][e] = 0.f;

    const uint32_t qwarp_h = Qh_s + (uint32_t)(wid * 16 * AP);
    const uint32_t qwarp_l = Ql_s + (uint32_t)(wid * 16 * AP);

    for (int t = 0; t < 32; t++) {
        if (t < 31) { LOAD_KV(t + 1, (t + 1) & 1); CP_COMMIT; CP_WAIT1; }
        else        { CP_WAIT0; }
        __syncthreads();

        const uint32_t kvb  = KV0 + (uint32_t)((t & 1) * KVBUF);
        const uint32_t Kh_s = kvb;
        const uint32_t Kl_s = kvb + KT_BYTES;
        const uint32_t Vh_s = kvb + 2 * KT_BYTES;
        const uint32_t Vl_s = kvb + 3 * KT_BYTES;

        // ---- S = Q K^T (3 hi/lo products) ----
        float sfr[8][4];
        #pragma unroll
        for (int i = 0; i < 8; i++)
            #pragma unroll
            for (int e = 0; e < 4; e++) sfr[i][e] = 0.f;

        #pragma unroll
        for (int ks = 0; ks < 8; ks++) {
            uint32_t aqh0, aqh1, aqh2, aqh3, aql0, aql1, aql2, aql3;
            LDSM_X4(aqh0, aqh1, aqh2, aqh3, qwarp_h + ks * 32 + offA);
            LDSM_X4(aql0, aql1, aql2, aql3, qwarp_l + ks * 32 + offA);
            uint32_t bh[8][2], bl[8][2];
            #pragma unroll
            for (int np = 0; np < 4; np++) {
                uint32_t r0, r1, r2, r3;
                LDSM_X4(r0, r1, r2, r3, Kh_s + (uint32_t)(np * 16 * AP) + ks * 32 + offB);
                bh[np * 2][0] = r0; bh[np * 2][1] = r1;
                bh[np * 2 + 1][0] = r2; bh[np * 2 + 1][1] = r3;
                LDSM_X4(r0, r1, r2, r3, Kl_s + (uint32_t)(np * 16 * AP) + ks * 32 + offB);
                bl[np * 2][0] = r0; bl[np * 2][1] = r1;
                bl[np * 2 + 1][0] = r2; bl[np * 2 + 1][1] = r3;
            }
            #pragma unroll
            for (int nf = 0; nf < 8; nf++) {
                MMA16816(sfr[nf][0], sfr[nf][1], sfr[nf][2], sfr[nf][3],
                         aqh0, aqh1, aqh2, aqh3, bh[nf][0], bh[nf][1]);
                MMA16816(sfr[nf][0], sfr[nf][1], sfr[nf][2], sfr[nf][3],
                         aqh0, aqh1, aqh2, aqh3, bl[nf][0], bl[nf][1]);
                MMA16816(sfr[nf][0], sfr[nf][1], sfr[nf][2], sfr[nf][3],
                         aql0, aql1, aql2, aql3, bh[nf][0], bh[nf][1]);
            }
        }

        // ---- online softmax on fragments ----
        float mx0 = -1e30f, mx1 = -1e30f;
        #pragma unroll
        for (int nf = 0; nf < 8; nf++) {
            mx0 = fmaxf(mx0, fmaxf(sfr[nf][0], sfr[nf][1]));
            mx1 = fmaxf(mx1, fmaxf(sfr[nf][2], sfr[nf][3]));
        }
        mx0 = fmaxf(mx0, __shfl_xor_sync(0xffffffffu, mx0, 1));
        mx0 = fmaxf(mx0, __shfl_xor_sync(0xffffffffu, mx0, 2));
        mx1 = fmaxf(mx1, __shfl_xor_sync(0xffffffffu, mx1, 1));
        mx1 = fmaxf(mx1, __shfl_xor_sync(0xffffffffu, mx1, 2));
        float mn0 = fmaxf(m0, mx0), mn1 = fmaxf(m1, mx1);
        float al0 = fast_exp(m0 - mn0), al1 = fast_exp(m1 - mn1);

        uint32_t ph[4][4], pl[4][4];
        float rs0 = 0.f, rs1 = 0.f;
        #pragma unroll
        for (int nf = 0; nf < 8; nf++) {
            float p0 = fast_exp(sfr[nf][0] - mn0);
            float p1 = fast_exp(sfr[nf][1] - mn0);
            float p2 = fast_exp(sfr[nf][2] - mn1);
            float p3 = fast_exp(sfr[nf][3] - mn1);
            rs0 += p0 + p1; rs1 += p2 + p3;
            __nv_bfloat162 h01 = __floats2bfloat162_rn(p0, p1);
            __nv_bfloat162 h23 = __floats2bfloat162_rn(p2, p3);
            __nv_bfloat162 l01 = __floats2bfloat162_rn(p0 - __bfloat162float(h01.x),
                                                       p1 - __bfloat162float(h01.y));
            __nv_bfloat162 l23 = __floats2bfloat162_rn(p2 - __bfloat162float(h23.x),
                                                       p3 - __bfloat162float(h23.y));
            int kb = nf >> 1, hf = (nf & 1) * 2;
            ph[kb][hf]     = *(uint32_t*)&h01;
            ph[kb][hf + 1] = *(uint32_t*)&h23;
            pl[kb][hf]     = *(uint32_t*)&l01;
            pl[kb][hf + 1] = *(uint32_t*)&l23;
        }
        rs0 += __shfl_xor_sync(0xffffffffu, rs0, 1);
        rs0 += __shfl_xor_sync(0xffffffffu, rs0, 2);
        rs1 += __shfl_xor_sync(0xffffffffu, rs1, 1);
        rs1 += __shfl_xor_sync(0xffffffffu, rs1, 2);
        l0 = l0 * al0 + rs0;
        l1 = l1 * al1 + rs1;
        m0 = mn0; m1 = mn1;

        // rescale O
        #pragma unroll
        for (int nf = 0; nf < 16; nf++) {
            ofr[nf][0] *= al0; ofr[nf][1] *= al0;
            ofr[nf][2] *= al1; ofr[nf][3] *= al1;
        }

        // ---- O += P V (3 hi/lo products) ----
        #pragma unroll
        for (int kb = 0; kb < 4; kb++) {
            #pragma unroll
            for (int db = 0; db < 8; db++) {
                uint32_t vh0, vh1, vh2, vh3, vl0, vl1, vl2, vl3;
                uint32_t va = (uint32_t)(kb * 16 * AP + db * 32) + offA;
                LDSM_T_X4(vh0, vh1, vh2, vh3, Vh_s + va);
                LDSM_T_X4(vl0, vl1, vl2, vl3, Vl_s + va);
                int nf = db * 2;
                MMA16816(ofr[nf][0], ofr[nf][1], ofr[nf][2], ofr[nf][3],
                         ph[kb][0], ph[kb][1], ph[kb][2], ph[kb][3], vh0, vh1);
                MMA16816(ofr[nf][0], ofr[nf][1], ofr[nf][2], ofr[nf][3],
                         ph[kb][0], ph[kb][1], ph[kb][2], ph[kb][3], vl0, vl1);
                MMA16816(ofr[nf][0], ofr[nf][1], ofr[nf][2], ofr[nf][3],
                         pl[kb][0], pl[kb][1], pl[kb][2], pl[kb][3], vh0, vh1);
                MMA16816(ofr[nf + 1][0], ofr[nf + 1][1], ofr[nf + 1][2], ofr[nf + 1][3],
                         ph[kb][0], ph[kb][1], ph[kb][2], ph[kb][3], vh2, vh3);
                MMA16816(ofr[nf + 1][0], ofr[nf + 1][1], ofr[nf + 1][2], ofr[nf + 1][3],
                         ph[kb][0], ph[kb][1], ph[kb][2], ph[kb][3], vl2, vl3);
                MMA16816(ofr[nf + 1][0], ofr[nf + 1][1], ofr[nf + 1][2], ofr[nf + 1][3],
                         pl[kb][0], pl[kb][1], pl[kb][2], pl[kb][3], vh2, vh3);
            }
        }
        __syncthreads();
    }

    // ---- epilogue: normalize + store ----
    float li0 = 1.0f / l0, li1 = 1.0f / l1;
    int row0 = q0 + wid * 16 + (lane >> 2);
    float* ob = g_attn + (size_t)(b * S_LEN + row0) * EMB + h * HD + (lane & 3) * 2;
    #pragma unroll
    for (int nf = 0; nf < 16; nf++) {
        *(float2*)&ob[nf * 8]              = make_float2(ofr[nf][0] * li0, ofr[nf][1] * li0);
        *(float2*)&ob[8 * EMB + nf * 8]    = make_float2(ofr[nf][2] * li1, ofr[nf][3] * li1);
    }
    #undef LOAD_KV
}

// ---------------- launch ----------------------------------------------------------
extern "C" void kernel_launch(void* const* d_in, const int* in_sizes, int n_in,
                              void* d_out, int out_size)
{
    const float* x   = (const float*)d_in[0];
    const float* Wq  = (const float*)d_in[1];
    const float* bq  = (const float*)d_in[2];
    const float* Wkv = (const float*)d_in[3];
    const float* bkv = (const float*)d_in[4];
    const float* Wo  = (const float*)d_in[5];
    float* out = (float*)d_out;

    float *qp, *kvp, *ap;
    cudaGetSymbolAddress((void**)&qp,  g_q);
    cudaGetSymbolAddress((void**)&kvp, g_kv);
    cudaGetSymbolAddress((void**)&ap,  g_attn);

    cudaFuncSetAttribute(gemm_mma, cudaFuncAttributeMaxDynamicSharedMemorySize, GEMM_SMEM);
    cudaFuncSetAttribute(attn_mma, cudaFuncAttributeMaxDynamicSharedMemorySize, ATTN_SMEM);

    dim3 blk(256);

    init_invfreq_kernel<<<1, 64>>>();

    // Q = x @ Wq^T + bq  : M=4096, N=2048, K=2048
    gemm_mma<<<dim3(16, 32), blk, GEMM_SMEM>>>(x, Wq, bq, qp, EMB, EMB);
    // KV = x @ Wkv^T + bkv : M=4096, N=1024, K=2048
    gemm_mma<<<dim3(8, 32), blk, GEMM_SMEM>>>(x, Wkv, bkv, kvp, KVW, EMB);

    rope_bf16_kernel<<<(NBATCH * S_LEN * NHEADS * 64 + 255) / 256, 256>>>(0);
    rope_bf16_kernel<<<(NBATCH * S_LEN * NKV    * 64 + 255) / 256, 256>>>(1);
    vconv_kernel<<<(NBATCH * S_LEN * NKV * HD + 255) / 256, 256>>>();

    attn_mma<<<dim3(S_LEN / 128, NHEADS, NBATCH), blk, ATTN_SMEM>>>();

    // out = attn @ Wo^T : M=4096, N=2048, K=2048
    gemm_mma<<<dim3(16, 32), blk, GEMM_SMEM>>>(ap, Wo, nullptr, out, EMB, EMB);
}

// round 5
// speedup vs baseline: 4.1894x; 1.0049x over previous
#include <cuda_runtime.h>
#include <cuda_bf16.h>
#include <math.h>
#include <stdint.h>

#define S_LEN   2048
#define NBATCH  2
#define EMB     2048
#define NHEADS  16
#define NKV     4
#define HD      128
#define KVW     1024   // 2*NKV*HD

typedef unsigned long long u64;

// ---------------- scratch (device globals: no allocation allowed) ----------------
__device__ float  g_q   [(size_t)NBATCH * S_LEN * EMB];   // fp32 Q proj
__device__ float  g_kv  [(size_t)NBATCH * S_LEN * KVW];   // fp32 KV proj
__device__ double g_invfreq[64];
// hi/lo bf16 operand buffers
__device__ __nv_bfloat16 g_xh [(size_t)NBATCH * S_LEN * EMB];
__device__ __nv_bfloat16 g_xl [(size_t)NBATCH * S_LEN * EMB];
__device__ __nv_bfloat16 g_wqh[(size_t)EMB * EMB];
__device__ __nv_bfloat16 g_wql[(size_t)EMB * EMB];
__device__ __nv_bfloat16 g_wkvh[(size_t)KVW * EMB];
__device__ __nv_bfloat16 g_wkvl[(size_t)KVW * EMB];
__device__ __nv_bfloat16 g_woh[(size_t)EMB * EMB];
__device__ __nv_bfloat16 g_wol[(size_t)EMB * EMB];
__device__ __nv_bfloat16 g_qh[(size_t)NBATCH * S_LEN * EMB];
__device__ __nv_bfloat16 g_ql[(size_t)NBATCH * S_LEN * EMB];
__device__ __nv_bfloat16 g_kh[(size_t)NBATCH * S_LEN * NKV * HD];
__device__ __nv_bfloat16 g_kl[(size_t)NBATCH * S_LEN * NKV * HD];
__device__ __nv_bfloat16 g_vh[(size_t)NBATCH * S_LEN * NKV * HD];
__device__ __nv_bfloat16 g_vl[(size_t)NBATCH * S_LEN * NKV * HD];
__device__ __nv_bfloat16 g_ah[(size_t)NBATCH * S_LEN * EMB];   // attention out hi
__device__ __nv_bfloat16 g_al[(size_t)NBATCH * S_LEN * EMB];   // attention out lo

// ---------------- fast exp --------------------------------------------------------
__device__ __forceinline__ float fast_exp(float x) {
    float y  = fmaxf(x * 1.4426950408889634f, -127.0f);
    float fl = floorf(y);
    float f  = y - fl;
    float p  = 1.5403530e-4f;
    p = fmaf(p, f, 1.3333558e-3f);
    p = fmaf(p, f, 9.6181291e-3f);
    p = fmaf(p, f, 5.5504109e-2f);
    p = fmaf(p, f, 2.4022651e-1f);
    p = fmaf(p, f, 6.9314718e-1f);
    p = fmaf(p, f, 1.0f);
    int e = (int)fl;
    float s = __int_as_float((e + 127) << 23);
    return p * s;
}

// ---------------- mma.sync / ldmatrix / cp.async helpers --------------------------
__device__ __forceinline__ uint32_t smem_u32(const void* p) {
    uint32_t a;
    asm("{ .reg .u64 t; cvta.to.shared.u64 t, %1; cvt.u32.u64 %0, t; }" : "=r"(a) : "l"(p));
    return a;
}
#define LDSM_X4(r0, r1, r2, r3, addr) \
    asm volatile("ldmatrix.sync.aligned.m8n8.x4.shared.b16 {%0,%1,%2,%3}, [%4];" \
        : "=r"(r0), "=r"(r1), "=r"(r2), "=r"(r3) : "r"(addr))
#define LDSM_T_X4(r0, r1, r2, r3, addr) \
    asm volatile("ldmatrix.sync.aligned.m8n8.x4.trans.shared.b16 {%0,%1,%2,%3}, [%4];" \
        : "=r"(r0), "=r"(r1), "=r"(r2), "=r"(r3) : "r"(addr))
#define MMA16816(c0, c1, c2, c3, a0, a1, a2, a3, b0, b1) \
    asm volatile("mma.sync.aligned.m16n8k16.row.col.f32.bf16.bf16.f32 " \
        "{%0,%1,%2,%3}, {%4,%5,%6,%7}, {%8,%9}, {%0,%1,%2,%3};" \
        : "+f"(c0), "+f"(c1), "+f"(c2), "+f"(c3) \
        : "r"(a0), "r"(a1), "r"(a2), "r"(a3), "r"(b0), "r"(b1))
#define CP16(d, s) \
    asm volatile("cp.async.cg.shared.global [%0], [%1], 16;" :: "r"(d), "l"(s))
#define CP_COMMIT asm volatile("cp.async.commit_group;" ::: "memory")
#define CP_WAIT1  asm volatile("cp.async.wait_group 1;" ::: "memory")
#define CP_WAIT0  asm volatile("cp.async.wait_group 0;" ::: "memory")

// ---------------- split fp32 -> bf16 hi/lo ----------------------------------------
__global__ void split_kernel(const float* __restrict__ src,
                             __nv_bfloat16* __restrict__ h,
                             __nv_bfloat16* __restrict__ l, int n4)
{
    int i = blockIdx.x * blockDim.x + threadIdx.x;
    if (i >= n4) return;
    float4 v = ((const float4*)src)[i];
    __nv_bfloat162 h01 = __floats2bfloat162_rn(v.x, v.y);
    __nv_bfloat162 h23 = __floats2bfloat162_rn(v.z, v.w);
    __nv_bfloat162 l01 = __floats2bfloat162_rn(v.x - __bfloat162float(h01.x),
                                               v.y - __bfloat162float(h01.y));
    __nv_bfloat162 l23 = __floats2bfloat162_rn(v.z - __bfloat162float(h23.x),
                                               v.w - __bfloat162float(h23.y));
    uint2 hv; hv.x = *(uint32_t*)&h01; hv.y = *(uint32_t*)&h23;
    uint2 lv; lv.x = *(uint32_t*)&l01; lv.y = *(uint32_t*)&l23;
    ((uint2*)h)[i] = hv;
    ((uint2*)l)[i] = lv;
}

// ================= bf16 HMMA GEMM: C[M,N] = A @ W^T (+bias), pre-split ============
// 128x128 CTA tile, 8 warps (2x4), warp 64x32, K-chunk 32, cp.async double buffer.
#define GS_ROW    40                       // padded row: 40 bf16 = 80 B
#define GS_TILE   (128 * GS_ROW * 2)       // 10240 B
#define GS_STAGE  (4 * GS_TILE)            // 40960 B (Ah, Al, Wh, Wl)
#define GEMM_SMEM (2 * GS_STAGE)           // 81920 B

__global__ __launch_bounds__(256, 2)
void gemm_bf16(const __nv_bfloat16* __restrict__ Ah_g, const __nv_bfloat16* __restrict__ Al_g,
               const __nv_bfloat16* __restrict__ Wh_g, const __nv_bfloat16* __restrict__ Wl_g,
               const float* __restrict__ bias, float* __restrict__ C,
               int N, int K)
{
    extern __shared__ char smp[];
    const uint32_t sbase = smem_u32(smp);

    const int tid  = threadIdx.x;
    const int wid  = tid >> 5;
    const int lane = tid & 31;
    const int m0   = blockIdx.y * 128;
    const int n0   = blockIdx.x * 128;
    const int wm   = (wid >> 2) * 64;
    const int wn   = (wid & 3) * 32;

    const int rIT  = lane & 7;
    const int b0_  = (lane >> 3) & 1;
    const int b1_  = (lane >> 4) & 1;
    const uint32_t aLane = (uint32_t)(((b0_ * 8 + rIT) * GS_ROW + b1_ * 8) * 2);
    const uint32_t bLane = (uint32_t)(((b1_ * 8 + rIT) * GS_ROW + b0_ * 8) * 2);

    float acc[4][4][4];
    #pragma unroll
    for (int i = 0; i < 4; i++)
        #pragma unroll
        for (int j = 0; j < 4; j++)
            #pragma unroll
            for (int e = 0; e < 4; e++) acc[i][j][e] = 0.f;

    const int nch = K >> 5;

    #define LOAD_STAGE(c, buf) do {                                                    \
        int _k0 = (c) << 5;                                                            \
        uint32_t _st = sbase + (uint32_t)((buf) * GS_STAGE);                           \
        _Pragma("unroll")                                                              \
        for (int _i = 0; _i < 2; _i++) {                                               \
            int _ch = tid + _i * 256;                                                  \
            int _r = _ch >> 2, _cl = _ch & 3;                                          \
            uint32_t _d = _st + (uint32_t)(_r * (GS_ROW * 2) + _cl * 16);              \
            size_t _sa = (size_t)(m0 + _r) * K + _k0 + _cl * 8;                        \
            size_t _sw = (size_t)(n0 + _r) * K + _k0 + _cl * 8;                        \
            CP16(_d,                Ah_g + _sa);                                       \
            CP16(_d +     GS_TILE,  Al_g + _sa);                                       \
            CP16(_d + 2 * GS_TILE,  Wh_g + _sw);                                       \
            CP16(_d + 3 * GS_TILE,  Wl_g + _sw);                                       \
        } } while (0)

    LOAD_STAGE(0, 0); CP_COMMIT;
    if (nch > 1) { LOAD_STAGE(1, 1); CP_COMMIT; }

    for (int c = 0; c < nch; c++) {
        if (c + 1 < nch) CP_WAIT1; else CP_WAIT0;
        __syncthreads();

        const uint32_t bb = sbase + (uint32_t)((c & 1) * GS_STAGE);
        const uint32_t Ah = bb;
        const uint32_t Al = bb + GS_TILE;
        const uint32_t Wh = bb + 2 * GS_TILE;
        const uint32_t Wl = bb + 3 * GS_TILE;

        #pragma unroll
        for (int ks = 0; ks < 2; ks++) {
            const uint32_t kOff = (uint32_t)(ks * 32);
            uint32_t ah[4][4], al[4][4], bh[4][2], bl[4][2];
            #pragma unroll
            for (int mf = 0; mf < 4; mf++) {
                uint32_t addr = Ah + (uint32_t)((wm + mf * 16) * GS_ROW * 2) + kOff + aLane;
                LDSM_X4(ah[mf][0], ah[mf][1], ah[mf][2], ah[mf][3], addr);
            }
            #pragma unroll
            for (int np = 0; np < 2; np++) {
                uint32_t addr = Wh + (uint32_t)((wn + np * 16) * GS_ROW * 2) + kOff + bLane;
                uint32_t r0, r1, r2, r3;
                LDSM_X4(r0, r1, r2, r3, addr);
                bh[np * 2][0] = r0; bh[np * 2][1] = r1;
                bh[np * 2 + 1][0] = r2; bh[np * 2 + 1][1] = r3;
            }
            #pragma unroll
            for (int mf = 0; mf < 4; mf++)
                #pragma unroll
                for (int nf = 0; nf < 4; nf++)
                    MMA16816(acc[mf][nf][0], acc[mf][nf][1], acc[mf][nf][2], acc[mf][nf][3],
                             ah[mf][0], ah[mf][1], ah[mf][2], ah[mf][3],
                             bh[nf][0], bh[nf][1]);
            #pragma unroll
            for (int np = 0; np < 2; np++) {
                uint32_t addr = Wl + (uint32_t)((wn + np * 16) * GS_ROW * 2) + kOff + bLane;
                uint32_t r0, r1, r2, r3;
                LDSM_X4(r0, r1, r2, r3, addr);
                bl[np * 2][0] = r0; bl[np * 2][1] = r1;
                bl[np * 2 + 1][0] = r2; bl[np * 2 + 1][1] = r3;
            }
            #pragma unroll
            for (int mf = 0; mf < 4; mf++)
                #pragma unroll
                for (int nf = 0; nf < 4; nf++)
                    MMA16816(acc[mf][nf][0], acc[mf][nf][1], acc[mf][nf][2], acc[mf][nf][3],
                             ah[mf][0], ah[mf][1], ah[mf][2], ah[mf][3],
                             bl[nf][0], bl[nf][1]);
            #pragma unroll
            for (int mf = 0; mf < 4; mf++) {
                uint32_t addr = Al + (uint32_t)((wm + mf * 16) * GS_ROW * 2) + kOff + aLane;
                LDSM_X4(al[mf][0], al[mf][1], al[mf][2], al[mf][3], addr);
            }
            #pragma unroll
            for (int mf = 0; mf < 4; mf++)
                #pragma unroll
                for (int nf = 0; nf < 4; nf++)
                    MMA16816(acc[mf][nf][0], acc[mf][nf][1], acc[mf][nf][2], acc[mf][nf][3],
                             al[mf][0], al[mf][1], al[mf][2], al[mf][3],
                             bh[nf][0], bh[nf][1]);
        }

        __syncthreads();
        if (c + 2 < nch) { LOAD_STAGE(c + 2, c & 1); CP_COMMIT; }
    }

    const int trow  = lane >> 2;
    const int tcol2 = (lane & 3) * 2;
    #pragma unroll
    for (int mf = 0; mf < 4; mf++) {
        #pragma unroll
        for (int nf = 0; nf < 4; nf++) {
            int row = m0 + wm + mf * 16 + trow;
            int col = n0 + wn + nf * 8 + tcol2;
            float c0 = acc[mf][nf][0], c1 = acc[mf][nf][1];
            float c2 = acc[mf][nf][2], c3 = acc[mf][nf][3];
            if (bias) {
                float2 bv = *(const float2*)&bias[col];
                c0 += bv.x; c1 += bv.y; c2 += bv.x; c3 += bv.y;
            }
            *(float2*)&C[(size_t)row * N + col]       = make_float2(c0, c1);
            *(float2*)&C[(size_t)(row + 8) * N + col] = make_float2(c2, c3);
        }
    }
    #undef LOAD_STAGE
}

// ---------------- RoPE -> bf16 hi/lo ----------------------------------------------
__global__ void init_invfreq_kernel() {
    int d = threadIdx.x;
    if (d < 64) g_invfreq[d] = pow(10000.0, -(double)d / 64.0);
}

__global__ void rope_bf16_kernel(int which) {
    const float* src = which ? g_kv : g_q;
    __nv_bfloat16* oh = which ? g_kh : g_qh;
    __nv_bfloat16* ol = which ? g_kl : g_ql;
    int nHeads   = which ? NKV : NHEADS;
    int rowW     = which ? KVW : EMB;
    int outW     = which ? (NKV * HD) : EMB;
    float sc     = which ? 1.0f : 0.08838834764831845f;
    int idx = blockIdx.x * blockDim.x + threadIdx.x;
    int total = NBATCH * S_LEN * nHeads * 64;
    if (idx >= total) return;
    int d = idx & 63;
    int h = (idx >> 6) % nHeads;
    int r = idx / (64 * nHeads);
    int s = r & (S_LEN - 1);
    size_t base = (size_t)r * rowW + h * HD;
    float t1 = src[base + d];
    float t2 = src[base + 64 + d];
    double ang = (double)s * g_invfreq[d];
    double k   = floor(ang * 0.15915494309189535);
    float a    = (float)(ang - k * 6.283185307179586);
    float sn, cs;
    sincosf(a, &sn, &cs);
    float o1 = (t1 * cs - t2 * sn) * sc;
    float o2 = (t2 * cs + t1 * sn) * sc;
    size_t ob = (size_t)r * outW + h * HD;
    __nv_bfloat16 h1 = __float2bfloat16_rn(o1);
    __nv_bfloat16 h2 = __float2bfloat16_rn(o2);
    oh[ob + d]      = h1;
    oh[ob + 64 + d] = h2;
    ol[ob + d]      = __float2bfloat16_rn(o1 - __bfloat162float(h1));
    ol[ob + 64 + d] = __float2bfloat16_rn(o2 - __bfloat162float(h2));
}

__global__ void vconv_kernel() {
    int idx = blockIdx.x * blockDim.x + threadIdx.x;
    int total = NBATCH * S_LEN * NKV * HD;
    if (idx >= total) return;
    int r = idx >> 9;
    int c = idx & 511;
    float v = g_kv[(size_t)r * KVW + 512 + c];
    __nv_bfloat16 h = __float2bfloat16_rn(v);
    g_vh[(size_t)r * 512 + c] = h;
    g_vl[(size_t)r * 512 + c] = __float2bfloat16_rn(v - __bfloat162float(h));
}

// ================= HMMA attention (FA2 layout, hi/lo bf16, 3 products) ============
#define AP        272
#define QT_BYTES  (128 * AP)
#define KT_BYTES  (64 * AP)
#define KVBUF     (4 * KT_BYTES)
#define ATTN_SMEM (2 * QT_BYTES + 2 * KVBUF)

__global__ __launch_bounds__(256, 1) void attn_mma() {
    extern __shared__ char smb[];
    const uint32_t sb = smem_u32(smb);

    const int tid  = threadIdx.x;
    const int wid  = tid >> 5;
    const int lane = tid & 31;
    const int q0   = blockIdx.x * 128;
    const int h    = blockIdx.y;
    const int b    = blockIdx.z;
    const int kvh  = h >> 2;

    const int rIT  = lane & 7;
    const int b3   = (lane >> 3) & 1;
    const int b4   = (lane >> 4) & 1;
    const uint32_t offA = (uint32_t)((b3 * 8 + rIT) * AP + b4 * 16);
    const uint32_t offB = (uint32_t)((b4 * 8 + rIT) * AP + b3 * 16);

    const uint32_t Qh_s = sb;
    const uint32_t Ql_s = sb + QT_BYTES;
    const uint32_t KV0  = sb + 2 * QT_BYTES;

    const __nv_bfloat16* qh_g = g_qh + (size_t)(b * S_LEN + q0) * EMB + h * HD;
    const __nv_bfloat16* ql_g = g_ql + (size_t)(b * S_LEN + q0) * EMB + h * HD;
    const __nv_bfloat16* kh_g = g_kh + (size_t)b * S_LEN * 512 + kvh * HD;
    const __nv_bfloat16* kl_g = g_kl + (size_t)b * S_LEN * 512 + kvh * HD;
    const __nv_bfloat16* vh_g = g_vh + (size_t)b * S_LEN * 512 + kvh * HD;
    const __nv_bfloat16* vl_g = g_vl + (size_t)b * S_LEN * 512 + kvh * HD;

    #pragma unroll
    for (int i = 0; i < 8; i++) {
        int c = tid + i * 256;
        int row = c >> 4, col = c & 15;
        uint32_t d0 = (uint32_t)(row * AP + col * 16);
        CP16(Qh_s + d0, qh_g + (size_t)row * EMB + col * 8);
        CP16(Ql_s + d0, ql_g + (size_t)row * EMB + col * 8);
    }

    #define LOAD_KV(T, BUF) do {                                                       \
        size_t _j = (size_t)((T) * 64);                                                \
        uint32_t _dst = KV0 + (uint32_t)((BUF) * KVBUF);                               \
        _Pragma("unroll")                                                              \
        for (int _i = 0; _i < 4; _i++) {                                               \
            int _c = tid + _i * 256;                                                   \
            int _row = _c >> 4, _col = _c & 15;                                        \
            uint32_t _d0 = _dst + (uint32_t)(_row * AP + _col * 16);                   \
            size_t _s0 = (_j + _row) * 512 + _col * 8;                                 \
            CP16(_d0,                kh_g + _s0);                                      \
            CP16(_d0 +     KT_BYTES, kl_g + _s0);                                      \
            CP16(_d0 + 2 * KT_BYTES, vh_g + _s0);                                      \
            CP16(_d0 + 3 * KT_BYTES, vl_g + _s0);                                      \
        } } while (0)

    LOAD_KV(0, 0);
    CP_COMMIT;

    float m0 = -1e30f, m1 = -1e30f, l0 = 0.f, l1 = 0.f;
    float ofr[16][4];
    #pragma unroll
    for (int i = 0; i < 16; i++)
        #pragma unroll
        for (int e = 0; e < 4; e++) ofr[i][e] = 0.f;

    const uint32_t qwarp_h = Qh_s + (uint32_t)(wid * 16 * AP);
    const uint32_t qwarp_l = Ql_s + (uint32_t)(wid * 16 * AP);

    for (int t = 0; t < 32; t++) {
        if (t < 31) { LOAD_KV(t + 1, (t + 1) & 1); CP_COMMIT; CP_WAIT1; }
        else        { CP_WAIT0; }
        __syncthreads();

        const uint32_t kvb  = KV0 + (uint32_t)((t & 1) * KVBUF);
        const uint32_t Kh_s = kvb;
        const uint32_t Kl_s = kvb + KT_BYTES;
        const uint32_t Vh_s = kvb + 2 * KT_BYTES;
        const uint32_t Vl_s = kvb + 3 * KT_BYTES;

        float sfr[8][4];
        #pragma unroll
        for (int i = 0; i < 8; i++)
            #pragma unroll
            for (int e = 0; e < 4; e++) sfr[i][e] = 0.f;

        #pragma unroll
        for (int ks = 0; ks < 8; ks++) {
            uint32_t aqh0, aqh1, aqh2, aqh3, aql0, aql1, aql2, aql3;
            LDSM_X4(aqh0, aqh1, aqh2, aqh3, qwarp_h + ks * 32 + offA);
            LDSM_X4(aql0, aql1, aql2, aql3, qwarp_l + ks * 32 + offA);
            uint32_t bh[8][2], bl[8][2];
            #pragma unroll
            for (int np = 0; np < 4; np++) {
                uint32_t r0, r1, r2, r3;
                LDSM_X4(r0, r1, r2, r3, Kh_s + (uint32_t)(np * 16 * AP) + ks * 32 + offB);
                bh[np * 2][0] = r0; bh[np * 2][1] = r1;
                bh[np * 2 + 1][0] = r2; bh[np * 2 + 1][1] = r3;
                LDSM_X4(r0, r1, r2, r3, Kl_s + (uint32_t)(np * 16 * AP) + ks * 32 + offB);
                bl[np * 2][0] = r0; bl[np * 2][1] = r1;
                bl[np * 2 + 1][0] = r2; bl[np * 2 + 1][1] = r3;
            }
            #pragma unroll
            for (int nf = 0; nf < 8; nf++) {
                MMA16816(sfr[nf][0], sfr[nf][1], sfr[nf][2], sfr[nf][3],
                         aqh0, aqh1, aqh2, aqh3, bh[nf][0], bh[nf][1]);
                MMA16816(sfr[nf][0], sfr[nf][1], sfr[nf][2], sfr[nf][3],
                         aqh0, aqh1, aqh2, aqh3, bl[nf][0], bl[nf][1]);
                MMA16816(sfr[nf][0], sfr[nf][1], sfr[nf][2], sfr[nf][3],
                         aql0, aql1, aql2, aql3, bh[nf][0], bh[nf][1]);
            }
        }

        float mx0 = -1e30f, mx1 = -1e30f;
        #pragma unroll
        for (int nf = 0; nf < 8; nf++) {
            mx0 = fmaxf(mx0, fmaxf(sfr[nf][0], sfr[nf][1]));
            mx1 = fmaxf(mx1, fmaxf(sfr[nf][2], sfr[nf][3]));
        }
        mx0 = fmaxf(mx0, __shfl_xor_sync(0xffffffffu, mx0, 1));
        mx0 = fmaxf(mx0, __shfl_xor_sync(0xffffffffu, mx0, 2));
        mx1 = fmaxf(mx1, __shfl_xor_sync(0xffffffffu, mx1, 1));
        mx1 = fmaxf(mx1, __shfl_xor_sync(0xffffffffu, mx1, 2));
        float mn0 = fmaxf(m0, mx0), mn1 = fmaxf(m1, mx1);
        float al0 = fast_exp(m0 - mn0), al1 = fast_exp(m1 - mn1);

        uint32_t ph[4][4], pl[4][4];
        float rs0 = 0.f, rs1 = 0.f;
        #pragma unroll
        for (int nf = 0; nf < 8; nf++) {
            float p0 = fast_exp(sfr[nf][0] - mn0);
            float p1 = fast_exp(sfr[nf][1] - mn0);
            float p2 = fast_exp(sfr[nf][2] - mn1);
            float p3 = fast_exp(sfr[nf][3] - mn1);
            rs0 += p0 + p1; rs1 += p2 + p3;
            __nv_bfloat162 h01 = __floats2bfloat162_rn(p0, p1);
            __nv_bfloat162 h23 = __floats2bfloat162_rn(p2, p3);
            __nv_bfloat162 l01 = __floats2bfloat162_rn(p0 - __bfloat162float(h01.x),
                                                       p1 - __bfloat162float(h01.y));
            __nv_bfloat162 l23 = __floats2bfloat162_rn(p2 - __bfloat162float(h23.x),
                                                       p3 - __bfloat162float(h23.y));
            int kb = nf >> 1, hf = (nf & 1) * 2;
            ph[kb][hf]     = *(uint32_t*)&h01;
            ph[kb][hf + 1] = *(uint32_t*)&h23;
            pl[kb][hf]     = *(uint32_t*)&l01;
            pl[kb][hf + 1] = *(uint32_t*)&l23;
        }
        rs0 += __shfl_xor_sync(0xffffffffu, rs0, 1);
        rs0 += __shfl_xor_sync(0xffffffffu, rs0, 2);
        rs1 += __shfl_xor_sync(0xffffffffu, rs1, 1);
        rs1 += __shfl_xor_sync(0xffffffffu, rs1, 2);
        l0 = l0 * al0 + rs0;
        l1 = l1 * al1 + rs1;
        m0 = mn0; m1 = mn1;

        #pragma unroll
        for (int nf = 0; nf < 16; nf++) {
            ofr[nf][0] *= al0; ofr[nf][1] *= al0;
            ofr[nf][2] *= al1; ofr[nf][3] *= al1;
        }

        #pragma unroll
        for (int kb = 0; kb < 4; kb++) {
            #pragma unroll
            for (int db = 0; db < 8; db++) {
                uint32_t vh0, vh1, vh2, vh3, vl0, vl1, vl2, vl3;
                uint32_t va = (uint32_t)(kb * 16 * AP + db * 32) + offA;
                LDSM_T_X4(vh0, vh1, vh2, vh3, Vh_s + va);
                LDSM_T_X4(vl0, vl1, vl2, vl3, Vl_s + va);
                int nf = db * 2;
                MMA16816(ofr[nf][0], ofr[nf][1], ofr[nf][2], ofr[nf][3],
                         ph[kb][0], ph[kb][1], ph[kb][2], ph[kb][3], vh0, vh1);
                MMA16816(ofr[nf][0], ofr[nf][1], ofr[nf][2], ofr[nf][3],
                         ph[kb][0], ph[kb][1], ph[kb][2], ph[kb][3], vl0, vl1);
                MMA16816(ofr[nf][0], ofr[nf][1], ofr[nf][2], ofr[nf][3],
                         pl[kb][0], pl[kb][1], pl[kb][2], pl[kb][3], vh0, vh1);
                MMA16816(ofr[nf + 1][0], ofr[nf + 1][1], ofr[nf + 1][2], ofr[nf + 1][3],
                         ph[kb][0], ph[kb][1], ph[kb][2], ph[kb][3], vh2, vh3);
                MMA16816(ofr[nf + 1][0], ofr[nf + 1][1], ofr[nf + 1][2], ofr[nf + 1][3],
                         ph[kb][0], ph[kb][1], ph[kb][2], ph[kb][3], vl2, vl3);
                MMA16816(ofr[nf + 1][0], ofr[nf + 1][1], ofr[nf + 1][2], ofr[nf + 1][3],
                         pl[kb][0], pl[kb][1], pl[kb][2], pl[kb][3], vh2, vh3);
            }
        }
        __syncthreads();
    }

    // ---- epilogue: normalize + store as hi/lo bf16 (O-proj operand) ----
    float li0 = 1.0f / l0, li1 = 1.0f / l1;
    int row0 = q0 + wid * 16 + (lane >> 2);
    size_t ob = (size_t)(b * S_LEN + row0) * EMB + h * HD + (lane & 3) * 2;
    #pragma unroll
    for (int nf = 0; nf < 16; nf++) {
        float f0 = ofr[nf][0] * li0, f1 = ofr[nf][1] * li0;
        float f2 = ofr[nf][2] * li1, f3 = ofr[nf][3] * li1;
        __nv_bfloat162 h01 = __floats2bfloat162_rn(f0, f1);
        __nv_bfloat162 h23 = __floats2bfloat162_rn(f2, f3);
        __nv_bfloat162 l01 = __floats2bfloat162_rn(f0 - __bfloat162float(h01.x),
                                                   f1 - __bfloat162float(h01.y));
        __nv_bfloat162 l23 = __floats2bfloat162_rn(f2 - __bfloat162float(h23.x),
                                                   f3 - __bfloat162float(h23.y));
        *(uint32_t*)&g_ah[ob + nf * 8]           = *(uint32_t*)&h01;
        *(uint32_t*)&g_al[ob + nf * 8]           = *(uint32_t*)&l01;
        *(uint32_t*)&g_ah[ob + 8 * EMB + nf * 8] = *(uint32_t*)&h23;
        *(uint32_t*)&g_al[ob + 8 * EMB + nf * 8] = *(uint32_t*)&l23;
    }
    #undef LOAD_KV
}

// ---------------- launch ----------------------------------------------------------
extern "C" void kernel_launch(void* const* d_in, const int* in_sizes, int n_in,
                              void* d_out, int out_size)
{
    const float* x   = (const float*)d_in[0];
    const float* Wq  = (const float*)d_in[1];
    const float* bq  = (const float*)d_in[2];
    const float* Wkv = (const float*)d_in[3];
    const float* bkv = (const float*)d_in[4];
    const float* Wo  = (const float*)d_in[5];
    float* out = (float*)d_out;

    float *qp, *kvp;
    cudaGetSymbolAddress((void**)&qp,  g_q);
    cudaGetSymbolAddress((void**)&kvp, g_kv);
    __nv_bfloat16 *xh, *xl, *wqh, *wql, *wkvh, *wkvl, *woh, *wol, *ah, *al;
    cudaGetSymbolAddress((void**)&xh,  g_xh);
    cudaGetSymbolAddress((void**)&xl,  g_xl);
    cudaGetSymbolAddress((void**)&wqh, g_wqh);
    cudaGetSymbolAddress((void**)&wql, g_wql);
    cudaGetSymbolAddress((void**)&wkvh, g_wkvh);
    cudaGetSymbolAddress((void**)&wkvl, g_wkvl);
    cudaGetSymbolAddress((void**)&woh, g_woh);
    cudaGetSymbolAddress((void**)&wol, g_wol);
    cudaGetSymbolAddress((void**)&ah,  g_ah);
    cudaGetSymbolAddress((void**)&al,  g_al);

    cudaFuncSetAttribute(gemm_bf16, cudaFuncAttributeMaxDynamicSharedMemorySize, GEMM_SMEM);
    cudaFuncSetAttribute(attn_mma, cudaFuncAttributeMaxDynamicSharedMemorySize, ATTN_SMEM);

    dim3 blk(256);

    init_invfreq_kernel<<<1, 64>>>();

    // pre-split operands to bf16 hi/lo
    const int nx   = NBATCH * S_LEN * EMB / 4;
    const int nwq  = EMB * EMB / 4;
    const int nwkv = KVW * EMB / 4;
    split_kernel<<<(nx   + 255) / 256, 256>>>(x,   xh,  xl,  nx);
    split_kernel<<<(nwq  + 255) / 256, 256>>>(Wq,  wqh, wql, nwq);
    split_kernel<<<(nwkv + 255) / 256, 256>>>(Wkv, wkvh, wkvl, nwkv);
    split_kernel<<<(nwq  + 255) / 256, 256>>>(Wo,  woh, wol, nwq);

    // Q = x @ Wq^T + bq
    gemm_bf16<<<dim3(16, 32), blk, GEMM_SMEM>>>(xh, xl, wqh, wql, bq, qp, EMB, EMB);
    // KV = x @ Wkv^T + bkv
    gemm_bf16<<<dim3(8, 32), blk, GEMM_SMEM>>>(xh, xl, wkvh, wkvl, bkv, kvp, KVW, EMB);

    rope_bf16_kernel<<<(NBATCH * S_LEN * NHEADS * 64 + 255) / 256, 256>>>(0);
    rope_bf16_kernel<<<(NBATCH * S_LEN * NKV    * 64 + 255) / 256, 256>>>(1);
    vconv_kernel<<<(NBATCH * S_LEN * NKV * HD + 255) / 256, 256>>>();

    attn_mma<<<dim3(S_LEN / 128, NHEADS, NBATCH), blk, ATTN_SMEM>>>();

    // out = attn @ Wo^T
    gemm_bf16<<<dim3(16, 32), blk, GEMM_SMEM>>>(ah, al, woh, wol, nullptr, out, EMB, EMB);
}

// round 6
// speedup vs baseline: 5.6613x; 1.3513x over previous
#include <cuda_runtime.h>
#include <cuda_fp16.h>
#include <math.h>
#include <stdint.h>

#define S_LEN   2048
#define NBATCH  2
#define EMB     2048
#define NHEADS  16
#define NKV     4
#define HD      128
#define KVW     1024   // 2*NKV*HD

typedef unsigned long long u64;

// ---------------- scratch (device globals: no allocation allowed) ----------------
__device__ float  g_q   [(size_t)NBATCH * S_LEN * EMB];   // fp32 Q proj
__device__ float  g_kv  [(size_t)NBATCH * S_LEN * KVW];   // fp32 KV proj
__device__ double g_invfreq[64];
// fp16 operand buffers
__device__ __half g_xh [(size_t)NBATCH * S_LEN * EMB];    // x hi
__device__ __half g_xl [(size_t)NBATCH * S_LEN * EMB];    // x lo
__device__ __half g_wq [(size_t)EMB * EMB];               // weights: single fp16
__device__ __half g_wkv[(size_t)KVW * EMB];
__device__ __half g_wo [(size_t)EMB * EMB];
__device__ __half g_qh[(size_t)NBATCH * S_LEN * EMB];     // rope Q hi
__device__ __half g_ql[(size_t)NBATCH * S_LEN * EMB];     // rope Q lo
__device__ __half g_kh[(size_t)NBATCH * S_LEN * NKV * HD]; // rope K single
__device__ __half g_vh[(size_t)NBATCH * S_LEN * NKV * HD]; // V single
__device__ __half g_ah[(size_t)NBATCH * S_LEN * EMB];     // attention out hi
__device__ __half g_al[(size_t)NBATCH * S_LEN * EMB];     // attention out lo

// ---------------- fast exp --------------------------------------------------------
__device__ __forceinline__ float fast_exp(float x) {
    float y  = fmaxf(x * 1.4426950408889634f, -127.0f);
    float fl = floorf(y);
    float f  = y - fl;
    float p  = 1.5403530e-4f;
    p = fmaf(p, f, 1.3333558e-3f);
    p = fmaf(p, f, 9.6181291e-3f);
    p = fmaf(p, f, 5.5504109e-2f);
    p = fmaf(p, f, 2.4022651e-1f);
    p = fmaf(p, f, 6.9314718e-1f);
    p = fmaf(p, f, 1.0f);
    int e = (int)fl;
    float s = __int_as_float((e + 127) << 23);
    return p * s;
}

// ---------------- mma.sync / ldmatrix / cp.async helpers --------------------------
__device__ __forceinline__ uint32_t smem_u32(const void* p) {
    uint32_t a;
    asm("{ .reg .u64 t; cvta.to.shared.u64 t, %1; cvt.u32.u64 %0, t; }" : "=r"(a) : "l"(p));
    return a;
}
#define LDSM_X4(r0, r1, r2, r3, addr) \
    asm volatile("ldmatrix.sync.aligned.m8n8.x4.shared.b16 {%0,%1,%2,%3}, [%4];" \
        : "=r"(r0), "=r"(r1), "=r"(r2), "=r"(r3) : "r"(addr))
#define LDSM_T_X4(r0, r1, r2, r3, addr) \
    asm volatile("ldmatrix.sync.aligned.m8n8.x4.trans.shared.b16 {%0,%1,%2,%3}, [%4];" \
        : "=r"(r0), "=r"(r1), "=r"(r2), "=r"(r3) : "r"(addr))
#define MMAH(c0, c1, c2, c3, a0, a1, a2, a3, b0, b1) \
    asm volatile("mma.sync.aligned.m16n8k16.row.col.f32.f16.f16.f32 " \
        "{%0,%1,%2,%3}, {%4,%5,%6,%7}, {%8,%9}, {%0,%1,%2,%3};" \
        : "+f"(c0), "+f"(c1), "+f"(c2), "+f"(c3) \
        : "r"(a0), "r"(a1), "r"(a2), "r"(a3), "r"(b0), "r"(b1))
#define CP16(d, s) \
    asm volatile("cp.async.cg.shared.global [%0], [%1], 16;" :: "r"(d), "l"(s))
#define CP_COMMIT asm volatile("cp.async.commit_group;" ::: "memory")
#define CP_WAIT1  asm volatile("cp.async.wait_group 1;" ::: "memory")
#define CP_WAIT0  asm volatile("cp.async.wait_group 0;" ::: "memory")

// ---------------- splits ----------------------------------------------------------
__global__ void split2_kernel(const float* __restrict__ src,
                              __half* __restrict__ h, __half* __restrict__ l, int n4)
{
    int i = blockIdx.x * blockDim.x + threadIdx.x;
    if (i >= n4) return;
    float4 v = ((const float4*)src)[i];
    __half2 h01 = __floats2half2_rn(v.x, v.y);
    __half2 h23 = __floats2half2_rn(v.z, v.w);
    __half2 l01 = __floats2half2_rn(v.x - __low2float(h01), v.y - __high2float(h01));
    __half2 l23 = __floats2half2_rn(v.z - __low2float(h23), v.w - __high2float(h23));
    uint2 hv; hv.x = *(uint32_t*)&h01; hv.y = *(uint32_t*)&h23;
    uint2 lv; lv.x = *(uint32_t*)&l01; lv.y = *(uint32_t*)&l23;
    ((uint2*)h)[i] = hv;
    ((uint2*)l)[i] = lv;
}

__global__ void split1_kernel(const float* __restrict__ src, __half* __restrict__ h, int n4)
{
    int i = blockIdx.x * blockDim.x + threadIdx.x;
    if (i >= n4) return;
    float4 v = ((const float4*)src)[i];
    __half2 h01 = __floats2half2_rn(v.x, v.y);
    __half2 h23 = __floats2half2_rn(v.z, v.w);
    uint2 hv; hv.x = *(uint32_t*)&h01; hv.y = *(uint32_t*)&h23;
    ((uint2*)h)[i] = hv;
}

// ================= fp16 HMMA GEMM: C[M,N] = (Ah+Al) @ W^T (+bias) =================
// 128x128 CTA tile, 8 warps (2x4), warp 64x32, K-chunk 32, cp.async double buffer.
#define GS_ROW    40                       // padded row: 40 halfs = 80 B
#define GS_TILE   (128 * GS_ROW * 2)       // 10240 B
#define GS_STAGE  (3 * GS_TILE)            // 30720 B (Ah, Al, W)
#define GEMM_SMEM (2 * GS_STAGE)           // 61440 B

__global__ __launch_bounds__(256, 2)
void gemm_fp16(const __half* __restrict__ Ah_g, const __half* __restrict__ Al_g,
               const __half* __restrict__ Wh_g,
               const float* __restrict__ bias, float* __restrict__ C,
               int N, int K)
{
    extern __shared__ char smp[];
    const uint32_t sbase = smem_u32(smp);

    const int tid  = threadIdx.x;
    const int wid  = tid >> 5;
    const int lane = tid & 31;
    const int m0   = blockIdx.y * 128;
    const int n0   = blockIdx.x * 128;
    const int wm   = (wid >> 2) * 64;
    const int wn   = (wid & 3) * 32;

    const int rIT  = lane & 7;
    const int b0_  = (lane >> 3) & 1;
    const int b1_  = (lane >> 4) & 1;
    const uint32_t aLane = (uint32_t)(((b0_ * 8 + rIT) * GS_ROW + b1_ * 8) * 2);
    const uint32_t bLane = (uint32_t)(((b1_ * 8 + rIT) * GS_ROW + b0_ * 8) * 2);

    float acc[4][4][4];
    #pragma unroll
    for (int i = 0; i < 4; i++)
        #pragma unroll
        for (int j = 0; j < 4; j++)
            #pragma unroll
            for (int e = 0; e < 4; e++) acc[i][j][e] = 0.f;

    const int nch = K >> 5;

    #define LOAD_STAGE(c, buf) do {                                                    \
        int _k0 = (c) << 5;                                                            \
        uint32_t _st = sbase + (uint32_t)((buf) * GS_STAGE);                           \
        _Pragma("unroll")                                                              \
        for (int _i = 0; _i < 2; _i++) {                                               \
            int _ch = tid + _i * 256;                                                  \
            int _r = _ch >> 2, _cl = _ch & 3;                                          \
            uint32_t _d = _st + (uint32_t)(_r * (GS_ROW * 2) + _cl * 16);              \
            size_t _sa = (size_t)(m0 + _r) * K + _k0 + _cl * 8;                        \
            size_t _sw = (size_t)(n0 + _r) * K + _k0 + _cl * 8;                        \
            CP16(_d,                Ah_g + _sa);                                       \
            CP16(_d +     GS_TILE,  Al_g + _sa);                                       \
            CP16(_d + 2 * GS_TILE,  Wh_g + _sw);                                       \
        } } while (0)

    LOAD_STAGE(0, 0); CP_COMMIT;
    if (nch > 1) { LOAD_STAGE(1, 1); CP_COMMIT; }

    for (int c = 0; c < nch; c++) {
        if (c + 1 < nch) CP_WAIT1; else CP_WAIT0;
        __syncthreads();

        const uint32_t bb = sbase + (uint32_t)((c & 1) * GS_STAGE);
        const uint32_t Ah = bb;
        const uint32_t Al = bb + GS_TILE;
        const uint32_t Wh = bb + 2 * GS_TILE;

        #pragma unroll
        for (int ks = 0; ks < 2; ks++) {
            const uint32_t kOff = (uint32_t)(ks * 32);
            uint32_t ah[4][4], al[4][4], bh[4][2];
            #pragma unroll
            for (int mf = 0; mf < 4; mf++) {
                uint32_t addr = Ah + (uint32_t)((wm + mf * 16) * GS_ROW * 2) + kOff + aLane;
                LDSM_X4(ah[mf][0], ah[mf][1], ah[mf][2], ah[mf][3], addr);
            }
            #pragma unroll
            for (int np = 0; np < 2; np++) {
                uint32_t addr = Wh + (uint32_t)((wn + np * 16) * GS_ROW * 2) + kOff + bLane;
                uint32_t r0, r1, r2, r3;
                LDSM_X4(r0, r1, r2, r3, addr);
                bh[np * 2][0] = r0; bh[np * 2][1] = r1;
                bh[np * 2 + 1][0] = r2; bh[np * 2 + 1][1] = r3;
            }
            #pragma unroll
            for (int mf = 0; mf < 4; mf++)
                #pragma unroll
                for (int nf = 0; nf < 4; nf++)
                    MMAH(acc[mf][nf][0], acc[mf][nf][1], acc[mf][nf][2], acc[mf][nf][3],
                         ah[mf][0], ah[mf][1], ah[mf][2], ah[mf][3],
                         bh[nf][0], bh[nf][1]);
            #pragma unroll
            for (int mf = 0; mf < 4; mf++) {
                uint32_t addr = Al + (uint32_t)((wm + mf * 16) * GS_ROW * 2) + kOff + aLane;
                LDSM_X4(al[mf][0], al[mf][1], al[mf][2], al[mf][3], addr);
            }
            #pragma unroll
            for (int mf = 0; mf < 4; mf++)
                #pragma unroll
                for (int nf = 0; nf < 4; nf++)
                    MMAH(acc[mf][nf][0], acc[mf][nf][1], acc[mf][nf][2], acc[mf][nf][3],
                         al[mf][0], al[mf][1], al[mf][2], al[mf][3],
                         bh[nf][0], bh[nf][1]);
        }

        __syncthreads();
        if (c + 2 < nch) { LOAD_STAGE(c + 2, c & 1); CP_COMMIT; }
    }

    const int trow  = lane >> 2;
    const int tcol2 = (lane & 3) * 2;
    #pragma unroll
    for (int mf = 0; mf < 4; mf++) {
        #pragma unroll
        for (int nf = 0; nf < 4; nf++) {
            int row = m0 + wm + mf * 16 + trow;
            int col = n0 + wn + nf * 8 + tcol2;
            float c0 = acc[mf][nf][0], c1 = acc[mf][nf][1];
            float c2 = acc[mf][nf][2], c3 = acc[mf][nf][3];
            if (bias) {
                float2 bv = *(const float2*)&bias[col];
                c0 += bv.x; c1 += bv.y; c2 += bv.x; c3 += bv.y;
            }
            *(float2*)&C[(size_t)row * N + col]       = make_float2(c0, c1);
            *(float2*)&C[(size_t)(row + 8) * N + col] = make_float2(c2, c3);
        }
    }
    #undef LOAD_STAGE
}

// ---------------- RoPE -> fp16 ----------------------------------------------------
__global__ void init_invfreq_kernel() {
    int d = threadIdx.x;
    if (d < 64) g_invfreq[d] = pow(10000.0, -(double)d / 64.0);
}

// which=0: Q (16 heads, scale folded) -> hi/lo; which=1: K (4 heads) -> single fp16
__global__ void rope_fp16_kernel(int which) {
    const float* src = which ? g_kv : g_q;
    int nHeads   = which ? NKV : NHEADS;
    int rowW     = which ? KVW : EMB;
    int outW     = which ? (NKV * HD) : EMB;
    float sc     = which ? 1.0f : 0.08838834764831845f;
    int idx = blockIdx.x * blockDim.x + threadIdx.x;
    int total = NBATCH * S_LEN * nHeads * 64;
    if (idx >= total) return;
    int d = idx & 63;
    int h = (idx >> 6) % nHeads;
    int r = idx / (64 * nHeads);
    int s = r & (S_LEN - 1);
    size_t base = (size_t)r * rowW + h * HD;
    float t1 = src[base + d];
    float t2 = src[base + 64 + d];
    double ang = (double)s * g_invfreq[d];
    double k   = floor(ang * 0.15915494309189535);
    float a    = (float)(ang - k * 6.283185307179586);
    float sn, cs;
    sincosf(a, &sn, &cs);
    float o1 = (t1 * cs - t2 * sn) * sc;
    float o2 = (t2 * cs + t1 * sn) * sc;
    size_t ob = (size_t)r * outW + h * HD;
    if (which == 0) {
        __half h1 = __float2half_rn(o1);
        __half h2 = __float2half_rn(o2);
        g_qh[ob + d]      = h1;
        g_qh[ob + 64 + d] = h2;
        g_ql[ob + d]      = __float2half_rn(o1 - __half2float(h1));
        g_ql[ob + 64 + d] = __float2half_rn(o2 - __half2float(h2));
    } else {
        g_kh[ob + d]      = __float2half_rn(o1);
        g_kh[ob + 64 + d] = __float2half_rn(o2);
    }
}

__global__ void vconv_kernel() {
    int idx = blockIdx.x * blockDim.x + threadIdx.x;
    int total = NBATCH * S_LEN * NKV * HD;
    if (idx >= total) return;
    int r = idx >> 9;
    int c = idx & 511;
    g_vh[(size_t)r * 512 + c] = __float2half_rn(g_kv[(size_t)r * KVW + 512 + c]);
}

// ================= fp16 HMMA attention (FA2, 2 products) ==========================
#define AP        272
#define QT_BYTES  (128 * AP)
#define KT_BYTES  (64 * AP)
#define KVBUF     (2 * KT_BYTES)                 // K, V (single each)
#define ATTN_SMEM (2 * QT_BYTES + 2 * KVBUF)     // 139264

__global__ __launch_bounds__(256, 1) void attn_mma() {
    extern __shared__ char smb[];
    const uint32_t sb = smem_u32(smb);

    const int tid  = threadIdx.x;
    const int wid  = tid >> 5;
    const int lane = tid & 31;
    const int q0   = blockIdx.x * 128;
    const int h    = blockIdx.y;
    const int b    = blockIdx.z;
    const int kvh  = h >> 2;

    const int rIT  = lane & 7;
    const int b3   = (lane >> 3) & 1;
    const int b4   = (lane >> 4) & 1;
    const uint32_t offA = (uint32_t)((b3 * 8 + rIT) * AP + b4 * 16);
    const uint32_t offB = (uint32_t)((b4 * 8 + rIT) * AP + b3 * 16);

    const uint32_t Qh_s = sb;
    const uint32_t Ql_s = sb + QT_BYTES;
    const uint32_t KV0  = sb + 2 * QT_BYTES;

    const __half* qh_g = g_qh + (size_t)(b * S_LEN + q0) * EMB + h * HD;
    const __half* ql_g = g_ql + (size_t)(b * S_LEN + q0) * EMB + h * HD;
    const __half* kh_g = g_kh + (size_t)b * S_LEN * 512 + kvh * HD;
    const __half* vh_g = g_vh + (size_t)b * S_LEN * 512 + kvh * HD;

    #pragma unroll
    for (int i = 0; i < 8; i++) {
        int c = tid + i * 256;
        int row = c >> 4, col = c & 15;
        uint32_t d0 = (uint32_t)(row * AP + col * 16);
        CP16(Qh_s + d0, qh_g + (size_t)row * EMB + col * 8);
        CP16(Ql_s + d0, ql_g + (size_t)row * EMB + col * 8);
    }

    #define LOAD_KV(T, BUF) do {                                                       \
        size_t _j = (size_t)((T) * 64);                                                \
        uint32_t _dst = KV0 + (uint32_t)((BUF) * KVBUF);                               \
        _Pragma("unroll")                                                              \
        for (int _i = 0; _i < 4; _i++) {                                               \
            int _c = tid + _i * 256;                                                   \
            int _row = _c >> 4, _col = _c & 15;                                        \
            uint32_t _d0 = _dst + (uint32_t)(_row * AP + _col * 16);                   \
            size_t _s0 = (_j + _row) * 512 + _col * 8;                                 \
            CP16(_d0,            kh_g + _s0);                                          \
            CP16(_d0 + KT_BYTES, vh_g + _s0);                                          \
        } } while (0)

    LOAD_KV(0, 0);
    CP_COMMIT;

    float m0 = -1e30f, m1 = -1e30f, l0 = 0.f, l1 = 0.f;
    float ofr[16][4];
    #pragma unroll
    for (int i = 0; i < 16; i++)
        #pragma unroll
        for (int e = 0; e < 4; e++) ofr[i][e] = 0.f;

    const uint32_t qwarp_h = Qh_s + (uint32_t)(wid * 16 * AP);
    const uint32_t qwarp_l = Ql_s + (uint32_t)(wid * 16 * AP);

    for (int t = 0; t < 32; t++) {
        if (t < 31) { LOAD_KV(t + 1, (t + 1) & 1); CP_COMMIT; CP_WAIT1; }
        else        { CP_WAIT0; }
        __syncthreads();

        const uint32_t kvb  = KV0 + (uint32_t)((t & 1) * KVBUF);
        const uint32_t Kh_s = kvb;
        const uint32_t Vh_s = kvb + KT_BYTES;

        float sfr[8][4];
        #pragma unroll
        for (int i = 0; i < 8; i++)
            #pragma unroll
            for (int e = 0; e < 4; e++) sfr[i][e] = 0.f;

        #pragma unroll
        for (int ks = 0; ks < 8; ks++) {
            uint32_t aqh0, aqh1, aqh2, aqh3, aql0, aql1, aql2, aql3;
            LDSM_X4(aqh0, aqh1, aqh2, aqh3, qwarp_h + ks * 32 + offA);
            LDSM_X4(aql0, aql1, aql2, aql3, qwarp_l + ks * 32 + offA);
            uint32_t bh[8][2];
            #pragma unroll
            for (int np = 0; np < 4; np++) {
                uint32_t r0, r1, r2, r3;
                LDSM_X4(r0, r1, r2, r3, Kh_s + (uint32_t)(np * 16 * AP) + ks * 32 + offB);
                bh[np * 2][0] = r0; bh[np * 2][1] = r1;
                bh[np * 2 + 1][0] = r2; bh[np * 2 + 1][1] = r3;
            }
            #pragma unroll
            for (int nf = 0; nf < 8; nf++) {
                MMAH(sfr[nf][0], sfr[nf][1], sfr[nf][2], sfr[nf][3],
                     aqh0, aqh1, aqh2, aqh3, bh[nf][0], bh[nf][1]);
                MMAH(sfr[nf][0], sfr[nf][1], sfr[nf][2], sfr[nf][3],
                     aql0, aql1, aql2, aql3, bh[nf][0], bh[nf][1]);
            }
        }

        float mx0 = -1e30f, mx1 = -1e30f;
        #pragma unroll
        for (int nf = 0; nf < 8; nf++) {
            mx0 = fmaxf(mx0, fmaxf(sfr[nf][0], sfr[nf][1]));
            mx1 = fmaxf(mx1, fmaxf(sfr[nf][2], sfr[nf][3]));
        }
        mx0 = fmaxf(mx0, __shfl_xor_sync(0xffffffffu, mx0, 1));
        mx0 = fmaxf(mx0, __shfl_xor_sync(0xffffffffu, mx0, 2));
        mx1 = fmaxf(mx1, __shfl_xor_sync(0xffffffffu, mx1, 1));
        mx1 = fmaxf(mx1, __shfl_xor_sync(0xffffffffu, mx1, 2));
        float mn0 = fmaxf(m0, mx0), mn1 = fmaxf(m1, mx1);
        float al0 = fast_exp(m0 - mn0), al1 = fast_exp(m1 - mn1);

        uint32_t ph[4][4], pl[4][4];
        float rs0 = 0.f, rs1 = 0.f;
        #pragma unroll
        for (int nf = 0; nf < 8; nf++) {
            float p0 = fast_exp(sfr[nf][0] - mn0);
            float p1 = fast_exp(sfr[nf][1] - mn0);
            float p2 = fast_exp(sfr[nf][2] - mn1);
            float p3 = fast_exp(sfr[nf][3] - mn1);
            rs0 += p0 + p1; rs1 += p2 + p3;
            __half2 h01 = __floats2half2_rn(p0, p1);
            __half2 h23 = __floats2half2_rn(p2, p3);
            __half2 l01 = __floats2half2_rn(p0 - __low2float(h01), p1 - __high2float(h01));
            __half2 l23 = __floats2half2_rn(p2 - __low2float(h23), p3 - __high2float(h23));
            int kb = nf >> 1, hf = (nf & 1) * 2;
            ph[kb][hf]     = *(uint32_t*)&h01;
            ph[kb][hf + 1] = *(uint32_t*)&h23;
            pl[kb][hf]     = *(uint32_t*)&l01;
            pl[kb][hf + 1] = *(uint32_t*)&l23;
        }
        rs0 += __shfl_xor_sync(0xffffffffu, rs0, 1);
        rs0 += __shfl_xor_sync(0xffffffffu, rs0, 2);
        rs1 += __shfl_xor_sync(0xffffffffu, rs1, 1);
        rs1 += __shfl_xor_sync(0xffffffffu, rs1, 2);
        l0 = l0 * al0 + rs0;
        l1 = l1 * al1 + rs1;
        m0 = mn0; m1 = mn1;

        #pragma unroll
        for (int nf = 0; nf < 16; nf++) {
            ofr[nf][0] *= al0; ofr[nf][1] *= al0;
            ofr[nf][2] *= al1; ofr[nf][3] *= al1;
        }

        #pragma unroll
        for (int kb = 0; kb < 4; kb++) {
            #pragma unroll
            for (int db = 0; db < 8; db++) {
                uint32_t vh0, vh1, vh2, vh3;
                uint32_t va = (uint32_t)(kb * 16 * AP + db * 32) + offA;
                LDSM_T_X4(vh0, vh1, vh2, vh3, Vh_s + va);
                int nf = db * 2;
                MMAH(ofr[nf][0], ofr[nf][1], ofr[nf][2], ofr[nf][3],
                     ph[kb][0], ph[kb][1], ph[kb][2], ph[kb][3], vh0, vh1);
                MMAH(ofr[nf][0], ofr[nf][1], ofr[nf][2], ofr[nf][3],
                     pl[kb][0], pl[kb][1], pl[kb][2], pl[kb][3], vh0, vh1);
                MMAH(ofr[nf + 1][0], ofr[nf + 1][1], ofr[nf + 1][2], ofr[nf + 1][3],
                     ph[kb][0], ph[kb][1], ph[kb][2], ph[kb][3], vh2, vh3);
                MMAH(ofr[nf + 1][0], ofr[nf + 1][1], ofr[nf + 1][2], ofr[nf + 1][3],
                     pl[kb][0], pl[kb][1], pl[kb][2], pl[kb][3], vh2, vh3);
            }
        }
        __syncthreads();
    }

    // ---- epilogue: normalize + store as fp16 hi/lo (O-proj operand) ----
    float li0 = 1.0f / l0, li1 = 1.0f / l1;
    int row0 = q0 + wid * 16 + (lane >> 2);
    size_t ob = (size_t)(b * S_LEN + row0) * EMB + h * HD + (lane & 3) * 2;
    #pragma unroll
    for (int nf = 0; nf < 16; nf++) {
        float f0 = ofr[nf][0] * li0, f1 = ofr[nf][1] * li0;
        float f2 = ofr[nf][2] * li1, f3 = ofr[nf][3] * li1;
        __half2 h01 = __floats2half2_rn(f0, f1);
        __half2 h23 = __floats2half2_rn(f2, f3);
        __half2 l01 = __floats2half2_rn(f0 - __low2float(h01), f1 - __high2float(h01));
        __half2 l23 = __floats2half2_rn(f2 - __low2float(h23), f3 - __high2float(h23));
        *(uint32_t*)&g_ah[ob + nf * 8]           = *(uint32_t*)&h01;
        *(uint32_t*)&g_al[ob + nf * 8]           = *(uint32_t*)&l01;
        *(uint32_t*)&g_ah[ob + 8 * EMB + nf * 8] = *(uint32_t*)&h23;
        *(uint32_t*)&g_al[ob + 8 * EMB + nf * 8] = *(uint32_t*)&l23;
    }
    #undef LOAD_KV
}

// ---------------- launch ----------------------------------------------------------
extern "C" void kernel_launch(void* const* d_in, const int* in_sizes, int n_in,
                              void* d_out, int out_size)
{
    const float* x   = (const float*)d_in[0];
    const float* Wq  = (const float*)d_in[1];
    const float* bq  = (const float*)d_in[2];
    const float* Wkv = (const float*)d_in[3];
    const float* bkv = (const float*)d_in[4];
    const float* Wo  = (const float*)d_in[5];
    float* out = (float*)d_out;

    float *qp, *kvp;
    cudaGetSymbolAddress((void**)&qp,  g_q);
    cudaGetSymbolAddress((void**)&kvp, g_kv);
    __half *xh, *xl, *wq, *wkv, *wo, *ah, *al;
    cudaGetSymbolAddress((void**)&xh,  g_xh);
    cudaGetSymbolAddress((void**)&xl,  g_xl);
    cudaGetSymbolAddress((void**)&wq,  g_wq);
    cudaGetSymbolAddress((void**)&wkv, g_wkv);
    cudaGetSymbolAddress((void**)&wo,  g_wo);
    cudaGetSymbolAddress((void**)&ah,  g_ah);
    cudaGetSymbolAddress((void**)&al,  g_al);

    cudaFuncSetAttribute(gemm_fp16, cudaFuncAttributeMaxDynamicSharedMemorySize, GEMM_SMEM);
    cudaFuncSetAttribute(attn_mma, cudaFuncAttributeMaxDynamicSharedMemorySize, ATTN_SMEM);

    dim3 blk(256);

    init_invfreq_kernel<<<1, 64>>>();

    const int nx   = NBATCH * S_LEN * EMB / 4;
    const int nwq  = EMB * EMB / 4;
    const int nwkv = KVW * EMB / 4;
    split2_kernel<<<(nx   + 255) / 256, 256>>>(x,   xh, xl, nx);
    split1_kernel<<<(nwq  + 255) / 256, 256>>>(Wq,  wq,  nwq);
    split1_kernel<<<(nwkv + 255) / 256, 256>>>(Wkv, wkv, nwkv);
    split1_kernel<<<(nwq  + 255) / 256, 256>>>(Wo,  wo,  nwq);

    // Q = x @ Wq^T + bq
    gemm_fp16<<<dim3(16, 32), blk, GEMM_SMEM>>>(xh, xl, wq, bq, qp, EMB, EMB);
    // KV = x @ Wkv^T + bkv
    gemm_fp16<<<dim3(8, 32), blk, GEMM_SMEM>>>(xh, xl, wkv, bkv, kvp, KVW, EMB);

    rope_fp16_kernel<<<(NBATCH * S_LEN * NHEADS * 64 + 255) / 256, 256>>>(0);
    rope_fp16_kernel<<<(NBATCH * S_LEN * NKV    * 64 + 255) / 256, 256>>>(1);
    vconv_kernel<<<(NBATCH * S_LEN * NKV * HD + 255) / 256, 256>>>();

    attn_mma<<<dim3(S_LEN / 128, NHEADS, NBATCH), blk, ATTN_SMEM>>>();

    // out = attn @ Wo^T
    gemm_fp16<<<dim3(16, 32), blk, GEMM_SMEM>>>(ah, al, wo, nullptr, out, EMB, EMB);
}

// round 7
// speedup vs baseline: 6.4088x; 1.1320x over previous
#include <cuda_runtime.h>
#include <cuda_fp16.h>
#include <math.h>
#include <stdint.h>

#define S_LEN   2048
#define NBATCH  2
#define EMB     2048
#define NHEADS  16
#define NKV     4
#define HD      128
#define KVW     1024   // 2*NKV*HD

typedef unsigned long long u64;

// ---------------- scratch (device globals: no allocation allowed) ----------------
__device__ float  g_q   [(size_t)NBATCH * S_LEN * EMB];   // fp32 Q proj
__device__ float  g_kv  [(size_t)NBATCH * S_LEN * KVW];   // fp32 KV proj
__device__ double g_invfreq[64];
// fp16 operand buffers
__device__ __half g_xh [(size_t)NBATCH * S_LEN * EMB];    // x hi
__device__ __half g_xl [(size_t)NBATCH * S_LEN * EMB];    // x lo
__device__ __half g_wq [(size_t)EMB * EMB];               // weights: single fp16
__device__ __half g_wkv[(size_t)KVW * EMB];
__device__ __half g_wo [(size_t)EMB * EMB];
__device__ __half g_qs[(size_t)NBATCH * S_LEN * EMB];     // rope Q single
__device__ __half g_ks[(size_t)NBATCH * S_LEN * NKV * HD]; // rope K single
__device__ __half g_vs[(size_t)NBATCH * S_LEN * NKV * HD]; // V single
__device__ __half g_ah[(size_t)NBATCH * S_LEN * EMB];     // attention out hi
__device__ __half g_al[(size_t)NBATCH * S_LEN * EMB];     // attention out lo

// ---------------- fast exp --------------------------------------------------------
__device__ __forceinline__ float fast_exp(float x) {
    float y  = fmaxf(x * 1.4426950408889634f, -127.0f);
    float fl = floorf(y);
    float f  = y - fl;
    float p  = 1.5403530e-4f;
    p = fmaf(p, f, 1.3333558e-3f);
    p = fmaf(p, f, 9.6181291e-3f);
    p = fmaf(p, f, 5.5504109e-2f);
    p = fmaf(p, f, 2.4022651e-1f);
    p = fmaf(p, f, 6.9314718e-1f);
    p = fmaf(p, f, 1.0f);
    int e = (int)fl;
    float s = __int_as_float((e + 127) << 23);
    return p * s;
}

// ---------------- mma.sync / ldmatrix / cp.async helpers --------------------------
__device__ __forceinline__ uint32_t smem_u32(const void* p) {
    uint32_t a;
    asm("{ .reg .u64 t; cvta.to.shared.u64 t, %1; cvt.u32.u64 %0, t; }" : "=r"(a) : "l"(p));
    return a;
}
#define LDSM_X4(r0, r1, r2, r3, addr) \
    asm volatile("ldmatrix.sync.aligned.m8n8.x4.shared.b16 {%0,%1,%2,%3}, [%4];" \
        : "=r"(r0), "=r"(r1), "=r"(r2), "=r"(r3) : "r"(addr))
#define LDSM_T_X4(r0, r1, r2, r3, addr) \
    asm volatile("ldmatrix.sync.aligned.m8n8.x4.trans.shared.b16 {%0,%1,%2,%3}, [%4];" \
        : "=r"(r0), "=r"(r1), "=r"(r2), "=r"(r3) : "r"(addr))
#define MMAH(c0, c1, c2, c3, a0, a1, a2, a3, b0, b1) \
    asm volatile("mma.sync.aligned.m16n8k16.row.col.f32.f16.f16.f32 " \
        "{%0,%1,%2,%3}, {%4,%5,%6,%7}, {%8,%9}, {%0,%1,%2,%3};" \
        : "+f"(c0), "+f"(c1), "+f"(c2), "+f"(c3) \
        : "r"(a0), "r"(a1), "r"(a2), "r"(a3), "r"(b0), "r"(b1))
#define CP16(d, s) \
    asm volatile("cp.async.cg.shared.global [%0], [%1], 16;" :: "r"(d), "l"(s))
#define CP_COMMIT asm volatile("cp.async.commit_group;" ::: "memory")
#define CP_WAIT1  asm volatile("cp.async.wait_group 1;" ::: "memory")
#define CP_WAIT0  asm volatile("cp.async.wait_group 0;" ::: "memory")

// ---------------- splits ----------------------------------------------------------
__global__ void split2_kernel(const float* __restrict__ src,
                              __half* __restrict__ h, __half* __restrict__ l, int n4)
{
    int i = blockIdx.x * blockDim.x + threadIdx.x;
    if (i >= n4) return;
    float4 v = ((const float4*)src)[i];
    __half2 h01 = __floats2half2_rn(v.x, v.y);
    __half2 h23 = __floats2half2_rn(v.z, v.w);
    __half2 l01 = __floats2half2_rn(v.x - __low2float(h01), v.y - __high2float(h01));
    __half2 l23 = __floats2half2_rn(v.z - __low2float(h23), v.w - __high2float(h23));
    uint2 hv; hv.x = *(uint32_t*)&h01; hv.y = *(uint32_t*)&h23;
    uint2 lv; lv.x = *(uint32_t*)&l01; lv.y = *(uint32_t*)&l23;
    ((uint2*)h)[i] = hv;
    ((uint2*)l)[i] = lv;
}

__global__ void split1_kernel(const float* __restrict__ src, __half* __restrict__ h, int n4)
{
    int i = blockIdx.x * blockDim.x + threadIdx.x;
    if (i >= n4) return;
    float4 v = ((const float4*)src)[i];
    __half2 h01 = __floats2half2_rn(v.x, v.y);
    __half2 h23 = __floats2half2_rn(v.z, v.w);
    uint2 hv; hv.x = *(uint32_t*)&h01; hv.y = *(uint32_t*)&h23;
    ((uint2*)h)[i] = hv;
}

// ================= fp16 HMMA GEMM: C[M,N] = (Ah+Al) @ W^T (+bias) =================
#define GS_ROW    40                       // padded row: 40 halfs = 80 B
#define GS_TILE   (128 * GS_ROW * 2)       // 10240 B
#define GS_STAGE  (3 * GS_TILE)            // 30720 B (Ah, Al, W)
#define GEMM_SMEM (2 * GS_STAGE)           // 61440 B

__global__ __launch_bounds__(256, 2)
void gemm_fp16(const __half* __restrict__ Ah_g, const __half* __restrict__ Al_g,
               const __half* __restrict__ Wh_g,
               const float* __restrict__ bias, float* __restrict__ C,
               int N, int K)
{
    extern __shared__ char smp[];
    const uint32_t sbase = smem_u32(smp);

    const int tid  = threadIdx.x;
    const int wid  = tid >> 5;
    const int lane = tid & 31;
    const int m0   = blockIdx.y * 128;
    const int n0   = blockIdx.x * 128;
    const int wm   = (wid >> 2) * 64;
    const int wn   = (wid & 3) * 32;

    const int rIT  = lane & 7;
    const int b0_  = (lane >> 3) & 1;
    const int b1_  = (lane >> 4) & 1;
    const uint32_t aLane = (uint32_t)(((b0_ * 8 + rIT) * GS_ROW + b1_ * 8) * 2);
    const uint32_t bLane = (uint32_t)(((b1_ * 8 + rIT) * GS_ROW + b0_ * 8) * 2);

    float acc[4][4][4];
    #pragma unroll
    for (int i = 0; i < 4; i++)
        #pragma unroll
        for (int j = 0; j < 4; j++)
            #pragma unroll
            for (int e = 0; e < 4; e++) acc[i][j][e] = 0.f;

    const int nch = K >> 5;

    #define LOAD_STAGE(c, buf) do {                                                    \
        int _k0 = (c) << 5;                                                            \
        uint32_t _st = sbase + (uint32_t)((buf) * GS_STAGE);                           \
        _Pragma("unroll")                                                              \
        for (int _i = 0; _i < 2; _i++) {                                               \
            int _ch = tid + _i * 256;                                                  \
            int _r = _ch >> 2, _cl = _ch & 3;                                          \
            uint32_t _d = _st + (uint32_t)(_r * (GS_ROW * 2) + _cl * 16);              \
            size_t _sa = (size_t)(m0 + _r) * K + _k0 + _cl * 8;                        \
            size_t _sw = (size_t)(n0 + _r) * K + _k0 + _cl * 8;                        \
            CP16(_d,                Ah_g + _sa);                                       \
            CP16(_d +     GS_TILE,  Al_g + _sa);                                       \
            CP16(_d + 2 * GS_TILE,  Wh_g + _sw);                                       \
        } } while (0)

    LOAD_STAGE(0, 0); CP_COMMIT;
    if (nch > 1) { LOAD_STAGE(1, 1); CP_COMMIT; }

    for (int c = 0; c < nch; c++) {
        if (c + 1 < nch) CP_WAIT1; else CP_WAIT0;
        __syncthreads();

        const uint32_t bb = sbase + (uint32_t)((c & 1) * GS_STAGE);
        const uint32_t Ah = bb;
        const uint32_t Al = bb + GS_TILE;
        const uint32_t Wh = bb + 2 * GS_TILE;

        #pragma unroll
        for (int ks = 0; ks < 2; ks++) {
            const uint32_t kOff = (uint32_t)(ks * 32);
            uint32_t ah[4][4], al[4][4], bh[4][2];
            #pragma unroll
            for (int mf = 0; mf < 4; mf++) {
                uint32_t addr = Ah + (uint32_t)((wm + mf * 16) * GS_ROW * 2) + kOff + aLane;
                LDSM_X4(ah[mf][0], ah[mf][1], ah[mf][2], ah[mf][3], addr);
            }
            #pragma unroll
            for (int np = 0; np < 2; np++) {
                uint32_t addr = Wh + (uint32_t)((wn + np * 16) * GS_ROW * 2) + kOff + bLane;
                uint32_t r0, r1, r2, r3;
                LDSM_X4(r0, r1, r2, r3, addr);
                bh[np * 2][0] = r0; bh[np * 2][1] = r1;
                bh[np * 2 + 1][0] = r2; bh[np * 2 + 1][1] = r3;
            }
            #pragma unroll
            for (int mf = 0; mf < 4; mf++)
                #pragma unroll
                for (int nf = 0; nf < 4; nf++)
                    MMAH(acc[mf][nf][0], acc[mf][nf][1], acc[mf][nf][2], acc[mf][nf][3],
                         ah[mf][0], ah[mf][1], ah[mf][2], ah[mf][3],
                         bh[nf][0], bh[nf][1]);
            #pragma unroll
            for (int mf = 0; mf < 4; mf++) {
                uint32_t addr = Al + (uint32_t)((wm + mf * 16) * GS_ROW * 2) + kOff + aLane;
                LDSM_X4(al[mf][0], al[mf][1], al[mf][2], al[mf][3], addr);
            }
            #pragma unroll
            for (int mf = 0; mf < 4; mf++)
                #pragma unroll
                for (int nf = 0; nf < 4; nf++)
                    MMAH(acc[mf][nf][0], acc[mf][nf][1], acc[mf][nf][2], acc[mf][nf][3],
                         al[mf][0], al[mf][1], al[mf][2], al[mf][3],
                         bh[nf][0], bh[nf][1]);
        }

        __syncthreads();
        if (c + 2 < nch) { LOAD_STAGE(c + 2, c & 1); CP_COMMIT; }
    }

    const int trow  = lane >> 2;
    const int tcol2 = (lane & 3) * 2;
    #pragma unroll
    for (int mf = 0; mf < 4; mf++) {
        #pragma unroll
        for (int nf = 0; nf < 4; nf++) {
            int row = m0 + wm + mf * 16 + trow;
            int col = n0 + wn + nf * 8 + tcol2;
            float c0 = acc[mf][nf][0], c1 = acc[mf][nf][1];
            float c2 = acc[mf][nf][2], c3 = acc[mf][nf][3];
            if (bias) {
                float2 bv = *(const float2*)&bias[col];
                c0 += bv.x; c1 += bv.y; c2 += bv.x; c3 += bv.y;
            }
            *(float2*)&C[(size_t)row * N + col]       = make_float2(c0, c1);
            *(float2*)&C[(size_t)(row + 8) * N + col] = make_float2(c2, c3);
        }
    }
    #undef LOAD_STAGE
}

// ---------------- RoPE -> fp16 ----------------------------------------------------
__global__ void init_invfreq_kernel() {
    int d = threadIdx.x;
    if (d < 64) g_invfreq[d] = pow(10000.0, -(double)d / 64.0);
}

// which=0: Q (16 heads, scale folded) -> single; which=1: K (4 heads) -> single
__global__ void rope_fp16_kernel(int which) {
    const float* src = which ? g_kv : g_q;
    __half* dst  = which ? g_ks : g_qs;
    int nHeads   = which ? NKV : NHEADS;
    int rowW     = which ? KVW : EMB;
    int outW     = which ? (NKV * HD) : EMB;
    float sc     = which ? 1.0f : 0.08838834764831845f;
    int idx = blockIdx.x * blockDim.x + threadIdx.x;
    int total = NBATCH * S_LEN * nHeads * 64;
    if (idx >= total) return;
    int d = idx & 63;
    int h = (idx >> 6) % nHeads;
    int r = idx / (64 * nHeads);
    int s = r & (S_LEN - 1);
    size_t base = (size_t)r * rowW + h * HD;
    float t1 = src[base + d];
    float t2 = src[base + 64 + d];
    double ang = (double)s * g_invfreq[d];
    double k   = floor(ang * 0.15915494309189535);
    float a    = (float)(ang - k * 6.283185307179586);
    float sn, cs;
    sincosf(a, &sn, &cs);
    float o1 = (t1 * cs - t2 * sn) * sc;
    float o2 = (t2 * cs + t1 * sn) * sc;
    size_t ob = (size_t)r * outW + h * HD;
    dst[ob + d]      = __float2half_rn(o1);
    dst[ob + 64 + d] = __float2half_rn(o2);
}

__global__ void vconv_kernel() {
    int idx = blockIdx.x * blockDim.x + threadIdx.x;
    int total = NBATCH * S_LEN * NKV * HD;
    if (idx >= total) return;
    int r = idx >> 9;
    int c = idx & 511;
    g_vs[(size_t)r * 512 + c] = __float2half_rn(g_kv[(size_t)r * KVW + 512 + c]);
}

// ================= fp16 HMMA attention (FA2, single precision fp16) ===============
#define AP        272
#define QT_BYTES  (128 * AP)
#define KT_BYTES  (64 * AP)
#define KVBUF     (2 * KT_BYTES)                 // K, V
#define ATTN_SMEM (QT_BYTES + 2 * KVBUF)         // 104448

__global__ __launch_bounds__(256, 1) void attn_mma() {
    extern __shared__ char smb[];
    const uint32_t sb = smem_u32(smb);

    const int tid  = threadIdx.x;
    const int wid  = tid >> 5;
    const int lane = tid & 31;
    const int q0   = blockIdx.x * 128;
    const int h    = blockIdx.y;
    const int b    = blockIdx.z;
    const int kvh  = h >> 2;

    const int rIT  = lane & 7;
    const int b3   = (lane >> 3) & 1;
    const int b4   = (lane >> 4) & 1;
    const uint32_t offA = (uint32_t)((b3 * 8 + rIT) * AP + b4 * 16);
    const uint32_t offB = (uint32_t)((b4 * 8 + rIT) * AP + b3 * 16);

    const uint32_t Q_s  = sb;
    const uint32_t KV0  = sb + QT_BYTES;

    const __half* q_g = g_qs + (size_t)(b * S_LEN + q0) * EMB + h * HD;
    const __half* k_g = g_ks + (size_t)b * S_LEN * 512 + kvh * HD;
    const __half* v_g = g_vs + (size_t)b * S_LEN * 512 + kvh * HD;

    #pragma unroll
    for (int i = 0; i < 8; i++) {
        int c = tid + i * 256;
        int row = c >> 4, col = c & 15;
        CP16(Q_s + (uint32_t)(row * AP + col * 16), q_g + (size_t)row * EMB + col * 8);
    }

    #define LOAD_KV(T, BUF) do {                                                       \
        size_t _j = (size_t)((T) * 64);                                                \
        uint32_t _dst = KV0 + (uint32_t)((BUF) * KVBUF);                               \
        _Pragma("unroll")                                                              \
        for (int _i = 0; _i < 4; _i++) {                                               \
            int _c = tid + _i * 256;                                                   \
            int _row = _c >> 4, _col = _c & 15;                                        \
            uint32_t _d0 = _dst + (uint32_t)(_row * AP + _col * 16);                   \
            size_t _s0 = (_j + _row) * 512 + _col * 8;                                 \
            CP16(_d0,            k_g + _s0);                                           \
            CP16(_d0 + KT_BYTES, v_g + _s0);                                           \
        } } while (0)

    LOAD_KV(0, 0);
    CP_COMMIT;

    float m0 = -1e30f, m1 = -1e30f, l0 = 0.f, l1 = 0.f;
    float ofr[16][4];
    #pragma unroll
    for (int i = 0; i < 16; i++)
        #pragma unroll
        for (int e = 0; e < 4; e++) ofr[i][e] = 0.f;

    const uint32_t qwarp = Q_s + (uint32_t)(wid * 16 * AP);

    for (int t = 0; t < 32; t++) {
        if (t < 31) { LOAD_KV(t + 1, (t + 1) & 1); CP_COMMIT; CP_WAIT1; }
        else        { CP_WAIT0; }
        __syncthreads();

        const uint32_t kvb = KV0 + (uint32_t)((t & 1) * KVBUF);
        const uint32_t K_s = kvb;
        const uint32_t V_s = kvb + KT_BYTES;

        float sfr[8][4];
        #pragma unroll
        for (int i = 0; i < 8; i++)
            #pragma unroll
            for (int e = 0; e < 4; e++) sfr[i][e] = 0.f;

        #pragma unroll
        for (int ks = 0; ks < 8; ks++) {
            uint32_t aq0, aq1, aq2, aq3;
            LDSM_X4(aq0, aq1, aq2, aq3, qwarp + ks * 32 + offA);
            uint32_t bh[8][2];
            #pragma unroll
            for (int np = 0; np < 4; np++) {
                uint32_t r0, r1, r2, r3;
                LDSM_X4(r0, r1, r2, r3, K_s + (uint32_t)(np * 16 * AP) + ks * 32 + offB);
                bh[np * 2][0] = r0; bh[np * 2][1] = r1;
                bh[np * 2 + 1][0] = r2; bh[np * 2 + 1][1] = r3;
            }
            #pragma unroll
            for (int nf = 0; nf < 8; nf++)
                MMAH(sfr[nf][0], sfr[nf][1], sfr[nf][2], sfr[nf][3],
                     aq0, aq1, aq2, aq3, bh[nf][0], bh[nf][1]);
        }

        float mx0 = -1e30f, mx1 = -1e30f;
        #pragma unroll
        for (int nf = 0; nf < 8; nf++) {
            mx0 = fmaxf(mx0, fmaxf(sfr[nf][0], sfr[nf][1]));
            mx1 = fmaxf(mx1, fmaxf(sfr[nf][2], sfr[nf][3]));
        }
        mx0 = fmaxf(mx0, __shfl_xor_sync(0xffffffffu, mx0, 1));
        mx0 = fmaxf(mx0, __shfl_xor_sync(0xffffffffu, mx0, 2));
        mx1 = fmaxf(mx1, __shfl_xor_sync(0xffffffffu, mx1, 1));
        mx1 = fmaxf(mx1, __shfl_xor_sync(0xffffffffu, mx1, 2));
        float mn0 = fmaxf(m0, mx0), mn1 = fmaxf(m1, mx1);
        float al0 = fast_exp(m0 - mn0), al1 = fast_exp(m1 - mn1);

        uint32_t ph[4][4];
        float rs0 = 0.f, rs1 = 0.f;
        #pragma unroll
        for (int nf = 0; nf < 8; nf++) {
            float p0 = fast_exp(sfr[nf][0] - mn0);
            float p1 = fast_exp(sfr[nf][1] - mn0);
            float p2 = fast_exp(sfr[nf][2] - mn1);
            float p3 = fast_exp(sfr[nf][3] - mn1);
            rs0 += p0 + p1; rs1 += p2 + p3;
            __half2 h01 = __floats2half2_rn(p0, p1);
            __half2 h23 = __floats2half2_rn(p2, p3);
            int kb = nf >> 1, hf = (nf & 1) * 2;
            ph[kb][hf]     = *(uint32_t*)&h01;
            ph[kb][hf + 1] = *(uint32_t*)&h23;
        }
        rs0 += __shfl_xor_sync(0xffffffffu, rs0, 1);
        rs0 += __shfl_xor_sync(0xffffffffu, rs0, 2);
        rs1 += __shfl_xor_sync(0xffffffffu, rs1, 1);
        rs1 += __shfl_xor_sync(0xffffffffu, rs1, 2);
        l0 = l0 * al0 + rs0;
        l1 = l1 * al1 + rs1;
        m0 = mn0; m1 = mn1;

        #pragma unroll
        for (int nf = 0; nf < 16; nf++) {
            ofr[nf][0] *= al0; ofr[nf][1] *= al0;
            ofr[nf][2] *= al1; ofr[nf][3] *= al1;
        }

        #pragma unroll
        for (int kb = 0; kb < 4; kb++) {
            #pragma unroll
            for (int db = 0; db < 8; db++) {
                uint32_t vh0, vh1, vh2, vh3;
                uint32_t va = (uint32_t)(kb * 16 * AP + db * 32) + offA;
                LDSM_T_X4(vh0, vh1, vh2, vh3, V_s + va);
                int nf = db * 2;
                MMAH(ofr[nf][0], ofr[nf][1], ofr[nf][2], ofr[nf][3],
                     ph[kb][0], ph[kb][1], ph[kb][2], ph[kb][3], vh0, vh1);
                MMAH(ofr[nf + 1][0], ofr[nf + 1][1], ofr[nf + 1][2], ofr[nf + 1][3],
                     ph[kb][0], ph[kb][1], ph[kb][2], ph[kb][3], vh2, vh3);
            }
        }
        __syncthreads();
    }

    // ---- epilogue: normalize + store as fp16 hi/lo (O-proj operand) ----
    float li0 = 1.0f / l0, li1 = 1.0f / l1;
    int row0 = q0 + wid * 16 + (lane >> 2);
    size_t ob = (size_t)(b * S_LEN + row0) * EMB + h * HD + (lane & 3) * 2;
    #pragma unroll
    for (int nf = 0; nf < 16; nf++) {
        float f0 = ofr[nf][0] * li0, f1 = ofr[nf][1] * li0;
        float f2 = ofr[nf][2] * li1, f3 = ofr[nf][3] * li1;
        __half2 h01 = __floats2half2_rn(f0, f1);
        __half2 h23 = __floats2half2_rn(f2, f3);
        __half2 l01 = __floats2half2_rn(f0 - __low2float(h01), f1 - __high2float(h01));
        __half2 l23 = __floats2half2_rn(f2 - __low2float(h23), f3 - __high2float(h23));
        *(uint32_t*)&g_ah[ob + nf * 8]           = *(uint32_t*)&h01;
        *(uint32_t*)&g_al[ob + nf * 8]           = *(uint32_t*)&l01;
        *(uint32_t*)&g_ah[ob + 8 * EMB + nf * 8] = *(uint32_t*)&h23;
        *(uint32_t*)&g_al[ob + 8 * EMB + nf * 8] = *(uint32_t*)&l23;
    }
    #undef LOAD_KV
}

// ---------------- launch ----------------------------------------------------------
extern "C" void kernel_launch(void* const* d_in, const int* in_sizes, int n_in,
                              void* d_out, int out_size)
{
    const float* x   = (const float*)d_in[0];
    const float* Wq  = (const float*)d_in[1];
    const float* bq  = (const float*)d_in[2];
    const float* Wkv = (const float*)d_in[3];
    const float* bkv = (const float*)d_in[4];
    const float* Wo  = (const float*)d_in[5];
    float* out = (float*)d_out;

    float *qp, *kvp;
    cudaGetSymbolAddress((void**)&qp,  g_q);
    cudaGetSymbolAddress((void**)&kvp, g_kv);
    __half *xh, *xl, *wq, *wkv, *wo, *ah, *al;
    cudaGetSymbolAddress((void**)&xh,  g_xh);
    cudaGetSymbolAddress((void**)&xl,  g_xl);
    cudaGetSymbolAddress((void**)&wq,  g_wq);
    cudaGetSymbolAddress((void**)&wkv, g_wkv);
    cudaGetSymbolAddress((void**)&wo,  g_wo);
    cudaGetSymbolAddress((void**)&ah,  g_ah);
    cudaGetSymbolAddress((void**)&al,  g_al);

    cudaFuncSetAttribute(gemm_fp16, cudaFuncAttributeMaxDynamicSharedMemorySize, GEMM_SMEM);
    cudaFuncSetAttribute(attn_mma, cudaFuncAttributeMaxDynamicSharedMemorySize, ATTN_SMEM);

    dim3 blk(256);

    init_invfreq_kernel<<<1, 64>>>();

    const int nx   = NBATCH * S_LEN * EMB / 4;
    const int nwq  = EMB * EMB / 4;
    const int nwkv = KVW * EMB / 4;
    split2_kernel<<<(nx   + 255) / 256, 256>>>(x,   xh, xl, nx);
    split1_kernel<<<(nwq  + 255) / 256, 256>>>(Wq,  wq,  nwq);
    split1_kernel<<<(nwkv + 255) / 256, 256>>>(Wkv, wkv, nwkv);
    split1_kernel<<<(nwq  + 255) / 256, 256>>>(Wo,  wo,  nwq);

    // Q = x @ Wq^T + bq
    gemm_fp16<<<dim3(16, 32), blk, GEMM_SMEM>>>(xh, xl, wq, bq, qp, EMB, EMB);
    // KV = x @ Wkv^T + bkv
    gemm_fp16<<<dim3(8, 32), blk, GEMM_SMEM>>>(xh, xl, wkv, bkv, kvp, KVW, EMB);

    rope_fp16_kernel<<<(NBATCH * S_LEN * NHEADS * 64 + 255) / 256, 256>>>(0);
    rope_fp16_kernel<<<(NBATCH * S_LEN * NKV    * 64 + 255) / 256, 256>>>(1);
    vconv_kernel<<<(NBATCH * S_LEN * NKV * HD + 255) / 256, 256>>>();

    attn_mma<<<dim3(S_LEN / 128, NHEADS, NBATCH), blk, ATTN_SMEM>>>();

    // out = attn @ Wo^T
    gemm_fp16<<<dim3(16, 32), blk, GEMM_SMEM>>>(ah, al, wo, nullptr, out, EMB, EMB);
}

// round 8
// speedup vs baseline: 8.4452x; 1.3178x over previous
#include <cuda_runtime.h>
#include <cuda_fp16.h>
#include <math.h>
#include <stdint.h>

#define S_LEN   2048
#define NBATCH  2
#define EMB     2048
#define NHEADS  16
#define NKV     4
#define HD      128
#define KVW     1024   // 2*NKV*HD

typedef unsigned long long u64;

// ---------------- scratch (device globals: no allocation allowed) ----------------
__device__ float  g_q   [(size_t)NBATCH * S_LEN * EMB];   // fp32 Q proj
__device__ float  g_kv  [(size_t)NBATCH * S_LEN * KVW];   // fp32 KV proj
__device__ double g_invfreq[64];
// fp16 operand buffers (all single precision fp16)
__device__ __half g_xs [(size_t)NBATCH * S_LEN * EMB];     // x
__device__ __half g_wq [(size_t)EMB * EMB];
__device__ __half g_wkv[(size_t)KVW * EMB];
__device__ __half g_wo [(size_t)EMB * EMB];
__device__ __half g_qs [(size_t)NBATCH * S_LEN * EMB];     // rope Q (scale folded)
__device__ __half g_ks [(size_t)NBATCH * S_LEN * NKV * HD];
__device__ __half g_vs [(size_t)NBATCH * S_LEN * NKV * HD];
__device__ __half g_as [(size_t)NBATCH * S_LEN * EMB];     // attention out

// ---------------- fast exp --------------------------------------------------------
__device__ __forceinline__ float fast_exp(float x) {
    float y  = fmaxf(x * 1.4426950408889634f, -127.0f);
    float fl = floorf(y);
    float f  = y - fl;
    float p  = 1.5403530e-4f;
    p = fmaf(p, f, 1.3333558e-3f);
    p = fmaf(p, f, 9.6181291e-3f);
    p = fmaf(p, f, 5.5504109e-2f);
    p = fmaf(p, f, 2.4022651e-1f);
    p = fmaf(p, f, 6.9314718e-1f);
    p = fmaf(p, f, 1.0f);
    int e = (int)fl;
    float s = __int_as_float((e + 127) << 23);
    return p * s;
}

// ---------------- mma.sync / ldmatrix / cp.async helpers --------------------------
__device__ __forceinline__ uint32_t smem_u32(const void* p) {
    uint32_t a;
    asm("{ .reg .u64 t; cvta.to.shared.u64 t, %1; cvt.u32.u64 %0, t; }" : "=r"(a) : "l"(p));
    return a;
}
#define LDSM_X4(r0, r1, r2, r3, addr) \
    asm volatile("ldmatrix.sync.aligned.m8n8.x4.shared.b16 {%0,%1,%2,%3}, [%4];" \
        : "=r"(r0), "=r"(r1), "=r"(r2), "=r"(r3) : "r"(addr))
#define LDSM_T_X4(r0, r1, r2, r3, addr) \
    asm volatile("ldmatrix.sync.aligned.m8n8.x4.trans.shared.b16 {%0,%1,%2,%3}, [%4];" \
        : "=r"(r0), "=r"(r1), "=r"(r2), "=r"(r3) : "r"(addr))
#define MMAH(c0, c1, c2, c3, a0, a1, a2, a3, b0, b1) \
    asm volatile("mma.sync.aligned.m16n8k16.row.col.f32.f16.f16.f32 " \
        "{%0,%1,%2,%3}, {%4,%5,%6,%7}, {%8,%9}, {%0,%1,%2,%3};" \
        : "+f"(c0), "+f"(c1), "+f"(c2), "+f"(c3) \
        : "r"(a0), "r"(a1), "r"(a2), "r"(a3), "r"(b0), "r"(b1))
#define CP16(d, s) \
    asm volatile("cp.async.cg.shared.global [%0], [%1], 16;" :: "r"(d), "l"(s))
#define CP_COMMIT asm volatile("cp.async.commit_group;" ::: "memory")
#define CP_WAIT2  asm volatile("cp.async.wait_group 2;" ::: "memory")
#define CP_WAIT1  asm volatile("cp.async.wait_group 1;" ::: "memory")
#define CP_WAIT0  asm volatile("cp.async.wait_group 0;" ::: "memory")

// ---------------- split fp32 -> fp16 ----------------------------------------------
__global__ void split1_kernel(const float* __restrict__ src, __half* __restrict__ h, int n4)
{
    int i = blockIdx.x * blockDim.x + threadIdx.x;
    if (i >= n4) return;
    float4 v = ((const float4*)src)[i];
    __half2 h01 = __floats2half2_rn(v.x, v.y);
    __half2 h23 = __floats2half2_rn(v.z, v.w);
    uint2 hv; hv.x = *(uint32_t*)&h01; hv.y = *(uint32_t*)&h23;
    ((uint2*)h)[i] = hv;
}

// ================= fp16 HMMA GEMM: C[M,N] = A @ W^T (+bias), 3-stage pipeline =====
#define GS_ROW    40                       // padded row: 40 halfs = 80 B
#define GS_TILE   (128 * GS_ROW * 2)       // 10240 B
#define GS_STAGE  (2 * GS_TILE)            // 20480 B (A, W)
#define GEMM_SMEM (3 * GS_STAGE)           // 61440 B

__global__ __launch_bounds__(256, 2)
void gemm_fp16(const __half* __restrict__ A_g, const __half* __restrict__ W_g,
               const float* __restrict__ bias, float* __restrict__ C,
               int N, int K)
{
    extern __shared__ char smp[];
    const uint32_t sbase = smem_u32(smp);

    const int tid  = threadIdx.x;
    const int wid  = tid >> 5;
    const int lane = tid & 31;
    const int m0   = blockIdx.y * 128;
    const int n0   = blockIdx.x * 128;
    const int wm   = (wid >> 2) * 64;
    const int wn   = (wid & 3) * 32;

    const int rIT  = lane & 7;
    const int b0_  = (lane >> 3) & 1;
    const int b1_  = (lane >> 4) & 1;
    const uint32_t aLane = (uint32_t)(((b0_ * 8 + rIT) * GS_ROW + b1_ * 8) * 2);
    const uint32_t bLane = (uint32_t)(((b1_ * 8 + rIT) * GS_ROW + b0_ * 8) * 2);

    float acc[4][4][4];
    #pragma unroll
    for (int i = 0; i < 4; i++)
        #pragma unroll
        for (int j = 0; j < 4; j++)
            #pragma unroll
            for (int e = 0; e < 4; e++) acc[i][j][e] = 0.f;

    const int nch = K >> 5;

    #define LOAD_STAGE(c, buf) do {                                                    \
        int _k0 = (c) << 5;                                                            \
        uint32_t _st = sbase + (uint32_t)((buf) * GS_STAGE);                           \
        _Pragma("unroll")                                                              \
        for (int _i = 0; _i < 2; _i++) {                                               \
            int _ch = tid + _i * 256;                                                  \
            int _r = _ch >> 2, _cl = _ch & 3;                                          \
            uint32_t _d = _st + (uint32_t)(_r * (GS_ROW * 2) + _cl * 16);              \
            CP16(_d,           A_g + (size_t)(m0 + _r) * K + _k0 + _cl * 8);           \
            CP16(_d + GS_TILE, W_g + (size_t)(n0 + _r) * K + _k0 + _cl * 8);           \
        } } while (0)

    LOAD_STAGE(0, 0); CP_COMMIT;
    if (nch > 1) { LOAD_STAGE(1, 1); CP_COMMIT; }

    int buf = 0;
    for (int c = 0; c < nch; c++) {
        if (c + 2 < nch) { LOAD_STAGE(c + 2, (buf + 2) % 3); CP_COMMIT; CP_WAIT2; }
        else if (c + 1 < nch) CP_WAIT1;
        else                  CP_WAIT0;
        __syncthreads();

        const uint32_t bb = sbase + (uint32_t)(buf * GS_STAGE);
        const uint32_t Ah = bb;
        const uint32_t Wh = bb + GS_TILE;

        #pragma unroll
        for (int ks = 0; ks < 2; ks++) {
            const uint32_t kOff = (uint32_t)(ks * 32);
            uint32_t ah[4][4], bh[4][2];
            #pragma unroll
            for (int mf = 0; mf < 4; mf++) {
                uint32_t addr = Ah + (uint32_t)((wm + mf * 16) * GS_ROW * 2) + kOff + aLane;
                LDSM_X4(ah[mf][0], ah[mf][1], ah[mf][2], ah[mf][3], addr);
            }
            #pragma unroll
            for (int np = 0; np < 2; np++) {
                uint32_t addr = Wh + (uint32_t)((wn + np * 16) * GS_ROW * 2) + kOff + bLane;
                uint32_t r0, r1, r2, r3;
                LDSM_X4(r0, r1, r2, r3, addr);
                bh[np * 2][0] = r0; bh[np * 2][1] = r1;
                bh[np * 2 + 1][0] = r2; bh[np * 2 + 1][1] = r3;
            }
            #pragma unroll
            for (int mf = 0; mf < 4; mf++)
                #pragma unroll
                for (int nf = 0; nf < 4; nf++)
                    MMAH(acc[mf][nf][0], acc[mf][nf][1], acc[mf][nf][2], acc[mf][nf][3],
                         ah[mf][0], ah[mf][1], ah[mf][2], ah[mf][3],
                         bh[nf][0], bh[nf][1]);
        }

        __syncthreads();
        buf = (buf + 1) % 3;
    }

    const int trow  = lane >> 2;
    const int tcol2 = (lane & 3) * 2;
    #pragma unroll
    for (int mf = 0; mf < 4; mf++) {
        #pragma unroll
        for (int nf = 0; nf < 4; nf++) {
            int row = m0 + wm + mf * 16 + trow;
            int col = n0 + wn + nf * 8 + tcol2;
            float c0 = acc[mf][nf][0], c1 = acc[mf][nf][1];
            float c2 = acc[mf][nf][2], c3 = acc[mf][nf][3];
            if (bias) {
                float2 bv = *(const float2*)&bias[col];
                c0 += bv.x; c1 += bv.y; c2 += bv.x; c3 += bv.y;
            }
            *(float2*)&C[(size_t)row * N + col]       = make_float2(c0, c1);
            *(float2*)&C[(size_t)(row + 8) * N + col] = make_float2(c2, c3);
        }
    }
    #undef LOAD_STAGE
}

// ---------------- RoPE -> fp16 ----------------------------------------------------
__global__ void init_invfreq_kernel() {
    int d = threadIdx.x;
    if (d < 64) g_invfreq[d] = pow(10000.0, -(double)d / 64.0);
}

__global__ void rope_fp16_kernel(int which) {
    const float* src = which ? g_kv : g_q;
    __half* dst  = which ? g_ks : g_qs;
    int nHeads   = which ? NKV : NHEADS;
    int rowW     = which ? KVW : EMB;
    int outW     = which ? (NKV * HD) : EMB;
    float sc     = which ? 1.0f : 0.08838834764831845f;
    int idx = blockIdx.x * blockDim.x + threadIdx.x;
    int total = NBATCH * S_LEN * nHeads * 64;
    if (idx >= total) return;
    int d = idx & 63;
    int h = (idx >> 6) % nHeads;
    int r = idx / (64 * nHeads);
    int s = r & (S_LEN - 1);
    size_t base = (size_t)r * rowW + h * HD;
    float t1 = src[base + d];
    float t2 = src[base + 64 + d];
    double ang = (double)s * g_invfreq[d];
    double k   = floor(ang * 0.15915494309189535);
    float a    = (float)(ang - k * 6.283185307179586);
    float sn, cs;
    sincosf(a, &sn, &cs);
    float o1 = (t1 * cs - t2 * sn) * sc;
    float o2 = (t2 * cs + t1 * sn) * sc;
    size_t ob = (size_t)r * outW + h * HD;
    dst[ob + d]      = __float2half_rn(o1);
    dst[ob + 64 + d] = __float2half_rn(o2);
}

__global__ void vconv_kernel() {
    int idx = blockIdx.x * blockDim.x + threadIdx.x;
    int total = NBATCH * S_LEN * NKV * HD;
    if (idx >= total) return;
    int r = idx >> 9;
    int c = idx & 511;
    g_vs[(size_t)r * 512 + c] = __float2half_rn(g_kv[(size_t)r * KVW + 512 + c]);
}

// ================= fp16 HMMA attention (FA2, single fp16) =========================
#define AP        272
#define QT_BYTES  (128 * AP)
#define KT_BYTES  (64 * AP)
#define KVBUF     (2 * KT_BYTES)                 // K, V
#define ATTN_SMEM (QT_BYTES + 2 * KVBUF)         // 104448

__global__ __launch_bounds__(256, 1) void attn_mma() {
    extern __shared__ char smb[];
    const uint32_t sb = smem_u32(smb);

    const int tid  = threadIdx.x;
    const int wid  = tid >> 5;
    const int lane = tid & 31;
    const int q0   = blockIdx.x * 128;
    const int h    = blockIdx.y;
    const int b    = blockIdx.z;
    const int kvh  = h >> 2;

    const int rIT  = lane & 7;
    const int b3   = (lane >> 3) & 1;
    const int b4   = (lane >> 4) & 1;
    const uint32_t offA = (uint32_t)((b3 * 8 + rIT) * AP + b4 * 16);
    const uint32_t offB = (uint32_t)((b4 * 8 + rIT) * AP + b3 * 16);

    const uint32_t Q_s  = sb;
    const uint32_t KV0  = sb + QT_BYTES;

    const __half* q_g = g_qs + (size_t)(b * S_LEN + q0) * EMB + h * HD;
    const __half* k_g = g_ks + (size_t)b * S_LEN * 512 + kvh * HD;
    const __half* v_g = g_vs + (size_t)b * S_LEN * 512 + kvh * HD;

    #pragma unroll
    for (int i = 0; i < 8; i++) {
        int c = tid + i * 256;
        int row = c >> 4, col = c & 15;
        CP16(Q_s + (uint32_t)(row * AP + col * 16), q_g + (size_t)row * EMB + col * 8);
    }

    #define LOAD_KV(T, BUF) do {                                                       \
        size_t _j = (size_t)((T) * 64);                                                \
        uint32_t _dst = KV0 + (uint32_t)((BUF) * KVBUF);                               \
        _Pragma("unroll")                                                              \
        for (int _i = 0; _i < 4; _i++) {                                               \
            int _c = tid + _i * 256;                                                   \
            int _row = _c >> 4, _col = _c & 15;                                        \
            uint32_t _d0 = _dst + (uint32_t)(_row * AP + _col * 16);                   \
            size_t _s0 = (_j + _row) * 512 + _col * 8;                                 \
            CP16(_d0,            k_g + _s0);                                           \
            CP16(_d0 + KT_BYTES, v_g + _s0);                                           \
        } } while (0)

    LOAD_KV(0, 0);
    CP_COMMIT;

    float m0 = -1e30f, m1 = -1e30f, l0 = 0.f, l1 = 0.f;
    float ofr[16][4];
    #pragma unroll
    for (int i = 0; i < 16; i++)
        #pragma unroll
        for (int e = 0; e < 4; e++) ofr[i][e] = 0.f;

    const uint32_t qwarp = Q_s + (uint32_t)(wid * 16 * AP);

    for (int t = 0; t < 32; t++) {
        if (t < 31) { LOAD_KV(t + 1, (t + 1) & 1); CP_COMMIT; CP_WAIT1; }
        else        { CP_WAIT0; }
        __syncthreads();

        const uint32_t kvb = KV0 + (uint32_t)((t & 1) * KVBUF);
        const uint32_t K_s = kvb;
        const uint32_t V_s = kvb + KT_BYTES;

        float sfr[8][4];
        #pragma unroll
        for (int i = 0; i < 8; i++)
            #pragma unroll
            for (int e = 0; e < 4; e++) sfr[i][e] = 0.f;

        #pragma unroll
        for (int ks = 0; ks < 8; ks++) {
            uint32_t aq0, aq1, aq2, aq3;
            LDSM_X4(aq0, aq1, aq2, aq3, qwarp + ks * 32 + offA);
            uint32_t bh[8][2];
            #pragma unroll
            for (int np = 0; np < 4; np++) {
                uint32_t r0, r1, r2, r3;
                LDSM_X4(r0, r1, r2, r3, K_s + (uint32_t)(np * 16 * AP) + ks * 32 + offB);
                bh[np * 2][0] = r0; bh[np * 2][1] = r1;
                bh[np * 2 + 1][0] = r2; bh[np * 2 + 1][1] = r3;
            }
            #pragma unroll
            for (int nf = 0; nf < 8; nf++)
                MMAH(sfr[nf][0], sfr[nf][1], sfr[nf][2], sfr[nf][3],
                     aq0, aq1, aq2, aq3, bh[nf][0], bh[nf][1]);
        }

        float mx0 = -1e30f, mx1 = -1e30f;
        #pragma unroll
        for (int nf = 0; nf < 8; nf++) {
            mx0 = fmaxf(mx0, fmaxf(sfr[nf][0], sfr[nf][1]));
            mx1 = fmaxf(mx1, fmaxf(sfr[nf][2], sfr[nf][3]));
        }
        mx0 = fmaxf(mx0, __shfl_xor_sync(0xffffffffu, mx0, 1));
        mx0 = fmaxf(mx0, __shfl_xor_sync(0xffffffffu, mx0, 2));
        mx1 = fmaxf(mx1, __shfl_xor_sync(0xffffffffu, mx1, 1));
        mx1 = fmaxf(mx1, __shfl_xor_sync(0xffffffffu, mx1, 2));
        float mn0 = fmaxf(m0, mx0), mn1 = fmaxf(m1, mx1);
        float al0 = fast_exp(m0 - mn0), al1 = fast_exp(m1 - mn1);

        uint32_t ph[4][4];
        float rs0 = 0.f, rs1 = 0.f;
        #pragma unroll
        for (int nf = 0; nf < 8; nf++) {
            float p0 = fast_exp(sfr[nf][0] - mn0);
            float p1 = fast_exp(sfr[nf][1] - mn0);
            float p2 = fast_exp(sfr[nf][2] - mn1);
            float p3 = fast_exp(sfr[nf][3] - mn1);
            rs0 += p0 + p1; rs1 += p2 + p3;
            __half2 h01 = __floats2half2_rn(p0, p1);
            __half2 h23 = __floats2half2_rn(p2, p3);
            int kb = nf >> 1, hf = (nf & 1) * 2;
            ph[kb][hf]     = *(uint32_t*)&h01;
            ph[kb][hf + 1] = *(uint32_t*)&h23;
        }
        rs0 += __shfl_xor_sync(0xffffffffu, rs0, 1);
        rs0 += __shfl_xor_sync(0xffffffffu, rs0, 2);
        rs1 += __shfl_xor_sync(0xffffffffu, rs1, 1);
        rs1 += __shfl_xor_sync(0xffffffffu, rs1, 2);
        l0 = l0 * al0 + rs0;
        l1 = l1 * al1 + rs1;
        m0 = mn0; m1 = mn1;

        #pragma unroll
        for (int nf = 0; nf < 16; nf++) {
            ofr[nf][0] *= al0; ofr[nf][1] *= al0;
            ofr[nf][2] *= al1; ofr[nf][3] *= al1;
        }

        #pragma unroll
        for (int kb = 0; kb < 4; kb++) {
            #pragma unroll
            for (int db = 0; db < 8; db++) {
                uint32_t vh0, vh1, vh2, vh3;
                uint32_t va = (uint32_t)(kb * 16 * AP + db * 32) + offA;
                LDSM_T_X4(vh0, vh1, vh2, vh3, V_s + va);
                int nf = db * 2;
                MMAH(ofr[nf][0], ofr[nf][1], ofr[nf][2], ofr[nf][3],
                     ph[kb][0], ph[kb][1], ph[kb][2], ph[kb][3], vh0, vh1);
                MMAH(ofr[nf + 1][0], ofr[nf + 1][1], ofr[nf + 1][2], ofr[nf + 1][3],
                     ph[kb][0], ph[kb][1], ph[kb][2], ph[kb][3], vh2, vh3);
            }
        }
        __syncthreads();
    }

    // ---- epilogue: normalize + store as single fp16 (O-proj operand) ----
    float li0 = 1.0f / l0, li1 = 1.0f / l1;
    int row0 = q0 + wid * 16 + (lane >> 2);
    size_t ob = (size_t)(b * S_LEN + row0) * EMB + h * HD + (lane & 3) * 2;
    #pragma unroll
    for (int nf = 0; nf < 16; nf++) {
        __half2 h01 = __floats2half2_rn(ofr[nf][0] * li0, ofr[nf][1] * li0);
        __half2 h23 = __floats2half2_rn(ofr[nf][2] * li1, ofr[nf][3] * li1);
        *(uint32_t*)&g_as[ob + nf * 8]           = *(uint32_t*)&h01;
        *(uint32_t*)&g_as[ob + 8 * EMB + nf * 8] = *(uint32_t*)&h23;
    }
    #undef LOAD_KV
}

// ---------------- launch ----------------------------------------------------------
extern "C" void kernel_launch(void* const* d_in, const int* in_sizes, int n_in,
                              void* d_out, int out_size)
{
    const float* x   = (const float*)d_in[0];
    const float* Wq  = (const float*)d_in[1];
    const float* bq  = (const float*)d_in[2];
    const float* Wkv = (const float*)d_in[3];
    const float* bkv = (const float*)d_in[4];
    const float* Wo  = (const float*)d_in[5];
    float* out = (float*)d_out;

    float *qp, *kvp;
    cudaGetSymbolAddress((void**)&qp,  g_q);
    cudaGetSymbolAddress((void**)&kvp, g_kv);
    __half *xs, *wq, *wkv, *wo, *as;
    cudaGetSymbolAddress((void**)&xs,  g_xs);
    cudaGetSymbolAddress((void**)&wq,  g_wq);
    cudaGetSymbolAddress((void**)&wkv, g_wkv);
    cudaGetSymbolAddress((void**)&wo,  g_wo);
    cudaGetSymbolAddress((void**)&as,  g_as);

    cudaFuncSetAttribute(gemm_fp16, cudaFuncAttributeMaxDynamicSharedMemorySize, GEMM_SMEM);
    cudaFuncSetAttribute(attn_mma, cudaFuncAttributeMaxDynamicSharedMemorySize, ATTN_SMEM);

    dim3 blk(256);

    init_invfreq_kernel<<<1, 64>>>();

    const int nx   = NBATCH * S_LEN * EMB / 4;
    const int nwq  = EMB * EMB / 4;
    const int nwkv = KVW * EMB / 4;
    split1_kernel<<<(nx   + 255) / 256, 256>>>(x,   xs,  nx);
    split1_kernel<<<(nwq  + 255) / 256, 256>>>(Wq,  wq,  nwq);
    split1_kernel<<<(nwkv + 255) / 256, 256>>>(Wkv, wkv, nwkv);
    split1_kernel<<<(nwq  + 255) / 256, 256>>>(Wo,  wo,  nwq);

    // Q = x @ Wq^T + bq
    gemm_fp16<<<dim3(16, 32), blk, GEMM_SMEM>>>(xs, wq, bq, qp, EMB, EMB);
    // KV = x @ Wkv^T + bkv
    gemm_fp16<<<dim3(8, 32), blk, GEMM_SMEM>>>(xs, wkv, bkv, kvp, KVW, EMB);

    rope_fp16_kernel<<<(NBATCH * S_LEN * NHEADS * 64 + 255) / 256, 256>>>(0);
    rope_fp16_kernel<<<(NBATCH * S_LEN * NKV    * 64 + 255) / 256, 256>>>(1);
    vconv_kernel<<<(NBATCH * S_LEN * NKV * HD + 255) / 256, 256>>>();

    attn_mma<<<dim3(S_LEN / 128, NHEADS, NBATCH), blk, ATTN_SMEM>>>();

    // out = attn @ Wo^T
    gemm_fp16<<<dim3(16, 32), blk, GEMM_SMEM>>>(as, wo, nullptr, out, EMB, EMB);
}

// round 9
// speedup vs baseline: 9.0613x; 1.0729x over previous
#include <cuda_runtime.h>
#include <cuda_fp16.h>
#include <math.h>
#include <stdint.h>

#define S_LEN   2048
#define NBATCH  2
#define EMB     2048
#define NHEADS  16
#define NKV     4
#define HD      128
#define KVW     1024   // 2*NKV*HD

// ---------------- scratch (device globals: no allocation allowed) ----------------
__device__ float  g_cs[S_LEN * 64];   // cos table [s][d]
__device__ float  g_sn[S_LEN * 64];   // sin table [s][d]
// fp16 operand buffers
__device__ __half g_xs [(size_t)NBATCH * S_LEN * EMB];     // x
__device__ __half g_wq [(size_t)EMB * EMB];
__device__ __half g_wkv[(size_t)KVW * EMB];
__device__ __half g_wo [(size_t)EMB * EMB];
__device__ __half g_qs [(size_t)NBATCH * S_LEN * EMB];     // rope Q (scale folded)
__device__ __half g_ks [(size_t)NBATCH * S_LEN * NKV * HD];
__device__ __half g_vs [(size_t)NBATCH * S_LEN * NKV * HD];
__device__ __half g_as [(size_t)NBATCH * S_LEN * EMB];     // attention out

// ---------------- fast exp --------------------------------------------------------
__device__ __forceinline__ float fast_exp(float x) {
    float y  = fmaxf(x * 1.4426950408889634f, -127.0f);
    float fl = floorf(y);
    float f  = y - fl;
    float p  = 1.5403530e-4f;
    p = fmaf(p, f, 1.3333558e-3f);
    p = fmaf(p, f, 9.6181291e-3f);
    p = fmaf(p, f, 5.5504109e-2f);
    p = fmaf(p, f, 2.4022651e-1f);
    p = fmaf(p, f, 6.9314718e-1f);
    p = fmaf(p, f, 1.0f);
    int e = (int)fl;
    float s = __int_as_float((e + 127) << 23);
    return p * s;
}

// ---------------- mma.sync / ldmatrix / cp.async helpers --------------------------
__device__ __forceinline__ uint32_t smem_u32(const void* p) {
    uint32_t a;
    asm("{ .reg .u64 t; cvta.to.shared.u64 t, %1; cvt.u32.u64 %0, t; }" : "=r"(a) : "l"(p));
    return a;
}
#define LDSM_X4(r0, r1, r2, r3, addr) \
    asm volatile("ldmatrix.sync.aligned.m8n8.x4.shared.b16 {%0,%1,%2,%3}, [%4];" \
        : "=r"(r0), "=r"(r1), "=r"(r2), "=r"(r3) : "r"(addr))
#define LDSM_T_X4(r0, r1, r2, r3, addr) \
    asm volatile("ldmatrix.sync.aligned.m8n8.x4.trans.shared.b16 {%0,%1,%2,%3}, [%4];" \
        : "=r"(r0), "=r"(r1), "=r"(r2), "=r"(r3) : "r"(addr))
#define MMAH(c0, c1, c2, c3, a0, a1, a2, a3, b0, b1) \
    asm volatile("mma.sync.aligned.m16n8k16.row.col.f32.f16.f16.f32 " \
        "{%0,%1,%2,%3}, {%4,%5,%6,%7}, {%8,%9}, {%0,%1,%2,%3};" \
        : "+f"(c0), "+f"(c1), "+f"(c2), "+f"(c3) \
        : "r"(a0), "r"(a1), "r"(a2), "r"(a3), "r"(b0), "r"(b1))
#define CP16(d, s) \
    asm volatile("cp.async.cg.shared.global [%0], [%1], 16;" :: "r"(d), "l"(s))
#define CP_COMMIT asm volatile("cp.async.commit_group;" ::: "memory")
#define CP_WAIT2  asm volatile("cp.async.wait_group 2;" ::: "memory")
#define CP_WAIT1  asm volatile("cp.async.wait_group 1;" ::: "memory")
#define CP_WAIT0  asm volatile("cp.async.wait_group 0;" ::: "memory")

// ---------------- init: cos/sin tables (fp64-reduced angles) ----------------------
__global__ void init_tables() {
    int i = blockIdx.x * blockDim.x + threadIdx.x;
    if (i >= S_LEN * 64) return;
    int s = i >> 6, d = i & 63;
    double invf = pow(10000.0, -(double)d / 64.0);
    double ang = (double)s * invf;
    double k = floor(ang * 0.15915494309189535);
    float a = (float)(ang - k * 6.283185307179586);
    g_cs[i] = cosf(a);
    g_sn[i] = sinf(a);
}

// ---------------- split fp32 -> fp16 ----------------------------------------------
__global__ void split1_kernel(const float* __restrict__ src, __half* __restrict__ h, int n4)
{
    int i = blockIdx.x * blockDim.x + threadIdx.x;
    if (i >= n4) return;
    float4 v = ((const float4*)src)[i];
    __half2 h01 = __floats2half2_rn(v.x, v.y);
    __half2 h23 = __floats2half2_rn(v.z, v.w);
    uint2 hv; hv.x = *(uint32_t*)&h01; hv.y = *(uint32_t*)&h23;
    ((uint2*)h)[i] = hv;
}

// ================= GEMM mainloop (shared macro body) ==============================
#define GS_ROW    40                       // padded row: 40 halfs = 80 B
#define GS_TILE   (128 * GS_ROW * 2)       // 10240 B
#define GS_STAGE  (2 * GS_TILE)            // 20480 B (A, W)
#define GEMM_SMEM   (3 * GS_STAGE)         // 61440 B (plain gemm)
#define QKV_SMEM    (128 * 132 * 4 + 1024) // 68608 B (epilogue fp32 tile, > pipeline)

// mainloop macro: fills acc[4][4][4] for (m0, n0) tile, operands A_g/W_g, inner K.
#define GEMM_MAINLOOP(A_g, W_g, K)                                                     \
    const int rIT  = lane & 7;                                                         \
    const int b0_  = (lane >> 3) & 1;                                                  \
    const int b1_  = (lane >> 4) & 1;                                                  \
    const uint32_t aLane = (uint32_t)(((b0_ * 8 + rIT) * GS_ROW + b1_ * 8) * 2);       \
    const uint32_t bLane = (uint32_t)(((b1_ * 8 + rIT) * GS_ROW + b0_ * 8) * 2);       \
    const int nch = (K) >> 5;                                                          \
    LOAD_STAGE(0, 0); CP_COMMIT;                                                       \
    LOAD_STAGE(1, 1); CP_COMMIT;                                                       \
    int buf = 0;                                                                       \
    for (int c = 0; c < nch; c++) {                                                    \
        if (c + 2 < nch) { LOAD_STAGE(c + 2, (buf + 2) % 3); CP_COMMIT; CP_WAIT2; }    \
        else if (c + 1 < nch) CP_WAIT1;                                                \
        else                  CP_WAIT0;                                                \
        __syncthreads();                                                               \
        const uint32_t bb = sbase + (uint32_t)(buf * GS_STAGE);                        \
        const uint32_t Ahs = bb;                                                       \
        const uint32_t Whs = bb + GS_TILE;                                             \
        _Pragma("unroll")                                                              \
        for (int ks = 0; ks < 2; ks++) {                                               \
            const uint32_t kOff = (uint32_t)(ks * 32);                                 \
            uint32_t ah[4][4], bh[4][2];                                               \
            _Pragma("unroll")                                                          \
            for (int mf = 0; mf < 4; mf++) {                                           \
                uint32_t addr = Ahs + (uint32_t)((wm + mf * 16) * GS_ROW * 2) + kOff + aLane; \
                LDSM_X4(ah[mf][0], ah[mf][1], ah[mf][2], ah[mf][3], addr);             \
            }                                                                          \
            _Pragma("unroll")                                                          \
            for (int np = 0; np < 2; np++) {                                           \
                uint32_t addr = Whs + (uint32_t)((wn + np * 16) * GS_ROW * 2) + kOff + bLane; \
                uint32_t r0, r1, r2, r3;                                               \
                LDSM_X4(r0, r1, r2, r3, addr);                                         \
                bh[np * 2][0] = r0; bh[np * 2][1] = r1;                                \
                bh[np * 2 + 1][0] = r2; bh[np * 2 + 1][1] = r3;                        \
            }                                                                          \
            _Pragma("unroll")                                                          \
            for (int mf = 0; mf < 4; mf++)                                             \
                _Pragma("unroll")                                                      \
                for (int nf = 0; nf < 4; nf++)                                         \
                    MMAH(acc[mf][nf][0], acc[mf][nf][1], acc[mf][nf][2], acc[mf][nf][3], \
                         ah[mf][0], ah[mf][1], ah[mf][2], ah[mf][3],                   \
                         bh[nf][0], bh[nf][1]);                                        \
        }                                                                              \
        __syncthreads();                                                               \
        buf = (buf + 1) % 3;                                                           \
    }

#define LOAD_STAGE(c, bufi) do {                                                       \
    int _k0 = (c) << 5;                                                                \
    uint32_t _st = sbase + (uint32_t)((bufi) * GS_STAGE);                              \
    _Pragma("unroll")                                                                  \
    for (int _i = 0; _i < 2; _i++) {                                                   \
        int _ch = tid + _i * 256;                                                      \
        int _r = _ch >> 2, _cl = _ch & 3;                                              \
        uint32_t _d = _st + (uint32_t)(_r * (GS_ROW * 2) + _cl * 16);                  \
        CP16(_d,           A_gp + (size_t)(m0 + _r) * Kd + _k0 + _cl * 8);             \
        CP16(_d + GS_TILE, W_gp + (size_t)(n0 + _r) * Kd + _k0 + _cl * 8);             \
    } } while (0)

// ================= fused QKV projection + RoPE/convert ============================
// grid (24, 32): bx<16 -> Q tile (head bx); bx>=16 -> KV tile (n0=(bx-16)*128).
__global__ __launch_bounds__(256, 2)
void gemm_qkv(const __half* __restrict__ xs_g,
              const __half* __restrict__ wq_g, const __half* __restrict__ wkv_g,
              const float* __restrict__ bq_g, const float* __restrict__ bkv_g)
{
    extern __shared__ char smp[];
    const uint32_t sbase = smem_u32(smp);

    const int tid  = threadIdx.x;
    const int wid  = tid >> 5;
    const int lane = tid & 31;
    const int bx   = blockIdx.x;
    const bool isQ = bx < 16;
    const int m0   = blockIdx.y * 128;
    const int n0   = isQ ? bx * 128 : (bx - 16) * 128;
    const int wm   = (wid >> 2) * 64;
    const int wn   = (wid & 3) * 32;
    const int Kd   = EMB;

    const __half* A_gp = xs_g;
    const __half* W_gp = isQ ? wq_g : wkv_g;
    const float*  bias = isQ ? bq_g : bkv_g;

    float acc[4][4][4];
    #pragma unroll
    for (int i = 0; i < 4; i++)
        #pragma unroll
        for (int j = 0; j < 4; j++)
            #pragma unroll
            for (int e = 0; e < 4; e++) acc[i][j][e] = 0.f;

    GEMM_MAINLOOP(xs_g, W_gp, EMB)

    // ---- bias add (uniform) ----
    const int trow  = lane >> 2;
    const int tcol2 = (lane & 3) * 2;
    #pragma unroll
    for (int nf = 0; nf < 4; nf++) {
        float2 bv = *(const float2*)&bias[n0 + wn + nf * 8 + tcol2];
        #pragma unroll
        for (int mf = 0; mf < 4; mf++) {
            acc[mf][nf][0] += bv.x; acc[mf][nf][1] += bv.y;
            acc[mf][nf][2] += bv.x; acc[mf][nf][3] += bv.y;
        }
    }

    if (!isQ && n0 >= 512) {
        // ---- V tile: direct fp16 convert ----
        #pragma unroll
        for (int mf = 0; mf < 4; mf++) {
            #pragma unroll
            for (int nf = 0; nf < 4; nf++) {
                int grow = m0 + wm + mf * 16 + trow;
                int vcol = n0 - 512 + wn + nf * 8 + tcol2;
                __half2 ha = __floats2half2_rn(acc[mf][nf][0], acc[mf][nf][1]);
                __half2 hb = __floats2half2_rn(acc[mf][nf][2], acc[mf][nf][3]);
                *(uint32_t*)&g_vs[(size_t)grow * 512 + vcol]       = *(uint32_t*)&ha;
                *(uint32_t*)&g_vs[(size_t)(grow + 8) * 512 + vcol] = *(uint32_t*)&hb;
            }
        }
        return;
    }

    // ---- Q or K tile: stage fp32 to smem, RoPE, store fp16 ----
    float* smf = (float*)smp;           // [128][132]
    #pragma unroll
    for (int mf = 0; mf < 4; mf++) {
        #pragma unroll
        for (int nf = 0; nf < 4; nf++) {
            int r = wm + mf * 16 + trow;
            int cidx = wn + nf * 8 + tcol2;
            *(float2*)&smf[r * 132 + cidx]       = make_float2(acc[mf][nf][0], acc[mf][nf][1]);
            *(float2*)&smf[(r + 8) * 132 + cidx] = make_float2(acc[mf][nf][2], acc[mf][nf][3]);
        }
    }
    __syncthreads();

    const float sc = isQ ? 0.08838834764831845f : 1.0f;
    __half* dst    = isQ ? g_qs : g_ks;
    const int width = isQ ? EMB : 512;

    #pragma unroll
    for (int i = 0; i < 16; i++) {
        int idx = tid + i * 256;           // 0..4095
        int row = idx >> 5;                // 0..127
        int dp  = (idx & 31) * 2;          // 0..62
        int grow = m0 + row;
        int s = grow & (S_LEN - 1);
        float t1a = smf[row * 132 + dp];
        float t1b = smf[row * 132 + dp + 1];
        float t2a = smf[row * 132 + dp + 64];
        float t2b = smf[row * 132 + dp + 65];
        float2 csv = *(const float2*)&g_cs[s * 64 + dp];
        float2 snv = *(const float2*)&g_sn[s * 64 + dp];
        float o1a = (t1a * csv.x - t2a * snv.x) * sc;
        float o1b = (t1b * csv.y - t2b * snv.y) * sc;
        float o2a = (t2a * csv.x + t1a * snv.x) * sc;
        float o2b = (t2b * csv.y + t1b * snv.y) * sc;
        __half2 h1 = __floats2half2_rn(o1a, o1b);
        __half2 h2 = __floats2half2_rn(o2a, o2b);
        size_t ob = (size_t)grow * width + n0 + dp;
        *(uint32_t*)&dst[ob]      = *(uint32_t*)&h1;
        *(uint32_t*)&dst[ob + 64] = *(uint32_t*)&h2;
    }
}

// ================= plain GEMM for O projection ====================================
__global__ __launch_bounds__(256, 2)
void gemm_fp16(const __half* __restrict__ A_gp2, const __half* __restrict__ W_gp2,
               float* __restrict__ C, int N, int K)
{
    extern __shared__ char smp[];
    const uint32_t sbase = smem_u32(smp);

    const int tid  = threadIdx.x;
    const int wid  = tid >> 5;
    const int lane = tid & 31;
    const int m0   = blockIdx.y * 128;
    const int n0   = blockIdx.x * 128;
    const int wm   = (wid >> 2) * 64;
    const int wn   = (wid & 3) * 32;
    const int Kd   = K;
    const __half* A_gp = A_gp2;
    const __half* W_gp = W_gp2;

    float acc[4][4][4];
    #pragma unroll
    for (int i = 0; i < 4; i++)
        #pragma unroll
        for (int j = 0; j < 4; j++)
            #pragma unroll
            for (int e = 0; e < 4; e++) acc[i][j][e] = 0.f;

    GEMM_MAINLOOP(A_gp2, W_gp2, K)

    const int trow  = lane >> 2;
    const int tcol2 = (lane & 3) * 2;
    #pragma unroll
    for (int mf = 0; mf < 4; mf++) {
        #pragma unroll
        for (int nf = 0; nf < 4; nf++) {
            int row = m0 + wm + mf * 16 + trow;
            int col = n0 + wn + nf * 8 + tcol2;
            *(float2*)&C[(size_t)row * N + col]       = make_float2(acc[mf][nf][0], acc[mf][nf][1]);
            *(float2*)&C[(size_t)(row + 8) * N + col] = make_float2(acc[mf][nf][2], acc[mf][nf][3]);
        }
    }
}

// ================= fp16 HMMA attention (FA2, single fp16) =========================
#define AP        272
#define QT_BYTES  (128 * AP)
#define KT_BYTES  (64 * AP)
#define KVBUF     (2 * KT_BYTES)                 // K, V
#define ATTN_SMEM (QT_BYTES + 2 * KVBUF)         // 104448

__global__ __launch_bounds__(256, 1) void attn_mma() {
    extern __shared__ char smb[];
    const uint32_t sb = smem_u32(smb);

    const int tid  = threadIdx.x;
    const int wid  = tid >> 5;
    const int lane = tid & 31;
    const int q0   = blockIdx.x * 128;
    const int h    = blockIdx.y;
    const int b    = blockIdx.z;
    const int kvh  = h >> 2;

    const int rIT  = lane & 7;
    const int b3   = (lane >> 3) & 1;
    const int b4   = (lane >> 4) & 1;
    const uint32_t offA = (uint32_t)((b3 * 8 + rIT) * AP + b4 * 16);
    const uint32_t offB = (uint32_t)((b4 * 8 + rIT) * AP + b3 * 16);

    const uint32_t Q_s  = sb;
    const uint32_t KV0  = sb + QT_BYTES;

    const __half* q_g = g_qs + (size_t)(b * S_LEN + q0) * EMB + h * HD;
    const __half* k_g = g_ks + (size_t)b * S_LEN * 512 + kvh * HD;
    const __half* v_g = g_vs + (size_t)b * S_LEN * 512 + kvh * HD;

    #pragma unroll
    for (int i = 0; i < 8; i++) {
        int c = tid + i * 256;
        int row = c >> 4, col = c & 15;
        CP16(Q_s + (uint32_t)(row * AP + col * 16), q_g + (size_t)row * EMB + col * 8);
    }

    #define LOAD_KV(T, BUF) do {                                                       \
        size_t _j = (size_t)((T) * 64);                                                \
        uint32_t _dst = KV0 + (uint32_t)((BUF) * KVBUF);                               \
        _Pragma("unroll")                                                              \
        for (int _i = 0; _i < 4; _i++) {                                               \
            int _c = tid + _i * 256;                                                   \
            int _row = _c >> 4, _col = _c & 15;                                        \
            uint32_t _d0 = _dst + (uint32_t)(_row * AP + _col * 16);                   \
            size_t _s0 = (_j + _row) * 512 + _col * 8;                                 \
            CP16(_d0,            k_g + _s0);                                           \
            CP16(_d0 + KT_BYTES, v_g + _s0);                                           \
        } } while (0)

    LOAD_KV(0, 0);
    CP_COMMIT;

    float m0 = -1e30f, m1 = -1e30f, l0 = 0.f, l1 = 0.f;
    float ofr[16][4];
    #pragma unroll
    for (int i = 0; i < 16; i++)
        #pragma unroll
        for (int e = 0; e < 4; e++) ofr[i][e] = 0.f;

    const uint32_t qwarp = Q_s + (uint32_t)(wid * 16 * AP);

    for (int t = 0; t < 32; t++) {
        if (t < 31) { LOAD_KV(t + 1, (t + 1) & 1); CP_COMMIT; CP_WAIT1; }
        else        { CP_WAIT0; }
        __syncthreads();

        const uint32_t kvb = KV0 + (uint32_t)((t & 1) * KVBUF);
        const uint32_t K_s = kvb;
        const uint32_t V_s = kvb + KT_BYTES;

        float sfr[8][4];
        #pragma unroll
        for (int i = 0; i < 8; i++)
            #pragma unroll
            for (int e = 0; e < 4; e++) sfr[i][e] = 0.f;

        #pragma unroll
        for (int ks = 0; ks < 8; ks++) {
            uint32_t aq0, aq1, aq2, aq3;
            LDSM_X4(aq0, aq1, aq2, aq3, qwarp + ks * 32 + offA);
            uint32_t bh[8][2];
            #pragma unroll
            for (int np = 0; np < 4; np++) {
                uint32_t r0, r1, r2, r3;
                LDSM_X4(r0, r1, r2, r3, K_s + (uint32_t)(np * 16 * AP) + ks * 32 + offB);
                bh[np * 2][0] = r0; bh[np * 2][1] = r1;
                bh[np * 2 + 1][0] = r2; bh[np * 2 + 1][1] = r3;
            }
            #pragma unroll
            for (int nf = 0; nf < 8; nf++)
                MMAH(sfr[nf][0], sfr[nf][1], sfr[nf][2], sfr[nf][3],
                     aq0, aq1, aq2, aq3, bh[nf][0], bh[nf][1]);
        }

        float mx0 = -1e30f, mx1 = -1e30f;
        #pragma unroll
        for (int nf = 0; nf < 8; nf++) {
            mx0 = fmaxf(mx0, fmaxf(sfr[nf][0], sfr[nf][1]));
            mx1 = fmaxf(mx1, fmaxf(sfr[nf][2], sfr[nf][3]));
        }
        mx0 = fmaxf(mx0, __shfl_xor_sync(0xffffffffu, mx0, 1));
        mx0 = fmaxf(mx0, __shfl_xor_sync(0xffffffffu, mx0, 2));
        mx1 = fmaxf(mx1, __shfl_xor_sync(0xffffffffu, mx1, 1));
        mx1 = fmaxf(mx1, __shfl_xor_sync(0xffffffffu, mx1, 2));
        float mn0 = fmaxf(m0, mx0), mn1 = fmaxf(m1, mx1);
        float al0 = fast_exp(m0 - mn0), al1 = fast_exp(m1 - mn1);

        uint32_t ph[4][4];
        float rs0 = 0.f, rs1 = 0.f;
        #pragma unroll
        for (int nf = 0; nf < 8; nf++) {
            float p0 = fast_exp(sfr[nf][0] - mn0);
            float p1 = fast_exp(sfr[nf][1] - mn0);
            float p2 = fast_exp(sfr[nf][2] - mn1);
            float p3 = fast_exp(sfr[nf][3] - mn1);
            rs0 += p0 + p1; rs1 += p2 + p3;
            __half2 h01 = __floats2half2_rn(p0, p1);
            __half2 h23 = __floats2half2_rn(p2, p3);
            int kb = nf >> 1, hf = (nf & 1) * 2;
            ph[kb][hf]     = *(uint32_t*)&h01;
            ph[kb][hf + 1] = *(uint32_t*)&h23;
        }
        rs0 += __shfl_xor_sync(0xffffffffu, rs0, 1);
        rs0 += __shfl_xor_sync(0xffffffffu, rs0, 2);
        rs1 += __shfl_xor_sync(0xffffffffu, rs1, 1);
        rs1 += __shfl_xor_sync(0xffffffffu, rs1, 2);
        l0 = l0 * al0 + rs0;
        l1 = l1 * al1 + rs1;
        m0 = mn0; m1 = mn1;

        #pragma unroll
        for (int nf = 0; nf < 16; nf++) {
            ofr[nf][0] *= al0; ofr[nf][1] *= al0;
            ofr[nf][2] *= al1; ofr[nf][3] *= al1;
        }

        #pragma unroll
        for (int kb = 0; kb < 4; kb++) {
            #pragma unroll
            for (int db = 0; db < 8; db++) {
                uint32_t vh0, vh1, vh2, vh3;
                uint32_t va = (uint32_t)(kb * 16 * AP + db * 32) + offA;
                LDSM_T_X4(vh0, vh1, vh2, vh3, V_s + va);
                int nf = db * 2;
                MMAH(ofr[nf][0], ofr[nf][1], ofr[nf][2], ofr[nf][3],
                     ph[kb][0], ph[kb][1], ph[kb][2], ph[kb][3], vh0, vh1);
                MMAH(ofr[nf + 1][0], ofr[nf + 1][1], ofr[nf + 1][2], ofr[nf + 1][3],
                     ph[kb][0], ph[kb][1], ph[kb][2], ph[kb][3], vh2, vh3);
            }
        }
        __syncthreads();
    }

    float li0 = 1.0f / l0, li1 = 1.0f / l1;
    int row0 = q0 + wid * 16 + (lane >> 2);
    size_t ob = (size_t)(b * S_LEN + row0) * EMB + h * HD + (lane & 3) * 2;
    #pragma unroll
    for (int nf = 0; nf < 16; nf++) {
        __half2 h01 = __floats2half2_rn(ofr[nf][0] * li0, ofr[nf][1] * li0);
        __half2 h23 = __floats2half2_rn(ofr[nf][2] * li1, ofr[nf][3] * li1);
        *(uint32_t*)&g_as[ob + nf * 8]           = *(uint32_t*)&h01;
        *(uint32_t*)&g_as[ob + 8 * EMB + nf * 8] = *(uint32_t*)&h23;
    }
    #undef LOAD_KV
}

// ---------------- launch ----------------------------------------------------------
extern "C" void kernel_launch(void* const* d_in, const int* in_sizes, int n_in,
                              void* d_out, int out_size)
{
    const float* x   = (const float*)d_in[0];
    const float* Wq  = (const float*)d_in[1];
    const float* bq  = (const float*)d_in[2];
    const float* Wkv = (const float*)d_in[3];
    const float* bkv = (const float*)d_in[4];
    const float* Wo  = (const float*)d_in[5];
    float* out = (float*)d_out;

    __half *xs, *wq, *wkv, *wo, *as;
    cudaGetSymbolAddress((void**)&xs,  g_xs);
    cudaGetSymbolAddress((void**)&wq,  g_wq);
    cudaGetSymbolAddress((void**)&wkv, g_wkv);
    cudaGetSymbolAddress((void**)&wo,  g_wo);
    cudaGetSymbolAddress((void**)&as,  g_as);

    cudaFuncSetAttribute(gemm_qkv, cudaFuncAttributeMaxDynamicSharedMemorySize, QKV_SMEM);
    cudaFuncSetAttribute(gemm_fp16, cudaFuncAttributeMaxDynamicSharedMemorySize, GEMM_SMEM);
    cudaFuncSetAttribute(attn_mma, cudaFuncAttributeMaxDynamicSharedMemorySize, ATTN_SMEM);

    dim3 blk(256);

    init_tables<<<(S_LEN * 64 + 255) / 256, 256>>>();

    const int nx   = NBATCH * S_LEN * EMB / 4;
    const int nwq  = EMB * EMB / 4;
    const int nwkv = KVW * EMB / 4;
    split1_kernel<<<(nx   + 255) / 256, 256>>>(x,   xs,  nx);
    split1_kernel<<<(nwq  + 255) / 256, 256>>>(Wq,  wq,  nwq);
    split1_kernel<<<(nwkv + 255) / 256, 256>>>(Wkv, wkv, nwkv);
    split1_kernel<<<(nwq  + 255) / 256, 256>>>(Wo,  wo,  nwq);

    // fused Q + KV projection with RoPE/convert epilogues
    gemm_qkv<<<dim3(24, 32), blk, QKV_SMEM>>>(xs, wq, wkv, bq, bkv);

    attn_mma<<<dim3(S_LEN / 128, NHEADS, NBATCH), blk, ATTN_SMEM>>>();

    // out = attn @ Wo^T
    gemm_fp16<<<dim3(16, 32), blk, GEMM_SMEM>>>(as, wo, out, EMB, EMB);
}

// round 10
// speedup vs baseline: 9.5131x; 1.0499x over previous
#include <cuda_runtime.h>
#include <cuda_fp16.h>
#include <math.h>
#include <stdint.h>

#define S_LEN   2048
#define NBATCH  2
#define EMB     2048
#define NHEADS  16
#define NKV     4
#define HD      128
#define KVW     1024   // 2*NKV*HD

// ---------------- scratch (device globals: no allocation allowed) ----------------
__device__ float  g_cs[S_LEN * 64];   // cos table [s][d]
__device__ float  g_sn[S_LEN * 64];   // sin table [s][d]
// fp16 operand buffers
__device__ __half g_xs [(size_t)NBATCH * S_LEN * EMB];     // x
__device__ __half g_wq [(size_t)EMB * EMB];
__device__ __half g_wkv[(size_t)KVW * EMB];
__device__ __half g_wo [(size_t)EMB * EMB];
__device__ __half g_qs [(size_t)NBATCH * S_LEN * EMB];     // rope Q (scale folded)
__device__ __half g_ks [(size_t)NBATCH * S_LEN * NKV * HD];
__device__ __half g_vs [(size_t)NBATCH * S_LEN * NKV * HD];
__device__ __half g_as [(size_t)NBATCH * S_LEN * EMB];     // attention out

// ---------------- fast exp --------------------------------------------------------
__device__ __forceinline__ float fast_exp(float x) {
    float y  = fmaxf(x * 1.4426950408889634f, -127.0f);
    float fl = floorf(y);
    float f  = y - fl;
    float p  = 1.5403530e-4f;
    p = fmaf(p, f, 1.3333558e-3f);
    p = fmaf(p, f, 9.6181291e-3f);
    p = fmaf(p, f, 5.5504109e-2f);
    p = fmaf(p, f, 2.4022651e-1f);
    p = fmaf(p, f, 6.9314718e-1f);
    p = fmaf(p, f, 1.0f);
    int e = (int)fl;
    float s = __int_as_float((e + 127) << 23);
    return p * s;
}

// ---------------- mma.sync / ldmatrix / cp.async helpers --------------------------
__device__ __forceinline__ uint32_t smem_u32(const void* p) {
    uint32_t a;
    asm("{ .reg .u64 t; cvta.to.shared.u64 t, %1; cvt.u32.u64 %0, t; }" : "=r"(a) : "l"(p));
    return a;
}
#define LDSM_X4(r0, r1, r2, r3, addr) \
    asm volatile("ldmatrix.sync.aligned.m8n8.x4.shared.b16 {%0,%1,%2,%3}, [%4];" \
        : "=r"(r0), "=r"(r1), "=r"(r2), "=r"(r3) : "r"(addr))
#define LDSM_T_X4(r0, r1, r2, r3, addr) \
    asm volatile("ldmatrix.sync.aligned.m8n8.x4.trans.shared.b16 {%0,%1,%2,%3}, [%4];" \
        : "=r"(r0), "=r"(r1), "=r"(r2), "=r"(r3) : "r"(addr))
#define MMAH(c0, c1, c2, c3, a0, a1, a2, a3, b0, b1) \
    asm volatile("mma.sync.aligned.m16n8k16.row.col.f32.f16.f16.f32 " \
        "{%0,%1,%2,%3}, {%4,%5,%6,%7}, {%8,%9}, {%0,%1,%2,%3};" \
        : "+f"(c0), "+f"(c1), "+f"(c2), "+f"(c3) \
        : "r"(a0), "r"(a1), "r"(a2), "r"(a3), "r"(b0), "r"(b1))
#define CP16(d, s) \
    asm volatile("cp.async.cg.shared.global [%0], [%1], 16;" :: "r"(d), "l"(s))
#define CP_COMMIT asm volatile("cp.async.commit_group;" ::: "memory")
#define CP_WAIT2  asm volatile("cp.async.wait_group 2;" ::: "memory")
#define CP_WAIT1  asm volatile("cp.async.wait_group 1;" ::: "memory")
#define CP_WAIT0  asm volatile("cp.async.wait_group 0;" ::: "memory")

// ================= merged prep: splits + rope tables (one launch) =================
#define NX4   (NBATCH * S_LEN * EMB / 4)   // 2097152
#define NWQ4  (EMB * EMB / 4)              // 1048576
#define NWKV4 (KVW * EMB / 4)              // 524288
#define NTAB  (S_LEN * 64)                 // 131072
#define PREP_TOTAL (NX4 + NWQ4 + NWKV4 + NWQ4 + NTAB)

__global__ void prep_kernel(const float* __restrict__ x,  const float* __restrict__ Wq,
                            const float* __restrict__ Wkv, const float* __restrict__ Wo)
{
    int i = blockIdx.x * blockDim.x + threadIdx.x;
    const float* src;
    __half* dst;
    if (i < NX4)                      { src = x;   dst = g_xs; }
    else if ((i -= NX4) < NWQ4)       { src = Wq;  dst = g_wq; }
    else if ((i -= NWQ4) < NWKV4)     { src = Wkv; dst = g_wkv; }
    else if ((i -= NWKV4) < NWQ4)     { src = Wo;  dst = g_wo; }
    else {
        i -= NWQ4;
        if (i >= NTAB) return;
        int s = i >> 6, d = i & 63;
        double invf = pow(10000.0, -(double)d / 64.0);
        double ang = (double)s * invf;
        double k = floor(ang * 0.15915494309189535);
        float a = (float)(ang - k * 6.283185307179586);
        g_cs[i] = cosf(a);
        g_sn[i] = sinf(a);
        return;
    }
    float4 v = ((const float4*)src)[i];
    __half2 h01 = __floats2half2_rn(v.x, v.y);
    __half2 h23 = __floats2half2_rn(v.z, v.w);
    uint2 hv; hv.x = *(uint32_t*)&h01; hv.y = *(uint32_t*)&h23;
    ((uint2*)dst)[i] = hv;
}

// ================= GEMM mainloop (shared macro body) ==============================
#define GS_ROW    40                       // padded row: 40 halfs = 80 B
#define GS_TILE   (128 * GS_ROW * 2)       // 10240 B
#define GS_STAGE  (2 * GS_TILE)            // 20480 B (A, W)
#define GEMM_SMEM   (3 * GS_STAGE)         // 61440 B (plain gemm)
#define QKV_SMEM    (128 * 132 * 4 + 1024) // 68608 B (epilogue fp32 tile, > pipeline)

#define GEMM_MAINLOOP(A_g, W_g, K)                                                     \
    const int rIT  = lane & 7;                                                         \
    const int b0_  = (lane >> 3) & 1;                                                  \
    const int b1_  = (lane >> 4) & 1;                                                  \
    const uint32_t aLane = (uint32_t)(((b0_ * 8 + rIT) * GS_ROW + b1_ * 8) * 2);       \
    const uint32_t bLane = (uint32_t)(((b1_ * 8 + rIT) * GS_ROW + b0_ * 8) * 2);       \
    const int nch = (K) >> 5;                                                          \
    LOAD_STAGE(0, 0); CP_COMMIT;                                                       \
    LOAD_STAGE(1, 1); CP_COMMIT;                                                       \
    int buf = 0;                                                                       \
    for (int c = 0; c < nch; c++) {                                                    \
        if (c + 2 < nch) { LOAD_STAGE(c + 2, (buf + 2) % 3); CP_COMMIT; CP_WAIT2; }    \
        else if (c + 1 < nch) CP_WAIT1;                                                \
        else                  CP_WAIT0;                                                \
        __syncthreads();                                                               \
        const uint32_t bb = sbase + (uint32_t)(buf * GS_STAGE);                        \
        const uint32_t Ahs = bb;                                                       \
        const uint32_t Whs = bb + GS_TILE;                                             \
        _Pragma("unroll")                                                              \
        for (int ks = 0; ks < 2; ks++) {                                               \
            const uint32_t kOff = (uint32_t)(ks * 32);                                 \
            uint32_t ah[4][4], bh[4][2];                                               \
            _Pragma("unroll")                                                          \
            for (int mf = 0; mf < 4; mf++) {                                           \
                uint32_t addr = Ahs + (uint32_t)((wm + mf * 16) * GS_ROW * 2) + kOff + aLane; \
                LDSM_X4(ah[mf][0], ah[mf][1], ah[mf][2], ah[mf][3], addr);             \
            }                                                                          \
            _Pragma("unroll")                                                          \
            for (int np = 0; np < 2; np++) {                                           \
                uint32_t addr = Whs + (uint32_t)((wn + np * 16) * GS_ROW * 2) + kOff + bLane; \
                uint32_t r0, r1, r2, r3;                                               \
                LDSM_X4(r0, r1, r2, r3, addr);                                         \
                bh[np * 2][0] = r0; bh[np * 2][1] = r1;                                \
                bh[np * 2 + 1][0] = r2; bh[np * 2 + 1][1] = r3;                        \
            }                                                                          \
            _Pragma("unroll")                                                          \
            for (int mf = 0; mf < 4; mf++)                                             \
                _Pragma("unroll")                                                      \
                for (int nf = 0; nf < 4; nf++)                                         \
                    MMAH(acc[mf][nf][0], acc[mf][nf][1], acc[mf][nf][2], acc[mf][nf][3], \
                         ah[mf][0], ah[mf][1], ah[mf][2], ah[mf][3],                   \
                         bh[nf][0], bh[nf][1]);                                        \
        }                                                                              \
        __syncthreads();                                                               \
        buf = (buf + 1) % 3;                                                           \
    }

#define LOAD_STAGE(c, bufi) do {                                                       \
    int _k0 = (c) << 5;                                                                \
    uint32_t _st = sbase + (uint32_t)((bufi) * GS_STAGE);                              \
    _Pragma("unroll")                                                                  \
    for (int _i = 0; _i < 2; _i++) {                                                   \
        int _ch = tid + _i * 256;                                                      \
        int _r = _ch >> 2, _cl = _ch & 3;                                              \
        uint32_t _d = _st + (uint32_t)(_r * (GS_ROW * 2) + _cl * 16);                  \
        CP16(_d,           A_gp + (size_t)(m0 + _r) * Kd + _k0 + _cl * 8);             \
        CP16(_d + GS_TILE, W_gp + (size_t)(n0 + _r) * Kd + _k0 + _cl * 8);             \
    } } while (0)

// ================= fused QKV projection + RoPE/convert ============================
__global__ __launch_bounds__(256, 2)
void gemm_qkv(const __half* __restrict__ xs_g,
              const __half* __restrict__ wq_g, const __half* __restrict__ wkv_g,
              const float* __restrict__ bq_g, const float* __restrict__ bkv_g)
{
    extern __shared__ char smp[];
    const uint32_t sbase = smem_u32(smp);

    const int tid  = threadIdx.x;
    const int wid  = tid >> 5;
    const int lane = tid & 31;
    const int bx   = blockIdx.x;
    const bool isQ = bx < 16;
    const int m0   = blockIdx.y * 128;
    const int n0   = isQ ? bx * 128 : (bx - 16) * 128;
    const int wm   = (wid >> 2) * 64;
    const int wn   = (wid & 3) * 32;
    const int Kd   = EMB;

    const __half* A_gp = xs_g;
    const __half* W_gp = isQ ? wq_g : wkv_g;
    const float*  bias = isQ ? bq_g : bkv_g;

    float acc[4][4][4];
    #pragma unroll
    for (int i = 0; i < 4; i++)
        #pragma unroll
        for (int j = 0; j < 4; j++)
            #pragma unroll
            for (int e = 0; e < 4; e++) acc[i][j][e] = 0.f;

    GEMM_MAINLOOP(xs_g, W_gp, EMB)

    const int trow  = lane >> 2;
    const int tcol2 = (lane & 3) * 2;
    #pragma unroll
    for (int nf = 0; nf < 4; nf++) {
        float2 bv = *(const float2*)&bias[n0 + wn + nf * 8 + tcol2];
        #pragma unroll
        for (int mf = 0; mf < 4; mf++) {
            acc[mf][nf][0] += bv.x; acc[mf][nf][1] += bv.y;
            acc[mf][nf][2] += bv.x; acc[mf][nf][3] += bv.y;
        }
    }

    if (!isQ && n0 >= 512) {
        // ---- V tile: direct fp16 convert ----
        #pragma unroll
        for (int mf = 0; mf < 4; mf++) {
            #pragma unroll
            for (int nf = 0; nf < 4; nf++) {
                int grow = m0 + wm + mf * 16 + trow;
                int vcol = n0 - 512 + wn + nf * 8 + tcol2;
                __half2 ha = __floats2half2_rn(acc[mf][nf][0], acc[mf][nf][1]);
                __half2 hb = __floats2half2_rn(acc[mf][nf][2], acc[mf][nf][3]);
                *(uint32_t*)&g_vs[(size_t)grow * 512 + vcol]       = *(uint32_t*)&ha;
                *(uint32_t*)&g_vs[(size_t)(grow + 8) * 512 + vcol] = *(uint32_t*)&hb;
            }
        }
        return;
    }

    // ---- Q or K tile: stage fp32 to smem, RoPE, store fp16 ----
    float* smf = (float*)smp;           // [128][132]
    #pragma unroll
    for (int mf = 0; mf < 4; mf++) {
        #pragma unroll
        for (int nf = 0; nf < 4; nf++) {
            int r = wm + mf * 16 + trow;
            int cidx = wn + nf * 8 + tcol2;
            *(float2*)&smf[r * 132 + cidx]       = make_float2(acc[mf][nf][0], acc[mf][nf][1]);
            *(float2*)&smf[(r + 8) * 132 + cidx] = make_float2(acc[mf][nf][2], acc[mf][nf][3]);
        }
    }
    __syncthreads();

    const float sc = isQ ? 0.08838834764831845f : 1.0f;
    __half* dst    = isQ ? g_qs : g_ks;
    const int width = isQ ? EMB : 512;

    #pragma unroll
    for (int i = 0; i < 16; i++) {
        int idx = tid + i * 256;
        int row = idx >> 5;
        int dp  = (idx & 31) * 2;
        int grow = m0 + row;
        int s = grow & (S_LEN - 1);
        float t1a = smf[row * 132 + dp];
        float t1b = smf[row * 132 + dp + 1];
        float t2a = smf[row * 132 + dp + 64];
        float t2b = smf[row * 132 + dp + 65];
        float2 csv = *(const float2*)&g_cs[s * 64 + dp];
        float2 snv = *(const float2*)&g_sn[s * 64 + dp];
        float o1a = (t1a * csv.x - t2a * snv.x) * sc;
        float o1b = (t1b * csv.y - t2b * snv.y) * sc;
        float o2a = (t2a * csv.x + t1a * snv.x) * sc;
        float o2b = (t2b * csv.y + t1b * snv.y) * sc;
        __half2 h1 = __floats2half2_rn(o1a, o1b);
        __half2 h2 = __floats2half2_rn(o2a, o2b);
        size_t ob = (size_t)grow * width + n0 + dp;
        *(uint32_t*)&dst[ob]      = *(uint32_t*)&h1;
        *(uint32_t*)&dst[ob + 64] = *(uint32_t*)&h2;
    }
}

// ================= plain GEMM for O projection ====================================
__global__ __launch_bounds__(256, 2)
void gemm_fp16(const __half* __restrict__ A_gp2, const __half* __restrict__ W_gp2,
               float* __restrict__ C, int N, int K)
{
    extern __shared__ char smp[];
    const uint32_t sbase = smem_u32(smp);

    const int tid  = threadIdx.x;
    const int wid  = tid >> 5;
    const int lane = tid & 31;
    const int m0   = blockIdx.y * 128;
    const int n0   = blockIdx.x * 128;
    const int wm   = (wid >> 2) * 64;
    const int wn   = (wid & 3) * 32;
    const int Kd   = K;
    const __half* A_gp = A_gp2;
    const __half* W_gp = W_gp2;

    float acc[4][4][4];
    #pragma unroll
    for (int i = 0; i < 4; i++)
        #pragma unroll
        for (int j = 0; j < 4; j++)
            #pragma unroll
            for (int e = 0; e < 4; e++) acc[i][j][e] = 0.f;

    GEMM_MAINLOOP(A_gp2, W_gp2, K)

    const int trow  = lane >> 2;
    const int tcol2 = (lane & 3) * 2;
    #pragma unroll
    for (int mf = 0; mf < 4; mf++) {
        #pragma unroll
        for (int nf = 0; nf < 4; nf++) {
            int row = m0 + wm + mf * 16 + trow;
            int col = n0 + wn + nf * 8 + tcol2;
            *(float2*)&C[(size_t)row * N + col]       = make_float2(acc[mf][nf][0], acc[mf][nf][1]);
            *(float2*)&C[(size_t)(row + 8) * N + col] = make_float2(acc[mf][nf][2], acc[mf][nf][3]);
        }
    }
}

// ================= fp16 HMMA attention (FA2, 64-row tiles, occupancy 2) ===========
#define AP        272
#define QT_BYTES  (64 * AP)                      // 17408
#define KT_BYTES  (64 * AP)
#define KVBUF     (2 * KT_BYTES)                 // K, V
#define ATTN_SMEM (QT_BYTES + 2 * KVBUF)         // 87040

__global__ __launch_bounds__(128, 2) void attn_mma() {
    extern __shared__ char smb[];
    const uint32_t sb = smem_u32(smb);

    const int tid  = threadIdx.x;
    const int wid  = tid >> 5;          // 0..3
    const int lane = tid & 31;
    const int q0   = blockIdx.x * 64;
    const int h    = blockIdx.y;
    const int b    = blockIdx.z;
    const int kvh  = h >> 2;

    const int rIT  = lane & 7;
    const int b3   = (lane >> 3) & 1;
    const int b4   = (lane >> 4) & 1;
    const uint32_t offA = (uint32_t)((b3 * 8 + rIT) * AP + b4 * 16);
    const uint32_t offB = (uint32_t)((b4 * 8 + rIT) * AP + b3 * 16);

    const uint32_t Q_s  = sb;
    const uint32_t KV0  = sb + QT_BYTES;

    const __half* q_g = g_qs + (size_t)(b * S_LEN + q0) * EMB + h * HD;
    const __half* k_g = g_ks + (size_t)b * S_LEN * 512 + kvh * HD;
    const __half* v_g = g_vs + (size_t)b * S_LEN * 512 + kvh * HD;

    #pragma unroll
    for (int i = 0; i < 8; i++) {
        int c = tid + i * 128;            // 0..1023 (64 rows x 16 col-chunks)
        int row = c >> 4, col = c & 15;
        CP16(Q_s + (uint32_t)(row * AP + col * 16), q_g + (size_t)row * EMB + col * 8);
    }

    #define LOAD_KV(T, BUF) do {                                                       \
        size_t _j = (size_t)((T) * 64);                                                \
        uint32_t _dst = KV0 + (uint32_t)((BUF) * KVBUF);                               \
        _Pragma("unroll")                                                              \
        for (int _i = 0; _i < 8; _i++) {                                               \
            int _c = tid + _i * 128;                                                   \
            int _row = _c >> 4, _col = _c & 15;                                        \
            uint32_t _d0 = _dst + (uint32_t)(_row * AP + _col * 16);                   \
            size_t _s0 = (_j + _row) * 512 + _col * 8;                                 \
            CP16(_d0,            k_g + _s0);                                           \
            CP16(_d0 + KT_BYTES, v_g + _s0);                                           \
        } } while (0)

    LOAD_KV(0, 0);
    CP_COMMIT;

    float m0 = -1e30f, m1 = -1e30f, l0 = 0.f, l1 = 0.f;
    float ofr[16][4];
    #pragma unroll
    for (int i = 0; i < 16; i++)
        #pragma unroll
        for (int e = 0; e < 4; e++) ofr[i][e] = 0.f;

    const uint32_t qwarp = Q_s + (uint32_t)(wid * 16 * AP);

    for (int t = 0; t < 32; t++) {
        if (t < 31) { LOAD_KV(t + 1, (t + 1) & 1); CP_COMMIT; CP_WAIT1; }
        else        { CP_WAIT0; }
        __syncthreads();

        const uint32_t kvb = KV0 + (uint32_t)((t & 1) * KVBUF);
        const uint32_t K_s = kvb;
        const uint32_t V_s = kvb + KT_BYTES;

        float sfr[8][4];
        #pragma unroll
        for (int i = 0; i < 8; i++)
            #pragma unroll
            for (int e = 0; e < 4; e++) sfr[i][e] = 0.f;

        #pragma unroll
        for (int ks = 0; ks < 8; ks++) {
            uint32_t aq0, aq1, aq2, aq3;
            LDSM_X4(aq0, aq1, aq2, aq3, qwarp + ks * 32 + offA);
            uint32_t bh[8][2];
            #pragma unroll
            for (int np = 0; np < 4; np++) {
                uint32_t r0, r1, r2, r3;
                LDSM_X4(r0, r1, r2, r3, K_s + (uint32_t)(np * 16 * AP) + ks * 32 + offB);
                bh[np * 2][0] = r0; bh[np * 2][1] = r1;
                bh[np * 2 + 1][0] = r2; bh[np * 2 + 1][1] = r3;
            }
            #pragma unroll
            for (int nf = 0; nf < 8; nf++)
                MMAH(sfr[nf][0], sfr[nf][1], sfr[nf][2], sfr[nf][3],
                     aq0, aq1, aq2, aq3, bh[nf][0], bh[nf][1]);
        }

        float mx0 = -1e30f, mx1 = -1e30f;
        #pragma unroll
        for (int nf = 0; nf < 8; nf++) {
            mx0 = fmaxf(mx0, fmaxf(sfr[nf][0], sfr[nf][1]));
            mx1 = fmaxf(mx1, fmaxf(sfr[nf][2], sfr[nf][3]));
        }
        mx0 = fmaxf(mx0, __shfl_xor_sync(0xffffffffu, mx0, 1));
        mx0 = fmaxf(mx0, __shfl_xor_sync(0xffffffffu, mx0, 2));
        mx1 = fmaxf(mx1, __shfl_xor_sync(0xffffffffu, mx1, 1));
        mx1 = fmaxf(mx1, __shfl_xor_sync(0xffffffffu, mx1, 2));
        float mn0 = fmaxf(m0, mx0), mn1 = fmaxf(m1, mx1);
        float al0 = fast_exp(m0 - mn0), al1 = fast_exp(m1 - mn1);

        uint32_t ph[4][4];
        float rs0 = 0.f, rs1 = 0.f;
        #pragma unroll
        for (int nf = 0; nf < 8; nf++) {
            float p0 = fast_exp(sfr[nf][0] - mn0);
            float p1 = fast_exp(sfr[nf][1] - mn0);
            float p2 = fast_exp(sfr[nf][2] - mn1);
            float p3 = fast_exp(sfr[nf][3] - mn1);
            rs0 += p0 + p1; rs1 += p2 + p3;
            __half2 h01 = __floats2half2_rn(p0, p1);
            __half2 h23 = __floats2half2_rn(p2, p3);
            int kb = nf >> 1, hf = (nf & 1) * 2;
            ph[kb][hf]     = *(uint32_t*)&h01;
            ph[kb][hf + 1] = *(uint32_t*)&h23;
        }
        rs0 += __shfl_xor_sync(0xffffffffu, rs0, 1);
        rs0 += __shfl_xor_sync(0xffffffffu, rs0, 2);
        rs1 += __shfl_xor_sync(0xffffffffu, rs1, 1);
        rs1 += __shfl_xor_sync(0xffffffffu, rs1, 2);
        l0 = l0 * al0 + rs0;
        l1 = l1 * al1 + rs1;
        m0 = mn0; m1 = mn1;

        #pragma unroll
        for (int nf = 0; nf < 16; nf++) {
            ofr[nf][0] *= al0; ofr[nf][1] *= al0;
            ofr[nf][2] *= al1; ofr[nf][3] *= al1;
        }

        #pragma unroll
        for (int kb = 0; kb < 4; kb++) {
            #pragma unroll
            for (int db = 0; db < 8; db++) {
                uint32_t vh0, vh1, vh2, vh3;
                uint32_t va = (uint32_t)(kb * 16 * AP + db * 32) + offA;
                LDSM_T_X4(vh0, vh1, vh2, vh3, V_s + va);
                int nf = db * 2;
                MMAH(ofr[nf][0], ofr[nf][1], ofr[nf][2], ofr[nf][3],
                     ph[kb][0], ph[kb][1], ph[kb][2], ph[kb][3], vh0, vh1);
                MMAH(ofr[nf + 1][0], ofr[nf + 1][1], ofr[nf + 1][2], ofr[nf + 1][3],
                     ph[kb][0], ph[kb][1], ph[kb][2], ph[kb][3], vh2, vh3);
            }
        }
        __syncthreads();
    }

    float li0 = 1.0f / l0, li1 = 1.0f / l1;
    int row0 = q0 + wid * 16 + (lane >> 2);
    size_t ob = (size_t)(b * S_LEN + row0) * EMB + h * HD + (lane & 3) * 2;
    #pragma unroll
    for (int nf = 0; nf < 16; nf++) {
        __half2 h01 = __floats2half2_rn(ofr[nf][0] * li0, ofr[nf][1] * li0);
        __half2 h23 = __floats2half2_rn(ofr[nf][2] * li1, ofr[nf][3] * li1);
        *(uint32_t*)&g_as[ob + nf * 8]           = *(uint32_t*)&h01;
        *(uint32_t*)&g_as[ob + 8 * EMB + nf * 8] = *(uint32_t*)&h23;
    }
    #undef LOAD_KV
}

// ---------------- launch ----------------------------------------------------------
extern "C" void kernel_launch(void* const* d_in, const int* in_sizes, int n_in,
                              void* d_out, int out_size)
{
    const float* x   = (const float*)d_in[0];
    const float* Wq  = (const float*)d_in[1];
    const float* bq  = (const float*)d_in[2];
    const float* Wkv = (const float*)d_in[3];
    const float* bkv = (const float*)d_in[4];
    const float* Wo  = (const float*)d_in[5];
    float* out = (float*)d_out;

    __half *xs, *wq, *wkv, *wo, *as;
    cudaGetSymbolAddress((void**)&xs,  g_xs);
    cudaGetSymbolAddress((void**)&wq,  g_wq);
    cudaGetSymbolAddress((void**)&wkv, g_wkv);
    cudaGetSymbolAddress((void**)&wo,  g_wo);
    cudaGetSymbolAddress((void**)&as,  g_as);

    cudaFuncSetAttribute(gemm_qkv, cudaFuncAttributeMaxDynamicSharedMemorySize, QKV_SMEM);
    cudaFuncSetAttribute(gemm_fp16, cudaFuncAttributeMaxDynamicSharedMemorySize, GEMM_SMEM);
    cudaFuncSetAttribute(attn_mma, cudaFuncAttributeMaxDynamicSharedMemorySize, ATTN_SMEM);

    // one prep launch: all fp16 splits + rope tables
    prep_kernel<<<(PREP_TOTAL + 255) / 256, 256>>>(x, Wq, Wkv, Wo);

    // fused Q + KV projection with RoPE/convert epilogues
    gemm_qkv<<<dim3(24, 32), dim3(256), QKV_SMEM>>>(xs, wq, wkv, bq, bkv);

    attn_mma<<<dim3(S_LEN / 64, NHEADS, NBATCH), dim3(128), ATTN_SMEM>>>();

    // out = attn @ Wo^T
    gemm_fp16<<<dim3(16, 32), dim3(256), GEMM_SMEM>>>(as, wo, out, EMB, EMB);
}

// round 11
// speedup vs baseline: 10.2380x; 1.0762x over previous
#include <cuda_runtime.h>
#include <cuda_fp16.h>
#include <math.h>
#include <stdint.h>

#define S_LEN   2048
#define NBATCH  2
#define EMB     2048
#define NHEADS  16
#define NKV     4
#define HD      128
#define KVW     1024   // 2*NKV*HD

// ---------------- scratch (device globals: no allocation allowed) ----------------
__device__ float  g_cs[S_LEN * 64];   // cos table [s][d]
__device__ float  g_sn[S_LEN * 64];   // sin table [s][d]
// fp16 operand buffers
__device__ __half g_xs [(size_t)NBATCH * S_LEN * EMB];     // x
__device__ __half g_wq [(size_t)EMB * EMB];
__device__ __half g_wkv[(size_t)KVW * EMB];
__device__ __half g_wo [(size_t)EMB * EMB];
__device__ __half g_qs [(size_t)NBATCH * S_LEN * EMB];     // rope Q (scale folded)
__device__ __half g_ks [(size_t)NBATCH * S_LEN * NKV * HD];
__device__ __half g_vs [(size_t)NBATCH * S_LEN * NKV * HD];
__device__ __half g_as [(size_t)NBATCH * S_LEN * EMB];     // attention out

// ---------------- fast exp --------------------------------------------------------
__device__ __forceinline__ float fast_exp(float x) {
    float y  = fmaxf(x * 1.4426950408889634f, -127.0f);
    float fl = floorf(y);
    float f  = y - fl;
    float p  = 1.5403530e-4f;
    p = fmaf(p, f, 1.3333558e-3f);
    p = fmaf(p, f, 9.6181291e-3f);
    p = fmaf(p, f, 5.5504109e-2f);
    p = fmaf(p, f, 2.4022651e-1f);
    p = fmaf(p, f, 6.9314718e-1f);
    p = fmaf(p, f, 1.0f);
    int e = (int)fl;
    float s = __int_as_float((e + 127) << 23);
    return p * s;
}

// ---------------- mma.sync / ldmatrix / cp.async helpers --------------------------
__device__ __forceinline__ uint32_t smem_u32(const void* p) {
    uint32_t a;
    asm("{ .reg .u64 t; cvta.to.shared.u64 t, %1; cvt.u32.u64 %0, t; }" : "=r"(a) : "l"(p));
    return a;
}
#define LDSM_X4(r0, r1, r2, r3, addr) \
    asm volatile("ldmatrix.sync.aligned.m8n8.x4.shared.b16 {%0,%1,%2,%3}, [%4];" \
        : "=r"(r0), "=r"(r1), "=r"(r2), "=r"(r3) : "r"(addr))
#define LDSM_T_X4(r0, r1, r2, r3, addr) \
    asm volatile("ldmatrix.sync.aligned.m8n8.x4.trans.shared.b16 {%0,%1,%2,%3}, [%4];" \
        : "=r"(r0), "=r"(r1), "=r"(r2), "=r"(r3) : "r"(addr))
#define MMAH(c0, c1, c2, c3, a0, a1, a2, a3, b0, b1) \
    asm volatile("mma.sync.aligned.m16n8k16.row.col.f32.f16.f16.f32 " \
        "{%0,%1,%2,%3}, {%4,%5,%6,%7}, {%8,%9}, {%0,%1,%2,%3};" \
        : "+f"(c0), "+f"(c1), "+f"(c2), "+f"(c3) \
        : "r"(a0), "r"(a1), "r"(a2), "r"(a3), "r"(b0), "r"(b1))
#define CP16(d, s) \
    asm volatile("cp.async.cg.shared.global [%0], [%1], 16;" :: "r"(d), "l"(s))
#define CP_COMMIT asm volatile("cp.async.commit_group;" ::: "memory")
#define CP_WAIT1  asm volatile("cp.async.wait_group 1;" ::: "memory")
#define CP_WAIT0  asm volatile("cp.async.wait_group 0;" ::: "memory")

// ================= merged prep: splits + rope tables (one launch) =================
#define NX4   (NBATCH * S_LEN * EMB / 4)
#define NWQ4  (EMB * EMB / 4)
#define NWKV4 (KVW * EMB / 4)
#define NTAB  (S_LEN * 64)
#define PREP_TOTAL (NX4 + NWQ4 + NWKV4 + NWQ4 + NTAB)

__global__ void prep_kernel(const float* __restrict__ x,  const float* __restrict__ Wq,
                            const float* __restrict__ Wkv, const float* __restrict__ Wo)
{
    int i = blockIdx.x * blockDim.x + threadIdx.x;
    const float* src;
    __half* dst;
    if (i < NX4)                      { src = x;   dst = g_xs; }
    else if ((i -= NX4) < NWQ4)       { src = Wq;  dst = g_wq; }
    else if ((i -= NWQ4) < NWKV4)     { src = Wkv; dst = g_wkv; }
    else if ((i -= NWKV4) < NWQ4)     { src = Wo;  dst = g_wo; }
    else {
        i -= NWQ4;
        if (i >= NTAB) return;
        int s = i >> 6, d = i & 63;
        double invf = pow(10000.0, -(double)d / 64.0);
        double ang = (double)s * invf;
        double k = floor(ang * 0.15915494309189535);
        float a = (float)(ang - k * 6.283185307179586);
        g_cs[i] = cosf(a);
        g_sn[i] = sinf(a);
        return;
    }
    float4 v = ((const float4*)src)[i];
    __half2 h01 = __floats2half2_rn(v.x, v.y);
    __half2 h23 = __floats2half2_rn(v.z, v.w);
    uint2 hv; hv.x = *(uint32_t*)&h01; hv.y = *(uint32_t*)&h23;
    ((uint2*)dst)[i] = hv;
}

// ================= GEMM mainloop: K-chunk 64, 2-stage double buffer ===============
#define GS_ROW    72                       // padded row: 72 halfs = 144 B (9x16B, odd)
#define GS_TILE   (128 * GS_ROW * 2)       // 18432 B
#define GS_STAGE  (2 * GS_TILE)            // 36864 B (A, W)
#define GEMM_SMEM (2 * GS_STAGE)           // 73728 B
#define QKV_SMEM  GEMM_SMEM                // epilogue fp32 tile 67584 B fits

#define GEMM_MAINLOOP(K)                                                               \
    const int rIT  = lane & 7;                                                         \
    const int b0_  = (lane >> 3) & 1;                                                  \
    const int b1_  = (lane >> 4) & 1;                                                  \
    const uint32_t aLane = (uint32_t)(((b0_ * 8 + rIT) * GS_ROW + b1_ * 8) * 2);       \
    const uint32_t bLane = (uint32_t)(((b1_ * 8 + rIT) * GS_ROW + b0_ * 8) * 2);       \
    const int nch = (K) >> 6;                                                          \
    LOAD_STAGE(0, 0); CP_COMMIT;                                                       \
    LOAD_STAGE(1, 1); CP_COMMIT;                                                       \
    for (int c = 0; c < nch; c++) {                                                    \
        if (c + 1 < nch) CP_WAIT1; else CP_WAIT0;                                      \
        __syncthreads();                                                               \
        const uint32_t bb = sbase + (uint32_t)((c & 1) * GS_STAGE);                    \
        const uint32_t Ahs = bb;                                                       \
        const uint32_t Whs = bb + GS_TILE;                                             \
        _Pragma("unroll")                                                              \
        for (int ks = 0; ks < 4; ks++) {                                               \
            const uint32_t kOff = (uint32_t)(ks * 32);                                 \
            uint32_t ah[4][4], bh[4][2];                                               \
            _Pragma("unroll")                                                          \
            for (int mf = 0; mf < 4; mf++) {                                           \
                uint32_t addr = Ahs + (uint32_t)((wm + mf * 16) * GS_ROW * 2) + kOff + aLane; \
                LDSM_X4(ah[mf][0], ah[mf][1], ah[mf][2], ah[mf][3], addr);             \
            }                                                                          \
            _Pragma("unroll")                                                          \
            for (int np = 0; np < 2; np++) {                                           \
                uint32_t addr = Whs + (uint32_t)((wn + np * 16) * GS_ROW * 2) + kOff + bLane; \
                uint32_t r0, r1, r2, r3;                                               \
                LDSM_X4(r0, r1, r2, r3, addr);                                         \
                bh[np * 2][0] = r0; bh[np * 2][1] = r1;                                \
                bh[np * 2 + 1][0] = r2; bh[np * 2 + 1][1] = r3;                        \
            }                                                                          \
            _Pragma("unroll")                                                          \
            for (int mf = 0; mf < 4; mf++)                                             \
                _Pragma("unroll")                                                      \
                for (int nf = 0; nf < 4; nf++)                                         \
                    MMAH(acc[mf][nf][0], acc[mf][nf][1], acc[mf][nf][2], acc[mf][nf][3], \
                         ah[mf][0], ah[mf][1], ah[mf][2], ah[mf][3],                   \
                         bh[nf][0], bh[nf][1]);                                        \
        }                                                                              \
        __syncthreads();                                                               \
        if (c + 2 < nch) { LOAD_STAGE(c + 2, c & 1); CP_COMMIT; }                      \
    }

#define LOAD_STAGE(c, bufi) do {                                                       \
    int _k0 = (c) << 6;                                                                \
    uint32_t _st = sbase + (uint32_t)((bufi) * GS_STAGE);                              \
    _Pragma("unroll")                                                                  \
    for (int _i = 0; _i < 4; _i++) {                                                   \
        int _ch = tid + _i * 256;                                                      \
        int _r = _ch >> 3, _cl = _ch & 7;                                              \
        uint32_t _d = _st + (uint32_t)(_r * (GS_ROW * 2) + _cl * 16);                  \
        CP16(_d,           A_gp + (size_t)(m0 + _r) * Kd + _k0 + _cl * 8);             \
        CP16(_d + GS_TILE, W_gp + (size_t)(n0 + _r) * Kd + _k0 + _cl * 8);             \
    } } while (0)

// ================= fused QKV projection + RoPE/convert ============================
__global__ __launch_bounds__(256, 2)
void gemm_qkv(const __half* __restrict__ xs_g,
              const __half* __restrict__ wq_g, const __half* __restrict__ wkv_g,
              const float* __restrict__ bq_g, const float* __restrict__ bkv_g)
{
    extern __shared__ char smp[];
    const uint32_t sbase = smem_u32(smp);

    const int tid  = threadIdx.x;
    const int wid  = tid >> 5;
    const int lane = tid & 31;
    const int bx   = blockIdx.x;
    const bool isQ = bx < 16;
    const int m0   = blockIdx.y * 128;
    const int n0   = isQ ? bx * 128 : (bx - 16) * 128;
    const int wm   = (wid >> 2) * 64;
    const int wn   = (wid & 3) * 32;
    const int Kd   = EMB;

    const __half* A_gp = xs_g;
    const __half* W_gp = isQ ? wq_g : wkv_g;
    const float*  bias = isQ ? bq_g : bkv_g;

    float acc[4][4][4];
    #pragma unroll
    for (int i = 0; i < 4; i++)
        #pragma unroll
        for (int j = 0; j < 4; j++)
            #pragma unroll
            for (int e = 0; e < 4; e++) acc[i][j][e] = 0.f;

    GEMM_MAINLOOP(EMB)

    const int trow  = lane >> 2;
    const int tcol2 = (lane & 3) * 2;
    #pragma unroll
    for (int nf = 0; nf < 4; nf++) {
        float2 bv = *(const float2*)&bias[n0 + wn + nf * 8 + tcol2];
        #pragma unroll
        for (int mf = 0; mf < 4; mf++) {
            acc[mf][nf][0] += bv.x; acc[mf][nf][1] += bv.y;
            acc[mf][nf][2] += bv.x; acc[mf][nf][3] += bv.y;
        }
    }

    if (!isQ && n0 >= 512) {
        // ---- V tile: direct fp16 convert ----
        #pragma unroll
        for (int mf = 0; mf < 4; mf++) {
            #pragma unroll
            for (int nf = 0; nf < 4; nf++) {
                int grow = m0 + wm + mf * 16 + trow;
                int vcol = n0 - 512 + wn + nf * 8 + tcol2;
                __half2 ha = __floats2half2_rn(acc[mf][nf][0], acc[mf][nf][1]);
                __half2 hb = __floats2half2_rn(acc[mf][nf][2], acc[mf][nf][3]);
                *(uint32_t*)&g_vs[(size_t)grow * 512 + vcol]       = *(uint32_t*)&ha;
                *(uint32_t*)&g_vs[(size_t)(grow + 8) * 512 + vcol] = *(uint32_t*)&hb;
            }
        }
        return;
    }

    // ---- Q or K tile: stage fp32 to smem, RoPE, store fp16 ----
    float* smf = (float*)smp;           // [128][132]
    #pragma unroll
    for (int mf = 0; mf < 4; mf++) {
        #pragma unroll
        for (int nf = 0; nf < 4; nf++) {
            int r = wm + mf * 16 + trow;
            int cidx = wn + nf * 8 + tcol2;
            *(float2*)&smf[r * 132 + cidx]       = make_float2(acc[mf][nf][0], acc[mf][nf][1]);
            *(float2*)&smf[(r + 8) * 132 + cidx] = make_float2(acc[mf][nf][2], acc[mf][nf][3]);
        }
    }
    __syncthreads();

    const float sc = isQ ? 0.08838834764831845f : 1.0f;
    __half* dst    = isQ ? g_qs : g_ks;
    const int width = isQ ? EMB : 512;

    #pragma unroll
    for (int i = 0; i < 16; i++) {
        int idx = tid + i * 256;
        int row = idx >> 5;
        int dp  = (idx & 31) * 2;
        int grow = m0 + row;
        int s = grow & (S_LEN - 1);
        float t1a = smf[row * 132 + dp];
        float t1b = smf[row * 132 + dp + 1];
        float t2a = smf[row * 132 + dp + 64];
        float t2b = smf[row * 132 + dp + 65];
        float2 csv = *(const float2*)&g_cs[s * 64 + dp];
        float2 snv = *(const float2*)&g_sn[s * 64 + dp];
        float o1a = (t1a * csv.x - t2a * snv.x) * sc;
        float o1b = (t1b * csv.y - t2b * snv.y) * sc;
        float o2a = (t2a * csv.x + t1a * snv.x) * sc;
        float o2b = (t2b * csv.y + t1b * snv.y) * sc;
        __half2 h1 = __floats2half2_rn(o1a, o1b);
        __half2 h2 = __floats2half2_rn(o2a, o2b);
        size_t ob = (size_t)grow * width + n0 + dp;
        *(uint32_t*)&dst[ob]      = *(uint32_t*)&h1;
        *(uint32_t*)&dst[ob + 64] = *(uint32_t*)&h2;
    }
}

// ================= plain GEMM for O projection ====================================
__global__ __launch_bounds__(256, 2)
void gemm_fp16(const __half* __restrict__ A_gp, const __half* __restrict__ W_gp,
               float* __restrict__ C, int N, int K)
{
    extern __shared__ char smp[];
    const uint32_t sbase = smem_u32(smp);

    const int tid  = threadIdx.x;
    const int wid  = tid >> 5;
    const int lane = tid & 31;
    const int m0   = blockIdx.y * 128;
    const int n0   = blockIdx.x * 128;
    const int wm   = (wid >> 2) * 64;
    const int wn   = (wid & 3) * 32;
    const int Kd   = K;

    float acc[4][4][4];
    #pragma unroll
    for (int i = 0; i < 4; i++)
        #pragma unroll
        for (int j = 0; j < 4; j++)
            #pragma unroll
            for (int e = 0; e < 4; e++) acc[i][j][e] = 0.f;

    GEMM_MAINLOOP(K)

    const int trow  = lane >> 2;
    const int tcol2 = (lane & 3) * 2;
    #pragma unroll
    for (int mf = 0; mf < 4; mf++) {
        #pragma unroll
        for (int nf = 0; nf < 4; nf++) {
            int row = m0 + wm + mf * 16 + trow;
            int col = n0 + wn + nf * 8 + tcol2;
            *(float2*)&C[(size_t)row * N + col]       = make_float2(acc[mf][nf][0], acc[mf][nf][1]);
            *(float2*)&C[(size_t)(row + 8) * N + col] = make_float2(acc[mf][nf][2], acc[mf][nf][3]);
        }
    }
}

// ================= fp16 HMMA attention (FA2, 64 rows, Q in registers) =============
#define AP        272
#define KT_BYTES  (64 * AP)
#define KVBUF     (2 * KT_BYTES)                 // K, V
#define ATTN_SMEM (2 * KVBUF)                    // 69632

__global__ __launch_bounds__(128, 2) void attn_mma() {
    extern __shared__ char smb[];
    const uint32_t sb = smem_u32(smb);

    const int tid  = threadIdx.x;
    const int wid  = tid >> 5;          // 0..3
    const int lane = tid & 31;
    const int q0   = blockIdx.x * 64;
    const int h    = blockIdx.y;
    const int b    = blockIdx.z;
    const int kvh  = h >> 2;

    const int rIT  = lane & 7;
    const int b3   = (lane >> 3) & 1;
    const int b4   = (lane >> 4) & 1;
    const uint32_t offA = (uint32_t)((b3 * 8 + rIT) * AP + b4 * 16);
    const uint32_t offB = (uint32_t)((b4 * 8 + rIT) * AP + b3 * 16);

    const __half* q_g = g_qs + (size_t)(b * S_LEN + q0) * EMB + h * HD;
    const __half* k_g = g_ks + (size_t)b * S_LEN * 512 + kvh * HD;
    const __half* v_g = g_vs + (size_t)b * S_LEN * 512 + kvh * HD;

    // ---- stage Q through buf0, LDSM to registers (loop-invariant) ----
    #pragma unroll
    for (int i = 0; i < 8; i++) {
        int c = tid + i * 128;
        int row = c >> 4, col = c & 15;
        CP16(sb + (uint32_t)(row * AP + col * 16), q_g + (size_t)row * EMB + col * 8);
    }
    CP_COMMIT; CP_WAIT0;
    __syncthreads();
    uint32_t qfr[8][4];
    {
        const uint32_t qwarp = sb + (uint32_t)(wid * 16 * AP);
        #pragma unroll
        for (int ks = 0; ks < 8; ks++)
            LDSM_X4(qfr[ks][0], qfr[ks][1], qfr[ks][2], qfr[ks][3], qwarp + ks * 32 + offA);
    }
    __syncthreads();

    #define LOAD_KV(T, BUF) do {                                                       \
        size_t _j = (size_t)((T) * 64);                                                \
        uint32_t _dst = sb + (uint32_t)((BUF) * KVBUF);                                \
        _Pragma("unroll")                                                              \
        for (int _i = 0; _i < 8; _i++) {                                               \
            int _c = tid + _i * 128;                                                   \
            int _row = _c >> 4, _col = _c & 15;                                        \
            uint32_t _d0 = _dst + (uint32_t)(_row * AP + _col * 16);                   \
            size_t _s0 = (_j + _row) * 512 + _col * 8;                                 \
            CP16(_d0,            k_g + _s0);                                           \
            CP16(_d0 + KT_BYTES, v_g + _s0);                                           \
        } } while (0)

    LOAD_KV(0, 0);
    CP_COMMIT;

    float m0 = -1e30f, m1 = -1e30f, l0 = 0.f, l1 = 0.f;
    float ofr[16][4];
    #pragma unroll
    for (int i = 0; i < 16; i++)
        #pragma unroll
        for (int e = 0; e < 4; e++) ofr[i][e] = 0.f;

    for (int t = 0; t < 32; t++) {
        if (t < 31) { LOAD_KV(t + 1, (t + 1) & 1); CP_COMMIT; CP_WAIT1; }
        else        { CP_WAIT0; }
        __syncthreads();

        const uint32_t kvb = sb + (uint32_t)((t & 1) * KVBUF);
        const uint32_t K_s = kvb;
        const uint32_t V_s = kvb + KT_BYTES;

        float sfr[8][4];
        #pragma unroll
        for (int i = 0; i < 8; i++)
            #pragma unroll
            for (int e = 0; e < 4; e++) sfr[i][e] = 0.f;

        #pragma unroll
        for (int ks = 0; ks < 8; ks++) {
            uint32_t bh[8][2];
            #pragma unroll
            for (int np = 0; np < 4; np++) {
                uint32_t r0, r1, r2, r3;
                LDSM_X4(r0, r1, r2, r3, K_s + (uint32_t)(np * 16 * AP) + ks * 32 + offB);
                bh[np * 2][0] = r0; bh[np * 2][1] = r1;
                bh[np * 2 + 1][0] = r2; bh[np * 2 + 1][1] = r3;
            }
            #pragma unroll
            for (int nf = 0; nf < 8; nf++)
                MMAH(sfr[nf][0], sfr[nf][1], sfr[nf][2], sfr[nf][3],
                     qfr[ks][0], qfr[ks][1], qfr[ks][2], qfr[ks][3],
                     bh[nf][0], bh[nf][1]);
        }

        float mx0 = -1e30f, mx1 = -1e30f;
        #pragma unroll
        for (int nf = 0; nf < 8; nf++) {
            mx0 = fmaxf(mx0, fmaxf(sfr[nf][0], sfr[nf][1]));
            mx1 = fmaxf(mx1, fmaxf(sfr[nf][2], sfr[nf][3]));
        }
        mx0 = fmaxf(mx0, __shfl_xor_sync(0xffffffffu, mx0, 1));
        mx0 = fmaxf(mx0, __shfl_xor_sync(0xffffffffu, mx0, 2));
        mx1 = fmaxf(mx1, __shfl_xor_sync(0xffffffffu, mx1, 1));
        mx1 = fmaxf(mx1, __shfl_xor_sync(0xffffffffu, mx1, 2));
        float mn0 = fmaxf(m0, mx0), mn1 = fmaxf(m1, mx1);
        float al0 = fast_exp(m0 - mn0), al1 = fast_exp(m1 - mn1);

        uint32_t ph[4][4];
        float rs0 = 0.f, rs1 = 0.f;
        #pragma unroll
        for (int nf = 0; nf < 8; nf++) {
            float p0 = fast_exp(sfr[nf][0] - mn0);
            float p1 = fast_exp(sfr[nf][1] - mn0);
            float p2 = fast_exp(sfr[nf][2] - mn1);
            float p3 = fast_exp(sfr[nf][3] - mn1);
            rs0 += p0 + p1; rs1 += p2 + p3;
            __half2 h01 = __floats2half2_rn(p0, p1);
            __half2 h23 = __floats2half2_rn(p2, p3);
            int kb = nf >> 1, hf = (nf & 1) * 2;
            ph[kb][hf]     = *(uint32_t*)&h01;
            ph[kb][hf + 1] = *(uint32_t*)&h23;
        }
        rs0 += __shfl_xor_sync(0xffffffffu, rs0, 1);
        rs0 += __shfl_xor_sync(0xffffffffu, rs0, 2);
        rs1 += __shfl_xor_sync(0xffffffffu, rs1, 1);
        rs1 += __shfl_xor_sync(0xffffffffu, rs1, 2);
        l0 = l0 * al0 + rs0;
        l1 = l1 * al1 + rs1;
        m0 = mn0; m1 = mn1;

        #pragma unroll
        for (int nf = 0; nf < 16; nf++) {
            ofr[nf][0] *= al0; ofr[nf][1] *= al0;
            ofr[nf][2] *= al1; ofr[nf][3] *= al1;
        }

        #pragma unroll
        for (int kb = 0; kb < 4; kb++) {
            #pragma unroll
            for (int db = 0; db < 8; db++) {
                uint32_t vh0, vh1, vh2, vh3;
                uint32_t va = (uint32_t)(kb * 16 * AP + db * 32) + offA;
                LDSM_T_X4(vh0, vh1, vh2, vh3, V_s + va);
                int nf = db * 2;
                MMAH(ofr[nf][0], ofr[nf][1], ofr[nf][2], ofr[nf][3],
                     ph[kb][0], ph[kb][1], ph[kb][2], ph[kb][3], vh0, vh1);
                MMAH(ofr[nf + 1][0], ofr[nf + 1][1], ofr[nf + 1][2], ofr[nf + 1][3],
                     ph[kb][0], ph[kb][1], ph[kb][2], ph[kb][3], vh2, vh3);
            }
        }
        __syncthreads();
    }

    float li0 = 1.0f / l0, li1 = 1.0f / l1;
    int row0 = q0 + wid * 16 + (lane >> 2);
    size_t ob = (size_t)(b * S_LEN + row0) * EMB + h * HD + (lane & 3) * 2;
    #pragma unroll
    for (int nf = 0; nf < 16; nf++) {
        __half2 h01 = __floats2half2_rn(ofr[nf][0] * li0, ofr[nf][1] * li0);
        __half2 h23 = __floats2half2_rn(ofr[nf][2] * li1, ofr[nf][3] * li1);
        *(uint32_t*)&g_as[ob + nf * 8]           = *(uint32_t*)&h01;
        *(uint32_t*)&g_as[ob + 8 * EMB + nf * 8] = *(uint32_t*)&h23;
    }
    #undef LOAD_KV
}

// ---------------- launch ----------------------------------------------------------
extern "C" void kernel_launch(void* const* d_in, const int* in_sizes, int n_in,
                              void* d_out, int out_size)
{
    const float* x   = (const float*)d_in[0];
    const float* Wq  = (const float*)d_in[1];
    const float* bq  = (const float*)d_in[2];
    const float* Wkv = (const float*)d_in[3];
    const float* bkv = (const float*)d_in[4];
    const float* Wo  = (const float*)d_in[5];
    float* out = (float*)d_out;

    __half *xs, *wq, *wkv, *wo, *as;
    cudaGetSymbolAddress((void**)&xs,  g_xs);
    cudaGetSymbolAddress((void**)&wq,  g_wq);
    cudaGetSymbolAddress((void**)&wkv, g_wkv);
    cudaGetSymbolAddress((void**)&wo,  g_wo);
    cudaGetSymbolAddress((void**)&as,  g_as);

    cudaFuncSetAttribute(gemm_qkv, cudaFuncAttributeMaxDynamicSharedMemorySize, QKV_SMEM);
    cudaFuncSetAttribute(gemm_fp16, cudaFuncAttributeMaxDynamicSharedMemorySize, GEMM_SMEM);
    cudaFuncSetAttribute(attn_mma, cudaFuncAttributeMaxDynamicSharedMemorySize, ATTN_SMEM);

    prep_kernel<<<(PREP_TOTAL + 255) / 256, 256>>>(x, Wq, Wkv, Wo);

    gemm_qkv<<<dim3(24, 32), dim3(256), QKV_SMEM>>>(xs, wq, wkv, bq, bkv);

    attn_mma<<<dim3(S_LEN / 64, NHEADS, NBATCH), dim3(128), ATTN_SMEM>>>();

    gemm_fp16<<<dim3(16, 32), dim3(256), GEMM_SMEM>>>(as, wo, out, EMB, EMB);
}